// round 1
// baseline (speedup 1.0000x reference)
#include <cuda_runtime.h>
#include <math.h>

#define SEQ 4096
#define EMB 960
#define NH 15
#define NKV 5
#define HD 64
#define GROUPS 3

// scratch (allocation-free contract -> device globals)
__device__ float g_q[SEQ * NH * HD];
__device__ float g_k[SEQ * NKV * HD];
__device__ float g_v[SEQ * NKV * HD];
__device__ float g_attn[SEQ * NH * HD];

// ---------------------------------------------------------------------------
// C[M,N] = A[M,K] @ B[N,K]^T   (all row-major, M%64==0, N%64==0, K%16==0)
// 64x64 block tile, BK=16, 256 threads, 4x4 per thread.
// ---------------------------------------------------------------------------
__global__ __launch_bounds__(256) void gemm_nt(const float* __restrict__ A,
                                               const float* __restrict__ B,
                                               float* __restrict__ C,
                                               int M, int N, int K) {
    __shared__ float As[16][68];  // [k][m], pad 68 keeps float4 alignment (272B)
    __shared__ float Bs[16][68];  // [k][n]
    const int bm = blockIdx.y * 64;
    const int bn = blockIdx.x * 64;
    const int tid = threadIdx.x;
    const int tx = tid & 15;
    const int ty = tid >> 4;

    float acc[4][4] = {};

    for (int k0 = 0; k0 < K; k0 += 16) {
        const int c = tid & 15;
        const int r = tid >> 4;
#pragma unroll
        for (int rr = 0; rr < 64; rr += 16) {
            As[c][r + rr] = A[(size_t)(bm + r + rr) * K + k0 + c];
            Bs[c][r + rr] = B[(size_t)(bn + r + rr) * K + k0 + c];
        }
        __syncthreads();
#pragma unroll
        for (int kk = 0; kk < 16; kk++) {
            float4 a = *(const float4*)&As[kk][ty * 4];
            float4 b = *(const float4*)&Bs[kk][tx * 4];
            float av[4] = {a.x, a.y, a.z, a.w};
            float bv[4] = {b.x, b.y, b.z, b.w};
#pragma unroll
            for (int i = 0; i < 4; i++)
#pragma unroll
                for (int j = 0; j < 4; j++) acc[i][j] += av[i] * bv[j];
        }
        __syncthreads();
    }
#pragma unroll
    for (int i = 0; i < 4; i++) {
        float4 v = {acc[i][0], acc[i][1], acc[i][2], acc[i][3]};
        *(float4*)&C[(size_t)(bm + ty * 4 + i) * N + bn + tx * 4] = v;
    }
}

// ---------------------------------------------------------------------------
// RoPE in-place on g_q / g_k. One thread per (s, head, pair i<32).
// fp64 phase for exact range reduction (tiny kernel; protects accuracy).
// ---------------------------------------------------------------------------
__global__ void rope_kernel(float* __restrict__ q, float* __restrict__ k,
                            const int* __restrict__ pos) {
    int idx = blockIdx.x * blockDim.x + threadIdx.x;
    if (idx >= SEQ * (NH + NKV) * 32) return;
    int i = idx & 31;
    int h = (idx >> 5) % (NH + NKV);
    int s = idx / (32 * (NH + NKV));

    double p = (double)pos[s];
    double inv = pow(10000.0, -(double)i / 32.0);  // = base^(-2i/64)
    double th = p * inv;
    float c = (float)cos(th);
    float sn = (float)sin(th);

    float* base = (h < NH) ? (q + (size_t)s * NH * HD + h * HD)
                           : (k + (size_t)s * NKV * HD + (h - NH) * HD);
    float x1 = base[i];
    float x2 = base[i + 32];
    base[i]      = x1 * c - x2 * sn;
    base[i + 32] = x2 * c + x1 * sn;
}

// ---------------------------------------------------------------------------
// Causal flash attention, fp32. Block = (query tile of 64, head).
// 256 threads as 16x16; each thread owns a 4x4 score / output tile.
// smem (dynamic, 52224B): sQ[d][q] 64x68, sKP[.][.] 64x68 (K then P), sV[key][d] 64x68
// ---------------------------------------------------------------------------
__global__ __launch_bounds__(256) void flash_attn(const float* __restrict__ Q,
                                                  const float* __restrict__ K,
                                                  const float* __restrict__ V,
                                                  float* __restrict__ O) {
    extern __shared__ float smem[];
    float* sQ = smem;              // [64][68]  sQ[d][qrow]
    float* sKP = smem + 64 * 68;   // [64][68]  K phase: [d][key]; P phase: [qrow][key]
    float* sV = smem + 2 * 64 * 68;// [64][68]  sV[key][d]

    const int h = blockIdx.y;
    const int qt = blockIdx.x;
    const int q0 = qt * 64;
    const int kvh = h / GROUPS;
    const int tid = threadIdx.x;
    const int tx = tid & 15;
    const int ty = tid >> 4;

    // load Q tile transposed (once)
    {
        int d = tid & 63, r4 = tid >> 6;
#pragma unroll
        for (int rr = 0; rr < 64; rr += 4)
            sQ[d * 68 + rr + r4] = Q[(size_t)(q0 + rr + r4) * (NH * HD) + h * HD + d];
    }

    float m_i[4], l_i[4], o_acc[4][4] = {};
#pragma unroll
    for (int i = 0; i < 4; i++) { m_i[i] = -1e30f; l_i[i] = 0.f; }

    for (int kt = 0; kt <= qt; kt++) {
        const int k0 = kt * 64;
        __syncthreads();  // prev PV reads of sKP done; also covers sQ on first iter
        {
            int d = tid & 63, r4 = tid >> 6;
#pragma unroll
            for (int rr = 0; rr < 64; rr += 4) {
                int key = rr + r4;
                float kv = K[(size_t)(k0 + key) * (NKV * HD) + kvh * HD + d];
                float vv = V[(size_t)(k0 + key) * (NKV * HD) + kvh * HD + d];
                sKP[d * 68 + key] = kv;   // transposed
                sV[key * 68 + d] = vv;    // natural
            }
        }
        __syncthreads();

        // S = Q K^T
        float s[4][4] = {};
#pragma unroll
        for (int kk = 0; kk < 64; kk++) {
            float4 a = *(const float4*)&sQ[kk * 68 + ty * 4];
            float4 b = *(const float4*)&sKP[kk * 68 + tx * 4];
            float av[4] = {a.x, a.y, a.z, a.w};
            float bv[4] = {b.x, b.y, b.z, b.w};
#pragma unroll
            for (int i = 0; i < 4; i++)
#pragma unroll
                for (int j = 0; j < 4; j++) s[i][j] += av[i] * bv[j];
        }

        // scale + causal mask (only the diagonal tile needs masking)
        const bool diag = (kt == qt);
#pragma unroll
        for (int i = 0; i < 4; i++)
#pragma unroll
            for (int j = 0; j < 4; j++) {
                float sc = s[i][j] * 0.125f;
                if (diag && (tx * 4 + j) > (ty * 4 + i)) sc = -1e30f;
                s[i][j] = sc;
            }

        // online softmax (row stats across 16 lanes of same ty)
        float corr[4];
#pragma unroll
        for (int i = 0; i < 4; i++) {
            float rm = fmaxf(fmaxf(s[i][0], s[i][1]), fmaxf(s[i][2], s[i][3]));
#pragma unroll
            for (int off = 8; off >= 1; off >>= 1)
                rm = fmaxf(rm, __shfl_xor_sync(0xffffffffu, rm, off, 16));
            float mnew = fmaxf(m_i[i], rm);
            corr[i] = __expf(m_i[i] - mnew);
            m_i[i] = mnew;
            float rs = 0.f;
#pragma unroll
            for (int j = 0; j < 4; j++) {
                s[i][j] = __expf(s[i][j] - mnew);
                rs += s[i][j];
            }
#pragma unroll
            for (int off = 8; off >= 1; off >>= 1)
                rs += __shfl_xor_sync(0xffffffffu, rs, off, 16);
            l_i[i] = l_i[i] * corr[i] + rs;
#pragma unroll
            for (int j = 0; j < 4; j++) o_acc[i][j] *= corr[i];
        }

        __syncthreads();  // everyone done reading K from sKP
        // write P (natural layout: [qrow][key])
#pragma unroll
        for (int i = 0; i < 4; i++)
#pragma unroll
            for (int j = 0; j < 4; j++)
                sKP[(ty * 4 + i) * 68 + tx * 4 + j] = s[i][j];
        __syncthreads();

        // O += P @ V
#pragma unroll
        for (int kk = 0; kk < 64; kk++) {
            float4 b = *(const float4*)&sV[kk * 68 + tx * 4];
            float bv[4] = {b.x, b.y, b.z, b.w};
            float pv[4];
#pragma unroll
            for (int i = 0; i < 4; i++) pv[i] = sKP[(ty * 4 + i) * 68 + kk];
#pragma unroll
            for (int i = 0; i < 4; i++)
#pragma unroll
                for (int j = 0; j < 4; j++) o_acc[i][j] += pv[i] * bv[j];
        }
    }

    // normalize + write out (attn buffer layout [S, NH*HD])
#pragma unroll
    for (int i = 0; i < 4; i++) {
        float inv_l = 1.0f / l_i[i];
        float4 v = {o_acc[i][0] * inv_l, o_acc[i][1] * inv_l,
                    o_acc[i][2] * inv_l, o_acc[i][3] * inv_l};
        *(float4*)&O[(size_t)(q0 + ty * 4 + i) * (NH * HD) + h * HD + tx * 4] = v;
    }
}

// ---------------------------------------------------------------------------
extern "C" void kernel_launch(void* const* d_in, const int* in_sizes, int n_in,
                              void* d_out, int out_size) {
    const float* hidden = (const float*)d_in[0];
    const float* Wq = (const float*)d_in[1];
    const float* Wk = (const float*)d_in[2];
    const float* Wv = (const float*)d_in[3];
    const float* Wo = (const float*)d_in[4];
    // d_in[5] = attention_mask (exactly causal -> computed analytically)
    const int* pos = (const int*)d_in[6];
    float* out = (float*)d_out;

    float *q, *k, *v, *attn;
    cudaGetSymbolAddress((void**)&q, g_q);
    cudaGetSymbolAddress((void**)&k, g_k);
    cudaGetSymbolAddress((void**)&v, g_v);
    cudaGetSymbolAddress((void**)&attn, g_attn);

    static bool attr_set = false;
    if (!attr_set) {
        cudaFuncSetAttribute(flash_attn, cudaFuncAttributeMaxDynamicSharedMemorySize,
                             3 * 64 * 68 * sizeof(float));
        attr_set = true;
    }

    // QKV projections
    gemm_nt<<<dim3(EMB / 64, SEQ / 64), 256>>>(hidden, Wq, q, SEQ, EMB, EMB);
    gemm_nt<<<dim3((NKV * HD) / 64, SEQ / 64), 256>>>(hidden, Wk, k, SEQ, NKV * HD, EMB);
    gemm_nt<<<dim3((NKV * HD) / 64, SEQ / 64), 256>>>(hidden, Wv, v, SEQ, NKV * HD, EMB);

    // RoPE
    {
        int total = SEQ * (NH + NKV) * 32;
        rope_kernel<<<(total + 255) / 256, 256>>>(q, k, pos);
    }

    // attention
    flash_attn<<<dim3(SEQ / 64, NH), 256, 3 * 64 * 68 * sizeof(float)>>>(q, k, v, attn);

    // output projection
    gemm_nt<<<dim3(EMB / 64, SEQ / 64), 256>>>(attn, Wo, out, SEQ, EMB, EMB);
}

// round 2
// speedup vs baseline: 1.3609x; 1.3609x over previous
#include <cuda_runtime.h>
#include <math.h>

#define SEQ 4096
#define EMB 960
#define NH 15
#define NKV 5
#define HD 64
#define GROUPS 3

// scratch (allocation-free contract -> device globals)
__device__ float g_q[SEQ * NH * HD];
__device__ float g_k[SEQ * NKV * HD];
__device__ float g_v[SEQ * NKV * HD];
__device__ float g_attn[SEQ * NH * HD];

// ---------------------------------------------------------------------------
// C[M,N] = A[M,K] @ B[N,K]^T   (all row-major, M%64==0, N%64==0, K%16==0)
// 64x64 block tile, BK=16, 256 threads, 4x4 per thread.
// ---------------------------------------------------------------------------
__global__ __launch_bounds__(256) void gemm_nt(const float* __restrict__ A,
                                               const float* __restrict__ B,
                                               float* __restrict__ C,
                                               int M, int N, int K) {
    __shared__ float As[16][68];  // [k][m], pad 68 keeps float4 alignment (272B)
    __shared__ float Bs[16][68];  // [k][n]
    const int bm = blockIdx.y * 64;
    const int bn = blockIdx.x * 64;
    const int tid = threadIdx.x;
    const int tx = tid & 15;
    const int ty = tid >> 4;

    float acc[4][4] = {};

    for (int k0 = 0; k0 < K; k0 += 16) {
        const int c = tid & 15;
        const int r = tid >> 4;
#pragma unroll
        for (int rr = 0; rr < 64; rr += 16) {
            As[c][r + rr] = A[(size_t)(bm + r + rr) * K + k0 + c];
            Bs[c][r + rr] = B[(size_t)(bn + r + rr) * K + k0 + c];
        }
        __syncthreads();
#pragma unroll
        for (int kk = 0; kk < 16; kk++) {
            float4 a = *(const float4*)&As[kk][ty * 4];
            float4 b = *(const float4*)&Bs[kk][tx * 4];
            float av[4] = {a.x, a.y, a.z, a.w};
            float bv[4] = {b.x, b.y, b.z, b.w};
#pragma unroll
            for (int i = 0; i < 4; i++)
#pragma unroll
                for (int j = 0; j < 4; j++) acc[i][j] += av[i] * bv[j];
        }
        __syncthreads();
    }
#pragma unroll
    for (int i = 0; i < 4; i++) {
        float4 v = {acc[i][0], acc[i][1], acc[i][2], acc[i][3]};
        *(float4*)&C[(size_t)(bm + ty * 4 + i) * N + bn + tx * 4] = v;
    }
}

// ---------------------------------------------------------------------------
// RoPE in-place on g_q / g_k. One thread per (s, pair i<32); each thread
// computes sincos ONCE in fp32 (matches reference fp32 trig) and applies it
// to all 15 Q heads + 5 KV heads. Consecutive i -> consecutive addresses
// within a head row -> fully coalesced.
// ---------------------------------------------------------------------------
__global__ void rope_kernel(float* __restrict__ q, float* __restrict__ k,
                            const int* __restrict__ pos) {
    int idx = blockIdx.x * blockDim.x + threadIdx.x;
    if (idx >= SEQ * 32) return;
    int i = idx & 31;
    int s = idx >> 5;

    float p = (float)pos[s];
    float inv = powf(10000.0f, -(float)i * (1.0f / 32.0f));  // base^(-2i/64)
    float sn, c;
    sincosf(p * inv, &sn, &c);

    float* qrow = q + (size_t)s * NH * HD;
#pragma unroll
    for (int h = 0; h < NH; h++) {
        float x1 = qrow[h * HD + i];
        float x2 = qrow[h * HD + i + 32];
        qrow[h * HD + i]      = x1 * c - x2 * sn;
        qrow[h * HD + i + 32] = x2 * c + x1 * sn;
    }
    float* krow = k + (size_t)s * NKV * HD;
#pragma unroll
    for (int h = 0; h < NKV; h++) {
        float x1 = krow[h * HD + i];
        float x2 = krow[h * HD + i + 32];
        krow[h * HD + i]      = x1 * c - x2 * sn;
        krow[h * HD + i + 32] = x2 * c + x1 * sn;
    }
}

// ---------------------------------------------------------------------------
// Causal flash attention, fp32. Block = (query tile of 64, head).
// 256 threads as 16x16; each thread owns a 4x4 score / output tile.
// smem (dynamic, 52224B): sQ[d][q] 64x68, sKP[.][.] 64x68 (K then P), sV[key][d] 64x68
// ---------------------------------------------------------------------------
__global__ __launch_bounds__(256) void flash_attn(const float* __restrict__ Q,
                                                  const float* __restrict__ K,
                                                  const float* __restrict__ V,
                                                  float* __restrict__ O) {
    extern __shared__ float smem[];
    float* sQ = smem;              // [64][68]  sQ[d][qrow]
    float* sKP = smem + 64 * 68;   // [64][68]  K phase: [d][key]; P phase: [qrow][key]
    float* sV = smem + 2 * 64 * 68;// [64][68]  sV[key][d]

    const int h = blockIdx.y;
    const int qt = blockIdx.x;
    const int q0 = qt * 64;
    const int kvh = h / GROUPS;
    const int tid = threadIdx.x;
    const int tx = tid & 15;
    const int ty = tid >> 4;

    // load Q tile transposed (once)
    {
        int d = tid & 63, r4 = tid >> 6;
#pragma unroll
        for (int rr = 0; rr < 64; rr += 4)
            sQ[d * 68 + rr + r4] = Q[(size_t)(q0 + rr + r4) * (NH * HD) + h * HD + d];
    }

    float m_i[4], l_i[4], o_acc[4][4] = {};
#pragma unroll
    for (int i = 0; i < 4; i++) { m_i[i] = -1e30f; l_i[i] = 0.f; }

    for (int kt = 0; kt <= qt; kt++) {
        const int k0 = kt * 64;
        __syncthreads();  // prev PV reads of sKP done; also covers sQ on first iter
        {
            int d = tid & 63, r4 = tid >> 6;
#pragma unroll
            for (int rr = 0; rr < 64; rr += 4) {
                int key = rr + r4;
                float kv = K[(size_t)(k0 + key) * (NKV * HD) + kvh * HD + d];
                float vv = V[(size_t)(k0 + key) * (NKV * HD) + kvh * HD + d];
                sKP[d * 68 + key] = kv;   // transposed
                sV[key * 68 + d] = vv;    // natural
            }
        }
        __syncthreads();

        // S = Q K^T
        float s[4][4] = {};
#pragma unroll
        for (int kk = 0; kk < 64; kk++) {
            float4 a = *(const float4*)&sQ[kk * 68 + ty * 4];
            float4 b = *(const float4*)&sKP[kk * 68 + tx * 4];
            float av[4] = {a.x, a.y, a.z, a.w};
            float bv[4] = {b.x, b.y, b.z, b.w};
#pragma unroll
            for (int i = 0; i < 4; i++)
#pragma unroll
                for (int j = 0; j < 4; j++) s[i][j] += av[i] * bv[j];
        }

        // scale + causal mask (only the diagonal tile needs masking)
        const bool diag = (kt == qt);
#pragma unroll
        for (int i = 0; i < 4; i++)
#pragma unroll
            for (int j = 0; j < 4; j++) {
                float sc = s[i][j] * 0.125f;
                if (diag && (tx * 4 + j) > (ty * 4 + i)) sc = -1e30f;
                s[i][j] = sc;
            }

        // online softmax (row stats across 16 lanes of same ty)
        float corr[4];
#pragma unroll
        for (int i = 0; i < 4; i++) {
            float rm = fmaxf(fmaxf(s[i][0], s[i][1]), fmaxf(s[i][2], s[i][3]));
#pragma unroll
            for (int off = 8; off >= 1; off >>= 1)
                rm = fmaxf(rm, __shfl_xor_sync(0xffffffffu, rm, off, 16));
            float mnew = fmaxf(m_i[i], rm);
            corr[i] = __expf(m_i[i] - mnew);
            m_i[i] = mnew;
            float rs = 0.f;
#pragma unroll
            for (int j = 0; j < 4; j++) {
                s[i][j] = __expf(s[i][j] - mnew);
                rs += s[i][j];
            }
#pragma unroll
            for (int off = 8; off >= 1; off >>= 1)
                rs += __shfl_xor_sync(0xffffffffu, rs, off, 16);
            l_i[i] = l_i[i] * corr[i] + rs;
#pragma unroll
            for (int j = 0; j < 4; j++) o_acc[i][j] *= corr[i];
        }

        __syncthreads();  // everyone done reading K from sKP
        // write P (natural layout: [qrow][key])
#pragma unroll
        for (int i = 0; i < 4; i++)
#pragma unroll
            for (int j = 0; j < 4; j++)
                sKP[(ty * 4 + i) * 68 + tx * 4 + j] = s[i][j];
        __syncthreads();

        // O += P @ V
#pragma unroll
        for (int kk = 0; kk < 64; kk++) {
            float4 b = *(const float4*)&sV[kk * 68 + tx * 4];
            float bv[4] = {b.x, b.y, b.z, b.w};
            float pv[4];
#pragma unroll
            for (int i = 0; i < 4; i++) pv[i] = sKP[(ty * 4 + i) * 68 + kk];
#pragma unroll
            for (int i = 0; i < 4; i++)
#pragma unroll
                for (int j = 0; j < 4; j++) o_acc[i][j] += pv[i] * bv[j];
        }
    }

    // normalize + write out (attn buffer layout [S, NH*HD])
#pragma unroll
    for (int i = 0; i < 4; i++) {
        float inv_l = 1.0f / l_i[i];
        float4 v = {o_acc[i][0] * inv_l, o_acc[i][1] * inv_l,
                    o_acc[i][2] * inv_l, o_acc[i][3] * inv_l};
        *(float4*)&O[(size_t)(q0 + ty * 4 + i) * (NH * HD) + h * HD + tx * 4] = v;
    }
}

// ---------------------------------------------------------------------------
extern "C" void kernel_launch(void* const* d_in, const int* in_sizes, int n_in,
                              void* d_out, int out_size) {
    const float* hidden = (const float*)d_in[0];
    const float* Wq = (const float*)d_in[1];
    const float* Wk = (const float*)d_in[2];
    const float* Wv = (const float*)d_in[3];
    const float* Wo = (const float*)d_in[4];
    // d_in[5] = attention_mask (exactly causal -> computed analytically)
    const int* pos = (const int*)d_in[6];
    float* out = (float*)d_out;

    float *q, *k, *v, *attn;
    cudaGetSymbolAddress((void**)&q, g_q);
    cudaGetSymbolAddress((void**)&k, g_k);
    cudaGetSymbolAddress((void**)&v, g_v);
    cudaGetSymbolAddress((void**)&attn, g_attn);

    static bool attr_set = false;
    if (!attr_set) {
        cudaFuncSetAttribute(flash_attn, cudaFuncAttributeMaxDynamicSharedMemorySize,
                             3 * 64 * 68 * sizeof(float));
        attr_set = true;
    }

    // QKV projections
    gemm_nt<<<dim3(EMB / 64, SEQ / 64), 256>>>(hidden, Wq, q, SEQ, EMB, EMB);
    gemm_nt<<<dim3((NKV * HD) / 64, SEQ / 64), 256>>>(hidden, Wk, k, SEQ, NKV * HD, EMB);
    gemm_nt<<<dim3((NKV * HD) / 64, SEQ / 64), 256>>>(hidden, Wv, v, SEQ, NKV * HD, EMB);

    // RoPE (4096*32 threads, each covers all 20 heads)
    rope_kernel<<<(SEQ * 32 + 255) / 256, 256>>>(q, k, pos);

    // attention
    flash_attn<<<dim3(SEQ / 64, NH), 256, 3 * 64 * 68 * sizeof(float)>>>(q, k, v, attn);

    // output projection
    gemm_nt<<<dim3(EMB / 64, SEQ / 64), 256>>>(attn, Wo, out, SEQ, EMB, EMB);
}

// round 3
// speedup vs baseline: 1.4197x; 1.0432x over previous
#include <cuda_runtime.h>
#include <math.h>

#define SEQ 4096
#define EMB 960
#define NH 15
#define NKV 5
#define HD 64
#define GROUPS 3

typedef unsigned long long ull;

// ---- packed fp32x2 helpers (sm_103a FFMA2 path, PTX-only) ------------------
__device__ __forceinline__ void ffma2(ull& d, ull a, ull b) {
    asm("fma.rn.f32x2 %0, %1, %2, %0;" : "+l"(d) : "l"(a), "l"(b));
}
__device__ __forceinline__ void fmul2(ull& d, ull b) {
    asm("mul.rn.f32x2 %0, %0, %1;" : "+l"(d) : "l"(b));
}
__device__ __forceinline__ ull bcast2(float x) {
    ull r;
    asm("mov.b64 %0, {%1, %1};" : "=l"(r) : "f"(x));
    return r;
}
__device__ __forceinline__ ull pack2(float lo, float hi) {
    ull r;
    asm("mov.b64 %0, {%1, %2};" : "=l"(r) : "f"(lo), "f"(hi));
    return r;
}
__device__ __forceinline__ void unpack2(ull v, float& lo, float& hi) {
    asm("mov.b64 {%0, %1}, %2;" : "=f"(lo), "=f"(hi) : "l"(v));
}

// scratch (allocation-free contract -> device globals)
__device__ float g_q[SEQ * NH * HD];
__device__ float g_k[SEQ * NKV * HD];
__device__ float g_v[SEQ * NKV * HD];
__device__ float g_attn[SEQ * NH * HD];

// ---------------------------------------------------------------------------
// C[M,N] = A[M,K] @ B[N,K]^T   (row-major, M%64==0, N%64==0, K%16==0)
// 64x64 tile, BK=16, 128 threads, 8x4 per thread, FFMA2 inner loop.
// Accumulators packed along the row dim (row pairs come free from float4 A
// loads); the 4 B columns are broadcast-packed (4 packs / kk).
// ---------------------------------------------------------------------------
__global__ __launch_bounds__(128) void gemm_nt(const float* __restrict__ A,
                                               const float* __restrict__ B,
                                               float* __restrict__ C,
                                               int M, int N, int K) {
    __shared__ float As[16][68];  // [k][m]
    __shared__ float Bs[16][68];  // [k][n]
    const int bm = blockIdx.y * 64;
    const int bn = blockIdx.x * 64;
    const int tid = threadIdx.x;
    const int tx = tid & 15;   // col group: cols tx*4..+3
    const int ty = tid >> 4;   // row group: rows ty*8..+7

    ull acc[4][4];  // [row pair p: rows ty*8+2p, +1][col j]
#pragma unroll
    for (int p = 0; p < 4; p++)
#pragma unroll
        for (int j = 0; j < 4; j++) acc[p][j] = 0ull;

    for (int k0 = 0; k0 < K; k0 += 16) {
        const int c = tid & 15;
        const int r = tid >> 4;  // 0..7
#pragma unroll
        for (int rr = 0; rr < 64; rr += 8) {
            As[c][rr + r] = A[(size_t)(bm + rr + r) * K + k0 + c];
            Bs[c][rr + r] = B[(size_t)(bn + rr + r) * K + k0 + c];
        }
        __syncthreads();
#pragma unroll
        for (int kk = 0; kk < 16; kk++) {
            float4 a0 = *(const float4*)&As[kk][ty * 8];
            float4 a1 = *(const float4*)&As[kk][ty * 8 + 4];
            float4 b = *(const float4*)&Bs[kk][tx * 4];
            ull ap[4] = {pack2(a0.x, a0.y), pack2(a0.z, a0.w),
                         pack2(a1.x, a1.y), pack2(a1.z, a1.w)};
            ull bb[4] = {bcast2(b.x), bcast2(b.y), bcast2(b.z), bcast2(b.w)};
#pragma unroll
            for (int p = 0; p < 4; p++)
#pragma unroll
                for (int j = 0; j < 4; j++) ffma2(acc[p][j], ap[p], bb[j]);
        }
        __syncthreads();
    }
#pragma unroll
    for (int p = 0; p < 4; p++) {
        float lo[4], hi[4];
#pragma unroll
        for (int j = 0; j < 4; j++) unpack2(acc[p][j], lo[j], hi[j]);
        float4 v0 = {lo[0], lo[1], lo[2], lo[3]};
        float4 v1 = {hi[0], hi[1], hi[2], hi[3]};
        *(float4*)&C[(size_t)(bm + ty * 8 + 2 * p) * N + bn + tx * 4] = v0;
        *(float4*)&C[(size_t)(bm + ty * 8 + 2 * p + 1) * N + bn + tx * 4] = v1;
    }
}

// ---------------------------------------------------------------------------
// RoPE in-place on g_q / g_k. One thread per (s, pair i<32); sincos once,
// applied to all 20 heads, coalesced.
// ---------------------------------------------------------------------------
__global__ void rope_kernel(float* __restrict__ q, float* __restrict__ k,
                            const int* __restrict__ pos) {
    int idx = blockIdx.x * blockDim.x + threadIdx.x;
    if (idx >= SEQ * 32) return;
    int i = idx & 31;
    int s = idx >> 5;

    float p = (float)pos[s];
    float inv = powf(10000.0f, -(float)i * (1.0f / 32.0f));
    float sn, c;
    sincosf(p * inv, &sn, &c);

    float* qrow = q + (size_t)s * NH * HD;
#pragma unroll
    for (int h = 0; h < NH; h++) {
        float x1 = qrow[h * HD + i];
        float x2 = qrow[h * HD + i + 32];
        qrow[h * HD + i]      = x1 * c - x2 * sn;
        qrow[h * HD + i + 32] = x2 * c + x1 * sn;
    }
    float* krow = k + (size_t)s * NKV * HD;
#pragma unroll
    for (int h = 0; h < NKV; h++) {
        float x1 = krow[h * HD + i];
        float x2 = krow[h * HD + i + 32];
        krow[h * HD + i]      = x1 * c - x2 * sn;
        krow[h * HD + i + 32] = x2 * c + x1 * sn;
    }
}

// ---------------------------------------------------------------------------
// Causal flash attention, fp32 with FFMA2 inner loops.
// Block = (query tile of 64, head). 256 threads as 16x16, 4x4 per thread.
// Score / output accumulators packed along the column dim (col pairs come
// free from float4 K/V loads); row operand broadcast-packed.
// ---------------------------------------------------------------------------
__global__ __launch_bounds__(256) void flash_attn(const float* __restrict__ Q,
                                                  const float* __restrict__ K,
                                                  const float* __restrict__ V,
                                                  float* __restrict__ O) {
    extern __shared__ float smem[];
    float* sQ = smem;               // [64][68]  sQ[d][qrow]
    float* sKP = smem + 64 * 68;    // [64][68]  K phase: [d][key]; P phase: [qrow][key]
    float* sV = smem + 2 * 64 * 68; // [64][68]  sV[key][d]

    const int h = blockIdx.y;
    const int qt = blockIdx.x;
    const int q0 = qt * 64;
    const int kvh = h / GROUPS;
    const int tid = threadIdx.x;
    const int tx = tid & 15;
    const int ty = tid >> 4;

    // load Q tile transposed (once)
    {
        int d = tid & 63, r4 = tid >> 6;
#pragma unroll
        for (int rr = 0; rr < 64; rr += 4)
            sQ[d * 68 + rr + r4] = Q[(size_t)(q0 + rr + r4) * (NH * HD) + h * HD + d];
    }

    float m_i[4], l_i[4];
    ull o2[4][2];  // output acc, packed col pairs (j01, j23)
#pragma unroll
    for (int i = 0; i < 4; i++) {
        m_i[i] = -1e30f;
        l_i[i] = 0.f;
        o2[i][0] = 0ull;
        o2[i][1] = 0ull;
    }

    for (int kt = 0; kt <= qt; kt++) {
        const int k0 = kt * 64;
        __syncthreads();  // prev PV reads of sKP done; also covers sQ on first iter
        {
            int d = tid & 63, r4 = tid >> 6;
#pragma unroll
            for (int rr = 0; rr < 64; rr += 4) {
                int key = rr + r4;
                float kv = K[(size_t)(k0 + key) * (NKV * HD) + kvh * HD + d];
                float vv = V[(size_t)(k0 + key) * (NKV * HD) + kvh * HD + d];
                sKP[d * 68 + key] = kv;   // transposed
                sV[key * 68 + d] = vv;    // natural
            }
        }
        __syncthreads();

        // S = Q K^T  (packed along keys)
        ull s2[4][2];
#pragma unroll
        for (int i = 0; i < 4; i++) { s2[i][0] = 0ull; s2[i][1] = 0ull; }
#pragma unroll
        for (int kk = 0; kk < 64; kk++) {
            float4 a = *(const float4*)&sQ[kk * 68 + ty * 4];
            float4 b = *(const float4*)&sKP[kk * 68 + tx * 4];
            ull b01 = pack2(b.x, b.y), b23 = pack2(b.z, b.w);
            ull aB[4] = {bcast2(a.x), bcast2(a.y), bcast2(a.z), bcast2(a.w)};
#pragma unroll
            for (int i = 0; i < 4; i++) {
                ffma2(s2[i][0], aB[i], b01);
                ffma2(s2[i][1], aB[i], b23);
            }
        }

        // unpack, scale + causal mask (only the diagonal tile needs masking)
        float s[4][4];
#pragma unroll
        for (int i = 0; i < 4; i++) {
            unpack2(s2[i][0], s[i][0], s[i][1]);
            unpack2(s2[i][1], s[i][2], s[i][3]);
        }
        const bool diag = (kt == qt);
#pragma unroll
        for (int i = 0; i < 4; i++)
#pragma unroll
            for (int j = 0; j < 4; j++) {
                float sc = s[i][j] * 0.125f;
                if (diag && (tx * 4 + j) > (ty * 4 + i)) sc = -1e30f;
                s[i][j] = sc;
            }

        // online softmax (row stats across 16 lanes of same ty)
#pragma unroll
        for (int i = 0; i < 4; i++) {
            float rm = fmaxf(fmaxf(s[i][0], s[i][1]), fmaxf(s[i][2], s[i][3]));
#pragma unroll
            for (int off = 8; off >= 1; off >>= 1)
                rm = fmaxf(rm, __shfl_xor_sync(0xffffffffu, rm, off, 16));
            float mnew = fmaxf(m_i[i], rm);
            float corr = __expf(m_i[i] - mnew);
            m_i[i] = mnew;
            float rs = 0.f;
#pragma unroll
            for (int j = 0; j < 4; j++) {
                s[i][j] = __expf(s[i][j] - mnew);
                rs += s[i][j];
            }
#pragma unroll
            for (int off = 8; off >= 1; off >>= 1)
                rs += __shfl_xor_sync(0xffffffffu, rs, off, 16);
            l_i[i] = l_i[i] * corr + rs;
            ull cb = bcast2(corr);
            fmul2(o2[i][0], cb);
            fmul2(o2[i][1], cb);
        }

        __syncthreads();  // everyone done reading K from sKP
        // write P (natural layout: [qrow][key])
#pragma unroll
        for (int i = 0; i < 4; i++)
#pragma unroll
            for (int j = 0; j < 4; j++)
                sKP[(ty * 4 + i) * 68 + tx * 4 + j] = s[i][j];
        __syncthreads();

        // O += P @ V  (packed along d-columns)
#pragma unroll
        for (int kk = 0; kk < 64; kk++) {
            float4 b = *(const float4*)&sV[kk * 68 + tx * 4];
            ull b01 = pack2(b.x, b.y), b23 = pack2(b.z, b.w);
#pragma unroll
            for (int i = 0; i < 4; i++) {
                ull pvB = bcast2(sKP[(ty * 4 + i) * 68 + kk]);
                ffma2(o2[i][0], pvB, b01);
                ffma2(o2[i][1], pvB, b23);
            }
        }
    }

    // normalize + write out (attn buffer layout [S, NH*HD])
#pragma unroll
    for (int i = 0; i < 4; i++) {
        ull il = bcast2(1.0f / l_i[i]);
        fmul2(o2[i][0], il);
        fmul2(o2[i][1], il);
        float v0, v1, v2, v3;
        unpack2(o2[i][0], v0, v1);
        unpack2(o2[i][1], v2, v3);
        float4 v = {v0, v1, v2, v3};
        *(float4*)&O[(size_t)(q0 + ty * 4 + i) * (NH * HD) + h * HD + tx * 4] = v;
    }
}

// ---------------------------------------------------------------------------
extern "C" void kernel_launch(void* const* d_in, const int* in_sizes, int n_in,
                              void* d_out, int out_size) {
    const float* hidden = (const float*)d_in[0];
    const float* Wq = (const float*)d_in[1];
    const float* Wk = (const float*)d_in[2];
    const float* Wv = (const float*)d_in[3];
    const float* Wo = (const float*)d_in[4];
    // d_in[5] = attention_mask (exactly causal -> computed analytically)
    const int* pos = (const int*)d_in[6];
    float* out = (float*)d_out;

    float *q, *k, *v, *attn;
    cudaGetSymbolAddress((void**)&q, g_q);
    cudaGetSymbolAddress((void**)&k, g_k);
    cudaGetSymbolAddress((void**)&v, g_v);
    cudaGetSymbolAddress((void**)&attn, g_attn);

    static bool attr_set = false;
    if (!attr_set) {
        cudaFuncSetAttribute(flash_attn, cudaFuncAttributeMaxDynamicSharedMemorySize,
                             3 * 64 * 68 * sizeof(float));
        attr_set = true;
    }

    // QKV projections
    gemm_nt<<<dim3(EMB / 64, SEQ / 64), 128>>>(hidden, Wq, q, SEQ, EMB, EMB);
    gemm_nt<<<dim3((NKV * HD) / 64, SEQ / 64), 128>>>(hidden, Wk, k, SEQ, NKV * HD, EMB);
    gemm_nt<<<dim3((NKV * HD) / 64, SEQ / 64), 128>>>(hidden, Wv, v, SEQ, NKV * HD, EMB);

    // RoPE (4096*32 threads, each covers all 20 heads)
    rope_kernel<<<(SEQ * 32 + 255) / 256, 256>>>(q, k, pos);

    // attention
    flash_attn<<<dim3(SEQ / 64, NH), 256, 3 * 64 * 68 * sizeof(float)>>>(q, k, v, attn);

    // output projection
    gemm_nt<<<dim3(EMB / 64, SEQ / 64), 128>>>(attn, Wo, out, SEQ, EMB, EMB);
}

// round 6
// speedup vs baseline: 1.6331x; 1.1503x over previous
#include <cuda_runtime.h>
#include <cuda_bf16.h>
#include <stdint.h>
#include <math.h>

#define SEQ 4096
#define EMB 960
#define NH 15
#define NKV 5
#define HD 64
#define GROUPS 3
#define KDIM 960
#define NQKV 1600   // 960 + 320 + 320

typedef unsigned long long ull;
typedef uint32_t u32;

// ---- packed fp32x2 helpers (flash kernel) ---------------------------------
__device__ __forceinline__ void ffma2(ull& d, ull a, ull b) {
    asm("fma.rn.f32x2 %0, %1, %2, %0;" : "+l"(d) : "l"(a), "l"(b));
}
__device__ __forceinline__ void fmul2(ull& d, ull b) {
    asm("mul.rn.f32x2 %0, %0, %1;" : "+l"(d) : "l"(b));
}
__device__ __forceinline__ ull bcast2(float x) {
    ull r; asm("mov.b64 %0, {%1, %1};" : "=l"(r) : "f"(x)); return r;
}
__device__ __forceinline__ ull pack2(float lo, float hi) {
    ull r; asm("mov.b64 %0, {%1, %2};" : "=l"(r) : "f"(lo), "f"(hi)); return r;
}
__device__ __forceinline__ void unpack2(ull v, float& lo, float& hi) {
    asm("mov.b64 {%0, %1}, %2;" : "=f"(lo), "=f"(hi) : "l"(v));
}

// ---- warp-level HMMA helpers (sm_80+ baseline, works on plain sm_103) -----
__device__ __forceinline__ uint32_t smem_to_u32(const void* p) {
    uint32_t a;
    asm("{ .reg .u64 t; cvta.to.shared.u64 t, %1; cvt.u32.u64 %0, t; }" : "=r"(a) : "l"(p));
    return a;
}
__device__ __forceinline__ void mma_bf16(float* c, const u32* a, const u32* b) {
    asm volatile(
        "mma.sync.aligned.m16n8k16.row.col.f32.bf16.bf16.f32 "
        "{%0,%1,%2,%3}, {%4,%5,%6,%7}, {%8,%9}, {%0,%1,%2,%3};"
        : "+f"(c[0]), "+f"(c[1]), "+f"(c[2]), "+f"(c[3])
        : "r"(a[0]), "r"(a[1]), "r"(a[2]), "r"(a[3]), "r"(b[0]), "r"(b[1]));
}
__device__ __forceinline__ void ldsm4(u32* r, u32 addr) {
    asm volatile("ldmatrix.sync.aligned.m8n8.x4.shared.b16 {%0,%1,%2,%3}, [%4];"
                 : "=r"(r[0]), "=r"(r[1]), "=r"(r[2]), "=r"(r[3]) : "r"(addr));
}

// ---- scratch (allocation-free contract -> device globals) -----------------
__device__ float g_q[SEQ * NH * HD];
__device__ float g_k[SEQ * NKV * HD];
__device__ float g_v[SEQ * NKV * HD];
__device__ float g_attn[SEQ * NH * HD];
__device__ __nv_bfloat16 g_hidH[SEQ * EMB];
__device__ __nv_bfloat16 g_hidL[SEQ * EMB];
__device__ __nv_bfloat16 g_wH[NQKV * KDIM];
__device__ __nv_bfloat16 g_wL[NQKV * KDIM];
__device__ __nv_bfloat16 g_woH[EMB * KDIM];
__device__ __nv_bfloat16 g_woL[EMB * KDIM];
__device__ __nv_bfloat16 g_aH[SEQ * EMB];
__device__ __nv_bfloat16 g_aL[SEQ * EMB];

// ---------------------------------------------------------------------------
// fp32 -> (bf16 hi, bf16 lo) split
// ---------------------------------------------------------------------------
__global__ void cvt_split(const float* __restrict__ src, __nv_bfloat16* __restrict__ hi,
                          __nv_bfloat16* __restrict__ lo, int n) {
    int i = blockIdx.x * blockDim.x + threadIdx.x;
    if (i >= n) return;
    float x = src[i];
    __nv_bfloat16 h = __float2bfloat16(x);
    float r = x - __bfloat162float(h);
    hi[i] = h;
    lo[i] = __float2bfloat16(r);
}

// ---------------------------------------------------------------------------
// HMMA bf16-split GEMM: C[M,N] = A[M,960] @ B[N,960]^T  (fp32-equivalent via
// Ah*Bh + Ah*Bl + Al*Bh, fp32 accumulation).
// CTA: 64x64 tile, 128 threads = 2x2 warps of 32x32; K-chunk 32.
// mode 0: write q/k/v segments (col<960 / <1280 / else); mode 1: write C.
// ---------------------------------------------------------------------------
#define PAD 40  // bf16 row stride in smem: 80B -> conflict-free ldmatrix

__global__ __launch_bounds__(128) void gemm_mma(
    const __nv_bfloat16* __restrict__ Ah, const __nv_bfloat16* __restrict__ Al,
    const __nv_bfloat16* __restrict__ Bh, const __nv_bfloat16* __restrict__ Bl,
    int mode, float* __restrict__ q, float* __restrict__ k, float* __restrict__ v,
    float* __restrict__ C) {
    __shared__ __nv_bfloat16 sAh[64 * PAD], sAl[64 * PAD];
    __shared__ __nv_bfloat16 sBh[64 * PAD], sBl[64 * PAD];
    const int tid = threadIdx.x;
    const int warp = tid >> 5, lane = tid & 31;
    const int wm = warp & 1, wn = warp >> 1;
    const int bm = blockIdx.y * 64, bn = blockIdx.x * 64;

    const u32 pAh = smem_to_u32(sAh), pAl = smem_to_u32(sAl);
    const u32 pBh = smem_to_u32(sBh), pBl = smem_to_u32(sBl);

    float acc[2][4][4];
#pragma unroll
    for (int am = 0; am < 2; am++)
#pragma unroll
        for (int nj = 0; nj < 4; nj++)
#pragma unroll
            for (int e = 0; e < 4; e++) acc[am][nj][e] = 0.f;

    const int a_r = lane & 15, a_h = lane >> 4;
    const int b_r = lane & 7, b_q = lane >> 3;

    for (int k0 = 0; k0 < KDIM; k0 += 32) {
#pragma unroll
        for (int it = 0; it < 2; it++) {
            int idx = tid + it * 128;       // 0..255
            int row = idx >> 2, c16 = idx & 3;
            size_t ga = (size_t)(bm + row) * KDIM + k0 + c16 * 8;
            size_t gb = (size_t)(bn + row) * KDIM + k0 + c16 * 8;
            int so = row * PAD + c16 * 8;
            *(uint4*)(sAh + so) = *(const uint4*)(Ah + ga);
            *(uint4*)(sAl + so) = *(const uint4*)(Al + ga);
            *(uint4*)(sBh + so) = *(const uint4*)(Bh + gb);
            *(uint4*)(sBl + so) = *(const uint4*)(Bl + gb);
        }
        __syncthreads();

#pragma unroll
        for (int kg = 0; kg < 2; kg++) {
            u32 aH[2][4], aL[2][4], bH[2][4], bL[2][4];
#pragma unroll
            for (int am = 0; am < 2; am++) {
                u32 off = (u32)((wm * 32 + am * 16 + a_r) * PAD + kg * 16 + a_h * 8) * 2;
                ldsm4(aH[am], pAh + off);
                ldsm4(aL[am], pAl + off);
            }
#pragma unroll
            for (int np = 0; np < 2; np++) {
                u32 off = (u32)((wn * 32 + np * 16 + (b_q >> 1) * 8 + b_r) * PAD +
                                kg * 16 + (b_q & 1) * 8) * 2;
                ldsm4(bH[np], pBh + off);
                ldsm4(bL[np], pBl + off);
            }
#pragma unroll
            for (int am = 0; am < 2; am++)
#pragma unroll
                for (int nj = 0; nj < 4; nj++) {
                    const u32* bh = &bH[nj >> 1][(nj & 1) * 2];
                    const u32* bl = &bL[nj >> 1][(nj & 1) * 2];
                    mma_bf16(acc[am][nj], aH[am], bh);
                    mma_bf16(acc[am][nj], aH[am], bl);
                    mma_bf16(acc[am][nj], aL[am], bh);
                }
        }
        __syncthreads();
    }

    // epilogue
    const int r0 = lane >> 2, cpair = (lane & 3) * 2;
#pragma unroll
    for (int am = 0; am < 2; am++)
#pragma unroll
        for (int half = 0; half < 2; half++) {
            int row = bm + wm * 32 + am * 16 + half * 8 + r0;
#pragma unroll
            for (int nj = 0; nj < 4; nj++) {
                int col = bn + wn * 32 + nj * 8 + cpair;
                float2 val = {acc[am][nj][half * 2], acc[am][nj][half * 2 + 1]};
                float* dst;
                if (mode == 0) {
                    if (col < 960)       dst = q + (size_t)row * 960 + col;
                    else if (col < 1280) dst = k + (size_t)row * 320 + (col - 960);
                    else                 dst = v + (size_t)row * 320 + (col - 1280);
                } else {
                    dst = C + (size_t)row * 960 + col;
                }
                *(float2*)dst = val;
            }
        }
}

// ---------------------------------------------------------------------------
// RoPE in-place on g_q / g_k (unchanged)
// ---------------------------------------------------------------------------
__global__ void rope_kernel(float* __restrict__ q, float* __restrict__ k,
                            const int* __restrict__ pos) {
    int idx = blockIdx.x * blockDim.x + threadIdx.x;
    if (idx >= SEQ * 32) return;
    int i = idx & 31;
    int s = idx >> 5;
    float p = (float)pos[s];
    float inv = powf(10000.0f, -(float)i * (1.0f / 32.0f));
    float sn, c;
    sincosf(p * inv, &sn, &c);
    float* qrow = q + (size_t)s * NH * HD;
#pragma unroll
    for (int h = 0; h < NH; h++) {
        float x1 = qrow[h * HD + i];
        float x2 = qrow[h * HD + i + 32];
        qrow[h * HD + i]      = x1 * c - x2 * sn;
        qrow[h * HD + i + 32] = x2 * c + x1 * sn;
    }
    float* krow = k + (size_t)s * NKV * HD;
#pragma unroll
    for (int h = 0; h < NKV; h++) {
        float x1 = krow[h * HD + i];
        float x2 = krow[h * HD + i + 32];
        krow[h * HD + i]      = x1 * c - x2 * sn;
        krow[h * HD + i + 32] = x2 * c + x1 * sn;
    }
}

// ---------------------------------------------------------------------------
// Causal flash attention, fp32 + FFMA2 (unchanged)
// ---------------------------------------------------------------------------
__global__ __launch_bounds__(256) void flash_attn(const float* __restrict__ Q,
                                                  const float* __restrict__ K,
                                                  const float* __restrict__ V,
                                                  float* __restrict__ O) {
    extern __shared__ float fsm[];
    float* sQ = fsm;
    float* sKP = fsm + 64 * 68;
    float* sV = fsm + 2 * 64 * 68;

    const int h = blockIdx.y;
    const int qt = blockIdx.x;
    const int q0 = qt * 64;
    const int kvh = h / GROUPS;
    const int tid = threadIdx.x;
    const int tx = tid & 15;
    const int ty = tid >> 4;

    {
        int d = tid & 63, r4 = tid >> 6;
#pragma unroll
        for (int rr = 0; rr < 64; rr += 4)
            sQ[d * 68 + rr + r4] = Q[(size_t)(q0 + rr + r4) * (NH * HD) + h * HD + d];
    }

    float m_i[4], l_i[4];
    ull o2[4][2];
#pragma unroll
    for (int i = 0; i < 4; i++) {
        m_i[i] = -1e30f; l_i[i] = 0.f; o2[i][0] = 0ull; o2[i][1] = 0ull;
    }

    for (int kt = 0; kt <= qt; kt++) {
        const int k0 = kt * 64;
        __syncthreads();
        {
            int d = tid & 63, r4 = tid >> 6;
#pragma unroll
            for (int rr = 0; rr < 64; rr += 4) {
                int key = rr + r4;
                float kv = K[(size_t)(k0 + key) * (NKV * HD) + kvh * HD + d];
                float vv = V[(size_t)(k0 + key) * (NKV * HD) + kvh * HD + d];
                sKP[d * 68 + key] = kv;
                sV[key * 68 + d] = vv;
            }
        }
        __syncthreads();

        ull s2[4][2];
#pragma unroll
        for (int i = 0; i < 4; i++) { s2[i][0] = 0ull; s2[i][1] = 0ull; }
#pragma unroll
        for (int kk = 0; kk < 64; kk++) {
            float4 a = *(const float4*)&sQ[kk * 68 + ty * 4];
            float4 b = *(const float4*)&sKP[kk * 68 + tx * 4];
            ull b01 = pack2(b.x, b.y), b23 = pack2(b.z, b.w);
            ull aB[4] = {bcast2(a.x), bcast2(a.y), bcast2(a.z), bcast2(a.w)};
#pragma unroll
            for (int i = 0; i < 4; i++) {
                ffma2(s2[i][0], aB[i], b01);
                ffma2(s2[i][1], aB[i], b23);
            }
        }

        float s[4][4];
#pragma unroll
        for (int i = 0; i < 4; i++) {
            unpack2(s2[i][0], s[i][0], s[i][1]);
            unpack2(s2[i][1], s[i][2], s[i][3]);
        }
        const bool diag = (kt == qt);
#pragma unroll
        for (int i = 0; i < 4; i++)
#pragma unroll
            for (int j = 0; j < 4; j++) {
                float sc = s[i][j] * 0.125f;
                if (diag && (tx * 4 + j) > (ty * 4 + i)) sc = -1e30f;
                s[i][j] = sc;
            }

#pragma unroll
        for (int i = 0; i < 4; i++) {
            float rm = fmaxf(fmaxf(s[i][0], s[i][1]), fmaxf(s[i][2], s[i][3]));
#pragma unroll
            for (int off = 8; off >= 1; off >>= 1)
                rm = fmaxf(rm, __shfl_xor_sync(0xffffffffu, rm, off, 16));
            float mnew = fmaxf(m_i[i], rm);
            float corr = __expf(m_i[i] - mnew);
            m_i[i] = mnew;
            float rs = 0.f;
#pragma unroll
            for (int j = 0; j < 4; j++) {
                s[i][j] = __expf(s[i][j] - mnew);
                rs += s[i][j];
            }
#pragma unroll
            for (int off = 8; off >= 1; off >>= 1)
                rs += __shfl_xor_sync(0xffffffffu, rs, off, 16);
            l_i[i] = l_i[i] * corr + rs;
            ull cb = bcast2(corr);
            fmul2(o2[i][0], cb);
            fmul2(o2[i][1], cb);
        }

        __syncthreads();
#pragma unroll
        for (int i = 0; i < 4; i++)
#pragma unroll
            for (int j = 0; j < 4; j++)
                sKP[(ty * 4 + i) * 68 + tx * 4 + j] = s[i][j];
        __syncthreads();

#pragma unroll
        for (int kk = 0; kk < 64; kk++) {
            float4 b = *(const float4*)&sV[kk * 68 + tx * 4];
            ull b01 = pack2(b.x, b.y), b23 = pack2(b.z, b.w);
#pragma unroll
            for (int i = 0; i < 4; i++) {
                ull pvB = bcast2(sKP[(ty * 4 + i) * 68 + kk]);
                ffma2(o2[i][0], pvB, b01);
                ffma2(o2[i][1], pvB, b23);
            }
        }
    }

#pragma unroll
    for (int i = 0; i < 4; i++) {
        ull il = bcast2(1.0f / l_i[i]);
        fmul2(o2[i][0], il);
        fmul2(o2[i][1], il);
        float v0, v1, v2, v3;
        unpack2(o2[i][0], v0, v1);
        unpack2(o2[i][1], v2, v3);
        float4 vv = {v0, v1, v2, v3};
        *(float4*)&O[(size_t)(q0 + ty * 4 + i) * (NH * HD) + h * HD + tx * 4] = vv;
    }
}

// ---------------------------------------------------------------------------
extern "C" void kernel_launch(void* const* d_in, const int* in_sizes, int n_in,
                              void* d_out, int out_size) {
    const float* hidden = (const float*)d_in[0];
    const float* Wq = (const float*)d_in[1];
    const float* Wk = (const float*)d_in[2];
    const float* Wv = (const float*)d_in[3];
    const float* Wo = (const float*)d_in[4];
    const int* pos = (const int*)d_in[6];
    float* out = (float*)d_out;

    float *q, *k, *v, *attn;
    __nv_bfloat16 *hidH, *hidL, *wH, *wL, *woH, *woL, *aH, *aL;
    cudaGetSymbolAddress((void**)&q, g_q);
    cudaGetSymbolAddress((void**)&k, g_k);
    cudaGetSymbolAddress((void**)&v, g_v);
    cudaGetSymbolAddress((void**)&attn, g_attn);
    cudaGetSymbolAddress((void**)&hidH, g_hidH);
    cudaGetSymbolAddress((void**)&hidL, g_hidL);
    cudaGetSymbolAddress((void**)&wH, g_wH);
    cudaGetSymbolAddress((void**)&wL, g_wL);
    cudaGetSymbolAddress((void**)&woH, g_woH);
    cudaGetSymbolAddress((void**)&woL, g_woL);
    cudaGetSymbolAddress((void**)&aH, g_aH);
    cudaGetSymbolAddress((void**)&aL, g_aL);

    static bool attr_set = false;
    if (!attr_set) {
        cudaFuncSetAttribute(flash_attn, cudaFuncAttributeMaxDynamicSharedMemorySize,
                             3 * 64 * 68 * sizeof(float));
        attr_set = true;
    }

    // bf16 hi/lo splits
    cvt_split<<<(SEQ * EMB + 255) / 256, 256>>>(hidden, hidH, hidL, SEQ * EMB);
    cvt_split<<<(EMB * KDIM + 255) / 256, 256>>>(Wq, wH, wL, EMB * KDIM);
    cvt_split<<<(320 * KDIM + 255) / 256, 256>>>(Wk, wH + (size_t)960 * KDIM,
                                                 wL + (size_t)960 * KDIM, 320 * KDIM);
    cvt_split<<<(320 * KDIM + 255) / 256, 256>>>(Wv, wH + (size_t)1280 * KDIM,
                                                 wL + (size_t)1280 * KDIM, 320 * KDIM);
    cvt_split<<<(EMB * KDIM + 255) / 256, 256>>>(Wo, woH, woL, EMB * KDIM);

    // fused QKV projection on HMMA tensor cores
    gemm_mma<<<dim3(NQKV / 64, SEQ / 64), 128>>>(hidH, hidL, wH, wL, 0,
                                                 q, k, v, nullptr);

    // RoPE
    rope_kernel<<<(SEQ * 32 + 255) / 256, 256>>>(q, k, pos);

    // attention (fp32 flash)
    flash_attn<<<dim3(SEQ / 64, NH), 256, 3 * 64 * 68 * sizeof(float)>>>(q, k, v, attn);

    // O projection on HMMA tensor cores
    cvt_split<<<(SEQ * EMB + 255) / 256, 256>>>(attn, aH, aL, SEQ * EMB);
    gemm_mma<<<dim3(EMB / 64, SEQ / 64), 128>>>(aH, aL, woH, woL, 1,
                                                nullptr, nullptr, nullptr, out);
}

// round 7
// speedup vs baseline: 3.6133x; 2.2126x over previous
#include <cuda_runtime.h>
#include <cuda_bf16.h>
#include <cuda_fp16.h>
#include <stdint.h>
#include <math.h>

#define SEQ 4096
#define EMB 960
#define NH 15
#define NKV 5
#define HD 64
#define GROUPS 3
#define KDIM 960
#define NQKV 1600   // 960 + 320 + 320
#define FD 72       // flash smem row stride (elems)

typedef unsigned long long ull;
typedef uint32_t u32;

// ---- warp-level HMMA helpers ----------------------------------------------
__device__ __forceinline__ uint32_t smem_to_u32(const void* p) {
    uint32_t a;
    asm("{ .reg .u64 t; cvta.to.shared.u64 t, %1; cvt.u32.u64 %0, t; }" : "=r"(a) : "l"(p));
    return a;
}
__device__ __forceinline__ void mma_bf16(float* c, const u32* a, const u32* b) {
    asm volatile(
        "mma.sync.aligned.m16n8k16.row.col.f32.bf16.bf16.f32 "
        "{%0,%1,%2,%3}, {%4,%5,%6,%7}, {%8,%9}, {%0,%1,%2,%3};"
        : "+f"(c[0]), "+f"(c[1]), "+f"(c[2]), "+f"(c[3])
        : "r"(a[0]), "r"(a[1]), "r"(a[2]), "r"(a[3]), "r"(b[0]), "r"(b[1]));
}
__device__ __forceinline__ void mma_f16(float* c, const u32* a, const u32* b) {
    asm volatile(
        "mma.sync.aligned.m16n8k16.row.col.f32.f16.f16.f32 "
        "{%0,%1,%2,%3}, {%4,%5,%6,%7}, {%8,%9}, {%0,%1,%2,%3};"
        : "+f"(c[0]), "+f"(c[1]), "+f"(c[2]), "+f"(c[3])
        : "r"(a[0]), "r"(a[1]), "r"(a[2]), "r"(a[3]), "r"(b[0]), "r"(b[1]));
}
__device__ __forceinline__ void ldsm4(u32* r, u32 addr) {
    asm volatile("ldmatrix.sync.aligned.m8n8.x4.shared.b16 {%0,%1,%2,%3}, [%4];"
                 : "=r"(r[0]), "=r"(r[1]), "=r"(r[2]), "=r"(r[3]) : "r"(addr));
}
__device__ __forceinline__ void ldsm4t(u32* r, u32 addr) {
    asm volatile("ldmatrix.sync.aligned.m8n8.x4.trans.shared.b16 {%0,%1,%2,%3}, [%4];"
                 : "=r"(r[0]), "=r"(r[1]), "=r"(r[2]), "=r"(r[3]) : "r"(addr));
}
__device__ __forceinline__ float ex2f(float x) {
    float y; asm("ex2.approx.f32 %0, %1;" : "=f"(y) : "f"(x)); return y;
}
__device__ __forceinline__ u32 pack_h2(float lo, float hi) {
    u32 r; asm("cvt.rn.f16x2.f32 %0, %1, %2;" : "=r"(r) : "f"(hi), "f"(lo)); return r;
}

// ---- scratch (allocation-free contract -> device globals) -----------------
__device__ float g_q[SEQ * NH * HD];
__device__ float g_k[SEQ * NKV * HD];
__device__ float g_v[SEQ * NKV * HD];
__device__ float g_attn[SEQ * NH * HD];
__device__ __nv_bfloat16 g_hidH[SEQ * EMB];
__device__ __nv_bfloat16 g_hidL[SEQ * EMB];
__device__ __nv_bfloat16 g_wH[NQKV * KDIM];
__device__ __nv_bfloat16 g_wL[NQKV * KDIM];
__device__ __nv_bfloat16 g_woH[EMB * KDIM];
__device__ __nv_bfloat16 g_woL[EMB * KDIM];
__device__ __nv_bfloat16 g_aH[SEQ * EMB];
__device__ __nv_bfloat16 g_aL[SEQ * EMB];
__device__ __nv_bfloat16 g_qh[SEQ * NH * HD];
__device__ __nv_bfloat16 g_ql[SEQ * NH * HD];
__device__ __nv_bfloat16 g_kh[SEQ * NKV * HD];
__device__ __nv_bfloat16 g_kl[SEQ * NKV * HD];
__device__ __half g_vh[SEQ * NKV * HD];
__device__ __half g_vl[SEQ * NKV * HD];

// ---------------------------------------------------------------------------
// fp32 -> split converters
// ---------------------------------------------------------------------------
__global__ void cvt_split(const float* __restrict__ src, __nv_bfloat16* __restrict__ hi,
                          __nv_bfloat16* __restrict__ lo, int n) {
    int i = blockIdx.x * blockDim.x + threadIdx.x;
    if (i >= n) return;
    float x = src[i];
    __nv_bfloat16 h = __float2bfloat16(x);
    hi[i] = h;
    lo[i] = __float2bfloat16(x - __bfloat162float(h));
}
__global__ void cvt_split_scale(const float* __restrict__ src, __nv_bfloat16* __restrict__ hi,
                                __nv_bfloat16* __restrict__ lo, int n, float scale) {
    int i = blockIdx.x * blockDim.x + threadIdx.x;
    if (i >= n) return;
    float x = src[i] * scale;
    __nv_bfloat16 h = __float2bfloat16(x);
    hi[i] = h;
    lo[i] = __float2bfloat16(x - __bfloat162float(h));
}
__global__ void cvt_split_h(const float* __restrict__ src, __half* __restrict__ hi,
                            __half* __restrict__ lo, int n) {
    int i = blockIdx.x * blockDim.x + threadIdx.x;
    if (i >= n) return;
    float x = src[i];
    __half h = __float2half_rn(x);
    hi[i] = h;
    lo[i] = __float2half_rn(x - __half2float(h));
}

// ---------------------------------------------------------------------------
// HMMA bf16-split GEMM (unchanged from R6, passing)
// ---------------------------------------------------------------------------
#define PAD 40

__global__ __launch_bounds__(128) void gemm_mma(
    const __nv_bfloat16* __restrict__ Ah, const __nv_bfloat16* __restrict__ Al,
    const __nv_bfloat16* __restrict__ Bh, const __nv_bfloat16* __restrict__ Bl,
    int mode, float* __restrict__ q, float* __restrict__ k, float* __restrict__ v,
    float* __restrict__ C) {
    __shared__ __nv_bfloat16 sAh[64 * PAD], sAl[64 * PAD];
    __shared__ __nv_bfloat16 sBh[64 * PAD], sBl[64 * PAD];
    const int tid = threadIdx.x;
    const int warp = tid >> 5, lane = tid & 31;
    const int wm = warp & 1, wn = warp >> 1;
    const int bm = blockIdx.y * 64, bn = blockIdx.x * 64;

    const u32 pAh = smem_to_u32(sAh), pAl = smem_to_u32(sAl);
    const u32 pBh = smem_to_u32(sBh), pBl = smem_to_u32(sBl);

    float acc[2][4][4];
#pragma unroll
    for (int am = 0; am < 2; am++)
#pragma unroll
        for (int nj = 0; nj < 4; nj++)
#pragma unroll
            for (int e = 0; e < 4; e++) acc[am][nj][e] = 0.f;

    const int a_r = lane & 15, a_h = lane >> 4;
    const int b_r = lane & 7, b_q = lane >> 3;

    for (int k0 = 0; k0 < KDIM; k0 += 32) {
#pragma unroll
        for (int it = 0; it < 2; it++) {
            int idx = tid + it * 128;
            int row = idx >> 2, c16 = idx & 3;
            size_t ga = (size_t)(bm + row) * KDIM + k0 + c16 * 8;
            size_t gb = (size_t)(bn + row) * KDIM + k0 + c16 * 8;
            int so = row * PAD + c16 * 8;
            *(uint4*)(sAh + so) = *(const uint4*)(Ah + ga);
            *(uint4*)(sAl + so) = *(const uint4*)(Al + ga);
            *(uint4*)(sBh + so) = *(const uint4*)(Bh + gb);
            *(uint4*)(sBl + so) = *(const uint4*)(Bl + gb);
        }
        __syncthreads();

#pragma unroll
        for (int kg = 0; kg < 2; kg++) {
            u32 aH[2][4], aL[2][4], bH[2][4], bL[2][4];
#pragma unroll
            for (int am = 0; am < 2; am++) {
                u32 off = (u32)((wm * 32 + am * 16 + a_r) * PAD + kg * 16 + a_h * 8) * 2;
                ldsm4(aH[am], pAh + off);
                ldsm4(aL[am], pAl + off);
            }
#pragma unroll
            for (int np = 0; np < 2; np++) {
                u32 off = (u32)((wn * 32 + np * 16 + (b_q >> 1) * 8 + b_r) * PAD +
                                kg * 16 + (b_q & 1) * 8) * 2;
                ldsm4(bH[np], pBh + off);
                ldsm4(bL[np], pBl + off);
            }
#pragma unroll
            for (int am = 0; am < 2; am++)
#pragma unroll
                for (int nj = 0; nj < 4; nj++) {
                    const u32* bh = &bH[nj >> 1][(nj & 1) * 2];
                    const u32* bl = &bL[nj >> 1][(nj & 1) * 2];
                    mma_bf16(acc[am][nj], aH[am], bh);
                    mma_bf16(acc[am][nj], aH[am], bl);
                    mma_bf16(acc[am][nj], aL[am], bh);
                }
        }
        __syncthreads();
    }

    const int r0 = lane >> 2, cpair = (lane & 3) * 2;
#pragma unroll
    for (int am = 0; am < 2; am++)
#pragma unroll
        for (int half = 0; half < 2; half++) {
            int row = bm + wm * 32 + am * 16 + half * 8 + r0;
#pragma unroll
            for (int nj = 0; nj < 4; nj++) {
                int col = bn + wn * 32 + nj * 8 + cpair;
                float2 val = {acc[am][nj][half * 2], acc[am][nj][half * 2 + 1]};
                float* dst;
                if (mode == 0) {
                    if (col < 960)       dst = q + (size_t)row * 960 + col;
                    else if (col < 1280) dst = k + (size_t)row * 320 + (col - 960);
                    else                 dst = v + (size_t)row * 320 + (col - 1280);
                } else {
                    dst = C + (size_t)row * 960 + col;
                }
                *(float2*)dst = val;
            }
        }
}

// ---------------------------------------------------------------------------
// RoPE in-place on g_q / g_k (unchanged)
// ---------------------------------------------------------------------------
__global__ void rope_kernel(float* __restrict__ q, float* __restrict__ k,
                            const int* __restrict__ pos) {
    int idx = blockIdx.x * blockDim.x + threadIdx.x;
    if (idx >= SEQ * 32) return;
    int i = idx & 31;
    int s = idx >> 5;
    float p = (float)pos[s];
    float inv = powf(10000.0f, -(float)i * (1.0f / 32.0f));
    float sn, c;
    sincosf(p * inv, &sn, &c);
    float* qrow = q + (size_t)s * NH * HD;
#pragma unroll
    for (int h = 0; h < NH; h++) {
        float x1 = qrow[h * HD + i];
        float x2 = qrow[h * HD + i + 32];
        qrow[h * HD + i]      = x1 * c - x2 * sn;
        qrow[h * HD + i + 32] = x2 * c + x1 * sn;
    }
    float* krow = k + (size_t)s * NKV * HD;
#pragma unroll
    for (int h = 0; h < NKV; h++) {
        float x1 = krow[h * HD + i];
        float x2 = krow[h * HD + i + 32];
        krow[h * HD + i]      = x1 * c - x2 * sn;
        krow[h * HD + i + 32] = x2 * c + x1 * sn;
    }
}

// ---------------------------------------------------------------------------
// HMMA causal flash attention.
// Block = (query tile 64, head), 128 threads = 4 warps x 16 query rows.
// S: 3-term bf16-split mma (Q pre-scaled by 0.125*log2e). Softmax: ex2 MUFU.
// PV: P in fp16 fragments (direct from ex2 output), V fp16 hi/lo, 2-term mma.
// ---------------------------------------------------------------------------
__global__ __launch_bounds__(128) void flash_mma(
    const __nv_bfloat16* __restrict__ Qh, const __nv_bfloat16* __restrict__ Ql,
    const __nv_bfloat16* __restrict__ Kh, const __nv_bfloat16* __restrict__ Kl,
    const __half* __restrict__ Vh, const __half* __restrict__ Vl,
    float* __restrict__ O) {
    __shared__ __nv_bfloat16 sKh[64 * FD], sKl[64 * FD];
    __shared__ __half sVh[64 * FD], sVl[64 * FD];

    const int h = blockIdx.y, qt = blockIdx.x, q0 = qt * 64, kvh = h / GROUPS;
    const int tid = threadIdx.x, warp = tid >> 5, lane = tid & 31;

    const u32 pKh = smem_to_u32(sKh), pKl = smem_to_u32(sKl);
    const u32 pVh = smem_to_u32(sVh), pVl = smem_to_u32(sVl);

    // ---- stage Q through sKh/sKl, ldmatrix to registers, keep for all kt
    for (int u = tid; u < 512; u += 128) {
        int row = u >> 3, c8 = u & 7;
        size_t g = (size_t)(q0 + row) * (NH * HD) + h * HD + c8 * 8;
        *(uint4*)(sKh + row * FD + c8 * 8) = *(const uint4*)(Qh + g);
        *(uint4*)(sKl + row * FD + c8 * 8) = *(const uint4*)(Ql + g);
    }
    __syncthreads();
    u32 aQh[4][4], aQl[4][4];
    {
        int row = warp * 16 + (lane & 15);
        int csel = (lane >> 4) * 8;
#pragma unroll
        for (int ks = 0; ks < 4; ks++) {
            u32 off = (u32)(row * FD + ks * 16 + csel) * 2;
            ldsm4(aQh[ks], pKh + off);
            ldsm4(aQl[ks], pKl + off);
        }
    }

    float m_i[2] = {-1e30f, -1e30f}, l_i[2] = {0.f, 0.f};
    float acc_o[8][4];
#pragma unroll
    for (int j = 0; j < 8; j++)
#pragma unroll
        for (int e = 0; e < 4; e++) acc_o[j][e] = 0.f;

    for (int kt = 0; kt <= qt; kt++) {
        const int k0 = kt * 64;
        __syncthreads();  // prior readers of smem done (incl. Q staging on iter 0)
        for (int u = tid; u < 512; u += 128) {
            int row = u >> 3, c8 = u & 7;
            size_t g = (size_t)(k0 + row) * (NKV * HD) + kvh * HD + c8 * 8;
            *(uint4*)(sKh + row * FD + c8 * 8) = *(const uint4*)(Kh + g);
            *(uint4*)(sKl + row * FD + c8 * 8) = *(const uint4*)(Kl + g);
            *(uint4*)(sVh + row * FD + c8 * 8) = *(const uint4*)(Vh + g);
            *(uint4*)(sVl + row * FD + c8 * 8) = *(const uint4*)(Vl + g);
        }
        __syncthreads();

        // ---- S = Q K^T (3-term bf16 split), fp32 frags; already log2e-scaled
        float s[8][4];
#pragma unroll
        for (int j = 0; j < 8; j++)
#pragma unroll
            for (int e = 0; e < 4; e++) s[j][e] = 0.f;

        const int sel = lane >> 3, l7 = lane & 7;
#pragma unroll
        for (int ks = 0; ks < 4; ks++) {
#pragma unroll
            for (int g2 = 0; g2 < 4; g2++) {
                int key = 16 * g2 + ((sel >> 1) << 3) + l7;
                int col = ks * 16 + (sel & 1) * 8;
                u32 off = (u32)(key * FD + col) * 2;
                u32 bh[4], bl[4];
                ldsm4(bh, pKh + off);
                ldsm4(bl, pKl + off);
                mma_bf16(s[2 * g2], aQh[ks], bh);
                mma_bf16(s[2 * g2], aQh[ks], bl);
                mma_bf16(s[2 * g2], aQl[ks], bh);
                mma_bf16(s[2 * g2 + 1], aQh[ks], bh + 2);
                mma_bf16(s[2 * g2 + 1], aQh[ks], bl + 2);
                mma_bf16(s[2 * g2 + 1], aQl[ks], bh + 2);
            }
        }

        // ---- causal mask (diagonal tile only)
        if (kt == qt) {
            const int c0 = (lane & 3) * 2, r0l = warp * 16 + (lane >> 2);
#pragma unroll
            for (int j = 0; j < 8; j++)
#pragma unroll
                for (int e = 0; e < 4; e++) {
                    int key = 8 * j + c0 + (e & 1);
                    int qr = r0l + (e >> 1) * 8;
                    if (key > qr) s[j][e] = -1e30f;
                }
        }

        // ---- online softmax (base-2), P -> fp16 fragments
        u32 ph2[8][2];
#pragma unroll
        for (int hf = 0; hf < 2; hf++) {
            float rm = -1e30f;
#pragma unroll
            for (int j = 0; j < 8; j++)
                rm = fmaxf(rm, fmaxf(s[j][2 * hf], s[j][2 * hf + 1]));
            rm = fmaxf(rm, __shfl_xor_sync(0xffffffffu, rm, 1));
            rm = fmaxf(rm, __shfl_xor_sync(0xffffffffu, rm, 2));
            float mnew = fmaxf(m_i[hf], rm);
            float corr = ex2f(m_i[hf] - mnew);
            m_i[hf] = mnew;
            float rsum = 0.f;
#pragma unroll
            for (int j = 0; j < 8; j++) {
                float p0 = ex2f(s[j][2 * hf] - mnew);
                float p1 = ex2f(s[j][2 * hf + 1] - mnew);
                ph2[j][hf] = pack_h2(p0, p1);
                rsum += p0 + p1;
            }
            rsum += __shfl_xor_sync(0xffffffffu, rsum, 1);
            rsum += __shfl_xor_sync(0xffffffffu, rsum, 2);
            l_i[hf] = l_i[hf] * corr + rsum;
#pragma unroll
            for (int j = 0; j < 8; j++) {
                acc_o[j][2 * hf] *= corr;
                acc_o[j][2 * hf + 1] *= corr;
            }
        }

        // ---- O += P V (fp16, 2-term split V)
#pragma unroll
        for (int g2 = 0; g2 < 4; g2++) {
            u32 pa[4] = {ph2[2 * g2][0], ph2[2 * g2][1],
                         ph2[2 * g2 + 1][0], ph2[2 * g2 + 1][1]};
#pragma unroll
            for (int dd = 0; dd < 4; dd += 2) {  // d chunks of 16 (dd, dd covers 2 loops)
            }
#pragma unroll
            for (int dd = 0; dd < 4; dd++) {  // d chunk of 16
                int key = 16 * g2 + ((sel & 1) << 3) + l7;
                int col = 16 * dd + ((sel >> 1) << 3);
                u32 off = (u32)(key * FD + col) * 2;
                u32 bh[4], bl[4];
                ldsm4t(bh, pVh + off);
                ldsm4t(bl, pVl + off);
                mma_f16(acc_o[2 * dd], pa, bh);
                mma_f16(acc_o[2 * dd], pa, bl);
                mma_f16(acc_o[2 * dd + 1], pa, bh + 2);
                mma_f16(acc_o[2 * dd + 1], pa, bl + 2);
            }
        }
    }

    // ---- normalize + write
    const float inv0 = 1.0f / l_i[0], inv1 = 1.0f / l_i[1];
    const int r0 = q0 + warp * 16 + (lane >> 2), c0 = (lane & 3) * 2;
#pragma unroll
    for (int j = 0; j < 8; j++) {
        int col = h * HD + 8 * j + c0;
        float2 v0 = {acc_o[j][0] * inv0, acc_o[j][1] * inv0};
        float2 v1 = {acc_o[j][2] * inv1, acc_o[j][3] * inv1};
        *(float2*)&O[(size_t)r0 * (NH * HD) + col] = v0;
        *(float2*)&O[(size_t)(r0 + 8) * (NH * HD) + col] = v1;
    }
}

// ---------------------------------------------------------------------------
extern "C" void kernel_launch(void* const* d_in, const int* in_sizes, int n_in,
                              void* d_out, int out_size) {
    const float* hidden = (const float*)d_in[0];
    const float* Wq = (const float*)d_in[1];
    const float* Wk = (const float*)d_in[2];
    const float* Wv = (const float*)d_in[3];
    const float* Wo = (const float*)d_in[4];
    const int* pos = (const int*)d_in[6];
    float* out = (float*)d_out;

    float *q, *k, *v, *attn;
    __nv_bfloat16 *hidH, *hidL, *wH, *wL, *woH, *woL, *aH, *aL, *qh, *ql, *kh, *kl;
    __half *vh, *vl;
    cudaGetSymbolAddress((void**)&q, g_q);
    cudaGetSymbolAddress((void**)&k, g_k);
    cudaGetSymbolAddress((void**)&v, g_v);
    cudaGetSymbolAddress((void**)&attn, g_attn);
    cudaGetSymbolAddress((void**)&hidH, g_hidH);
    cudaGetSymbolAddress((void**)&hidL, g_hidL);
    cudaGetSymbolAddress((void**)&wH, g_wH);
    cudaGetSymbolAddress((void**)&wL, g_wL);
    cudaGetSymbolAddress((void**)&woH, g_woH);
    cudaGetSymbolAddress((void**)&woL, g_woL);
    cudaGetSymbolAddress((void**)&aH, g_aH);
    cudaGetSymbolAddress((void**)&aL, g_aL);
    cudaGetSymbolAddress((void**)&qh, g_qh);
    cudaGetSymbolAddress((void**)&ql, g_ql);
    cudaGetSymbolAddress((void**)&kh, g_kh);
    cudaGetSymbolAddress((void**)&kl, g_kl);
    cudaGetSymbolAddress((void**)&vh, g_vh);
    cudaGetSymbolAddress((void**)&vl, g_vl);

    // bf16 hi/lo splits for projection GEMMs
    cvt_split<<<(SEQ * EMB + 255) / 256, 256>>>(hidden, hidH, hidL, SEQ * EMB);
    cvt_split<<<(EMB * KDIM + 255) / 256, 256>>>(Wq, wH, wL, EMB * KDIM);
    cvt_split<<<(320 * KDIM + 255) / 256, 256>>>(Wk, wH + (size_t)960 * KDIM,
                                                 wL + (size_t)960 * KDIM, 320 * KDIM);
    cvt_split<<<(320 * KDIM + 255) / 256, 256>>>(Wv, wH + (size_t)1280 * KDIM,
                                                 wL + (size_t)1280 * KDIM, 320 * KDIM);
    cvt_split<<<(EMB * KDIM + 255) / 256, 256>>>(Wo, woH, woL, EMB * KDIM);

    // fused QKV projection (HMMA)
    gemm_mma<<<dim3(NQKV / 64, SEQ / 64), 128>>>(hidH, hidL, wH, wL, 0,
                                                 q, k, v, nullptr);

    // RoPE on q, k
    rope_kernel<<<(SEQ * 32 + 255) / 256, 256>>>(q, k, pos);

    // split q (scaled by 0.125*log2e), k (bf16), v (fp16) for flash
    cvt_split_scale<<<(SEQ * NH * HD + 255) / 256, 256>>>(q, qh, ql, SEQ * NH * HD,
                                                          0.18033688011112042f);
    cvt_split<<<(SEQ * NKV * HD + 255) / 256, 256>>>(k, kh, kl, SEQ * NKV * HD);
    cvt_split_h<<<(SEQ * NKV * HD + 255) / 256, 256>>>(v, vh, vl, SEQ * NKV * HD);

    // flash attention (HMMA)
    flash_mma<<<dim3(SEQ / 64, NH), 128>>>(qh, ql, kh, kl, vh, vl, attn);

    // O projection (HMMA)
    cvt_split<<<(SEQ * EMB + 255) / 256, 256>>>(attn, aH, aL, SEQ * EMB);
    gemm_mma<<<dim3(EMB / 64, SEQ / 64), 128>>>(aH, aL, woH, woL, 1,
                                                nullptr, nullptr, nullptr, out);
}

// round 8
// speedup vs baseline: 4.5137x; 1.2492x over previous
#include <cuda_runtime.h>
#include <cuda_bf16.h>
#include <cuda_fp16.h>
#include <stdint.h>
#include <math.h>

#define SEQ 4096
#define EMB 960
#define NH 15
#define NKV 5
#define HD 64
#define GROUPS 3
#define KDIM 960
#define NQKV 1600
#define FD 72                 // flash smem row stride (elems)
#define FARR (64 * FD * 2)    // 9216 B per flash array
#define FBUF (4 * FARR)       // 36864 B per flash KV buffer
#define QSCALE 0.18033688011112042f  // 0.125 * log2(e)

typedef uint32_t u32;

// ---- PTX helpers ----------------------------------------------------------
__device__ __forceinline__ uint32_t smem_to_u32(const void* p) {
    uint32_t a;
    asm("{ .reg .u64 t; cvta.to.shared.u64 t, %1; cvt.u32.u64 %0, t; }" : "=r"(a) : "l"(p));
    return a;
}
__device__ __forceinline__ void mma_bf16(float* c, const u32* a, const u32* b) {
    asm volatile(
        "mma.sync.aligned.m16n8k16.row.col.f32.bf16.bf16.f32 "
        "{%0,%1,%2,%3}, {%4,%5,%6,%7}, {%8,%9}, {%0,%1,%2,%3};"
        : "+f"(c[0]), "+f"(c[1]), "+f"(c[2]), "+f"(c[3])
        : "r"(a[0]), "r"(a[1]), "r"(a[2]), "r"(a[3]), "r"(b[0]), "r"(b[1]));
}
__device__ __forceinline__ void mma_f16(float* c, const u32* a, const u32* b) {
    asm volatile(
        "mma.sync.aligned.m16n8k16.row.col.f32.f16.f16.f32 "
        "{%0,%1,%2,%3}, {%4,%5,%6,%7}, {%8,%9}, {%0,%1,%2,%3};"
        : "+f"(c[0]), "+f"(c[1]), "+f"(c[2]), "+f"(c[3])
        : "r"(a[0]), "r"(a[1]), "r"(a[2]), "r"(a[3]), "r"(b[0]), "r"(b[1]));
}
__device__ __forceinline__ void ldsm4(u32* r, u32 addr) {
    asm volatile("ldmatrix.sync.aligned.m8n8.x4.shared.b16 {%0,%1,%2,%3}, [%4];"
                 : "=r"(r[0]), "=r"(r[1]), "=r"(r[2]), "=r"(r[3]) : "r"(addr));
}
__device__ __forceinline__ void ldsm4t(u32* r, u32 addr) {
    asm volatile("ldmatrix.sync.aligned.m8n8.x4.trans.shared.b16 {%0,%1,%2,%3}, [%4];"
                 : "=r"(r[0]), "=r"(r[1]), "=r"(r[2]), "=r"(r[3]) : "r"(addr));
}
__device__ __forceinline__ float ex2f(float x) {
    float y; asm("ex2.approx.f32 %0, %1;" : "=f"(y) : "f"(x)); return y;
}
__device__ __forceinline__ u32 pack_h2(float lo, float hi) {
    u32 r; asm("cvt.rn.f16x2.f32 %0, %1, %2;" : "=r"(r) : "f"(hi), "f"(lo)); return r;
}
__device__ __forceinline__ void cp16(u32 saddr, const void* g) {
    asm volatile("cp.async.cg.shared.global [%0], [%1], 16;" :: "r"(saddr), "l"(g));
}
#define CP_COMMIT() asm volatile("cp.async.commit_group;" ::: "memory")
#define CP_WAIT1() asm volatile("cp.async.wait_group 1;" ::: "memory")
#define CP_WAIT0() asm volatile("cp.async.wait_group 0;" ::: "memory")

// ---- scratch --------------------------------------------------------------
__device__ float g_q[SEQ * NH * HD];
__device__ float g_k[SEQ * NKV * HD];
__device__ __nv_bfloat16 g_hidH[SEQ * EMB];
__device__ __nv_bfloat16 g_hidL[SEQ * EMB];
__device__ __nv_bfloat16 g_wH[NQKV * KDIM];
__device__ __nv_bfloat16 g_wL[NQKV * KDIM];
__device__ __nv_bfloat16 g_woH[EMB * KDIM];
__device__ __nv_bfloat16 g_woL[EMB * KDIM];
__device__ __nv_bfloat16 g_aH[SEQ * EMB];
__device__ __nv_bfloat16 g_aL[SEQ * EMB];
__device__ __nv_bfloat16 g_qh[SEQ * NH * HD];
__device__ __nv_bfloat16 g_ql[SEQ * NH * HD];
__device__ __nv_bfloat16 g_kh[SEQ * NKV * HD];
__device__ __nv_bfloat16 g_kl[SEQ * NKV * HD];
__device__ __half g_vh[SEQ * NKV * HD];
__device__ __half g_vl[SEQ * NKV * HD];

// ---------------------------------------------------------------------------
__global__ void cvt_split(const float* __restrict__ src, __nv_bfloat16* __restrict__ hi,
                          __nv_bfloat16* __restrict__ lo, int n) {
    int i = blockIdx.x * blockDim.x + threadIdx.x;
    if (i >= n) return;
    float x = src[i];
    __nv_bfloat16 h = __float2bfloat16(x);
    hi[i] = h;
    lo[i] = __float2bfloat16(x - __bfloat162float(h));
}

// ---------------------------------------------------------------------------
// HMMA bf16-split GEMM with cp.async double buffering.
// mode 0: q fp32 (col<960), k fp32 (<1280), V as fp16 hi/lo (>=1280)
// mode 1: C fp32
// ---------------------------------------------------------------------------
#define PAD 40
#define GARR (64 * PAD * 2)   // 5120 B
#define GBUF (4 * GARR)       // 20480 B

__device__ __forceinline__ void gemm_ld(
    u32 sbase, const __nv_bfloat16* Ah, const __nv_bfloat16* Al,
    const __nv_bfloat16* Bh, const __nv_bfloat16* Bl, int bm, int bn, int k0, int tid) {
#pragma unroll
    for (int it = 0; it < 2; it++) {
        int idx = tid + it * 128;
        int row = idx >> 2, c16 = idx & 3;
        size_t ga = (size_t)(bm + row) * KDIM + k0 + c16 * 8;
        size_t gb = (size_t)(bn + row) * KDIM + k0 + c16 * 8;
        u32 so = (u32)(row * PAD + c16 * 8) * 2;
        cp16(sbase + so, Ah + ga);
        cp16(sbase + GARR + so, Al + ga);
        cp16(sbase + 2 * GARR + so, Bh + gb);
        cp16(sbase + 3 * GARR + so, Bl + gb);
    }
}

__global__ __launch_bounds__(128) void gemm_mma(
    const __nv_bfloat16* __restrict__ Ah, const __nv_bfloat16* __restrict__ Al,
    const __nv_bfloat16* __restrict__ Bh, const __nv_bfloat16* __restrict__ Bl,
    int mode, float* __restrict__ q, float* __restrict__ k,
    __half* __restrict__ vh, __half* __restrict__ vl, float* __restrict__ C) {
    __shared__ __nv_bfloat16 gsm[2 * 4 * 64 * PAD];
    const u32 base = smem_to_u32(gsm);
    const int tid = threadIdx.x;
    const int warp = tid >> 5, lane = tid & 31;
    const int wm = warp & 1, wn = warp >> 1;
    const int bm = blockIdx.y * 64, bn = blockIdx.x * 64;

    float acc[2][4][4];
#pragma unroll
    for (int am = 0; am < 2; am++)
#pragma unroll
        for (int nj = 0; nj < 4; nj++)
#pragma unroll
            for (int e = 0; e < 4; e++) acc[am][nj][e] = 0.f;

    const int a_r = lane & 15, a_h = lane >> 4;
    const int b_r = lane & 7, b_q = lane >> 3;
    const int NCH = KDIM / 32;  // 30

    gemm_ld(base, Ah, Al, Bh, Bl, bm, bn, 0, tid);
    CP_COMMIT();

    for (int ch = 0; ch < NCH; ch++) {
        if (ch < NCH - 1) {
            gemm_ld(base + ((ch + 1) & 1) * GBUF, Ah, Al, Bh, Bl, bm, bn, (ch + 1) * 32, tid);
            CP_COMMIT();
            CP_WAIT1();
        } else {
            CP_WAIT0();
        }
        __syncthreads();
        const u32 pAh = base + (ch & 1) * GBUF;
        const u32 pAl = pAh + GARR, pBh = pAh + 2 * GARR, pBl = pAh + 3 * GARR;

#pragma unroll
        for (int kg = 0; kg < 2; kg++) {
            u32 aH[2][4], aL[2][4], bH[2][4], bL[2][4];
#pragma unroll
            for (int am = 0; am < 2; am++) {
                u32 off = (u32)((wm * 32 + am * 16 + a_r) * PAD + kg * 16 + a_h * 8) * 2;
                ldsm4(aH[am], pAh + off);
                ldsm4(aL[am], pAl + off);
            }
#pragma unroll
            for (int np = 0; np < 2; np++) {
                u32 off = (u32)((wn * 32 + np * 16 + (b_q >> 1) * 8 + b_r) * PAD +
                                kg * 16 + (b_q & 1) * 8) * 2;
                ldsm4(bH[np], pBh + off);
                ldsm4(bL[np], pBl + off);
            }
#pragma unroll
            for (int am = 0; am < 2; am++)
#pragma unroll
                for (int nj = 0; nj < 4; nj++) {
                    const u32* bh = &bH[nj >> 1][(nj & 1) * 2];
                    const u32* bl = &bL[nj >> 1][(nj & 1) * 2];
                    mma_bf16(acc[am][nj], aH[am], bh);
                    mma_bf16(acc[am][nj], aH[am], bl);
                    mma_bf16(acc[am][nj], aL[am], bh);
                }
        }
        __syncthreads();
    }

    const int r0 = lane >> 2, cpair = (lane & 3) * 2;
#pragma unroll
    for (int am = 0; am < 2; am++)
#pragma unroll
        for (int half = 0; half < 2; half++) {
            int row = bm + wm * 32 + am * 16 + half * 8 + r0;
#pragma unroll
            for (int nj = 0; nj < 4; nj++) {
                int col = bn + wn * 32 + nj * 8 + cpair;
                float2 val = {acc[am][nj][half * 2], acc[am][nj][half * 2 + 1]};
                if (mode == 0) {
                    if (col < 960) {
                        *(float2*)(q + (size_t)row * 960 + col) = val;
                    } else if (col < 1280) {
                        *(float2*)(k + (size_t)row * 320 + (col - 960)) = val;
                    } else {
                        __half h0 = __float2half_rn(val.x);
                        __half l0 = __float2half_rn(val.x - __half2float(h0));
                        __half h1 = __float2half_rn(val.y);
                        __half l1 = __float2half_rn(val.y - __half2float(h1));
                        size_t o = (size_t)row * 320 + (col - 1280);
                        *(__half2*)(vh + o) = __halves2half2(h0, h1);
                        *(__half2*)(vl + o) = __halves2half2(l0, l1);
                    }
                } else {
                    *(float2*)(C + (size_t)row * 960 + col) = val;
                }
            }
        }
}

// ---------------------------------------------------------------------------
// RoPE + split: q fp32 -> qh/ql (bf16, pre-scaled by QSCALE), k -> kh/kl.
// ---------------------------------------------------------------------------
__global__ void rope_split(const float* __restrict__ q, const float* __restrict__ k,
                           const int* __restrict__ pos,
                           __nv_bfloat16* __restrict__ qh, __nv_bfloat16* __restrict__ ql,
                           __nv_bfloat16* __restrict__ kh, __nv_bfloat16* __restrict__ kl) {
    int idx = blockIdx.x * blockDim.x + threadIdx.x;
    if (idx >= SEQ * 32) return;
    int i = idx & 31;
    int s = idx >> 5;
    float p = (float)pos[s];
    float inv = powf(10000.0f, -(float)i * (1.0f / 32.0f));
    float sn, c;
    sincosf(p * inv, &sn, &c);

    const float* qrow = q + (size_t)s * NH * HD;
#pragma unroll
    for (int h = 0; h < NH; h++) {
        float x1 = qrow[h * HD + i];
        float x2 = qrow[h * HD + i + 32];
        float r1 = (x1 * c - x2 * sn) * QSCALE;
        float r2 = (x2 * c + x1 * sn) * QSCALE;
        size_t o = (size_t)s * NH * HD + h * HD + i;
        __nv_bfloat16 h1 = __float2bfloat16(r1);
        __nv_bfloat16 h2 = __float2bfloat16(r2);
        qh[o] = h1;
        qh[o + 32] = h2;
        ql[o] = __float2bfloat16(r1 - __bfloat162float(h1));
        ql[o + 32] = __float2bfloat16(r2 - __bfloat162float(h2));
    }
    const float* krow = k + (size_t)s * NKV * HD;
#pragma unroll
    for (int h = 0; h < NKV; h++) {
        float x1 = krow[h * HD + i];
        float x2 = krow[h * HD + i + 32];
        float r1 = x1 * c - x2 * sn;
        float r2 = x2 * c + x1 * sn;
        size_t o = (size_t)s * NKV * HD + h * HD + i;
        __nv_bfloat16 h1 = __float2bfloat16(r1);
        __nv_bfloat16 h2 = __float2bfloat16(r2);
        kh[o] = h1;
        kh[o + 32] = h2;
        kl[o] = __float2bfloat16(r1 - __bfloat162float(h1));
        kl[o + 32] = __float2bfloat16(r2 - __bfloat162float(h2));
    }
}

// ---------------------------------------------------------------------------
// HMMA causal flash attention, double-buffered cp.async KV, balanced pairs.
// Grid (32, 15): CTA processes q-tiles {pa, 63-pa} -> uniform 65 iterations.
// Output written directly as bf16 hi/lo (aH/aL) for the O-projection.
// ---------------------------------------------------------------------------
__device__ __forceinline__ void kv_async(u32 dst, const __nv_bfloat16* Kh,
                                         const __nv_bfloat16* Kl, const __half* Vh,
                                         const __half* Vl, int k0, int kvh, int tid) {
#pragma unroll
    for (int u = tid; u < 512; u += 128) {
        int row = u >> 3, c8 = u & 7;
        size_t g = (size_t)(k0 + row) * (NKV * HD) + kvh * HD + c8 * 8;
        u32 so = (u32)(row * FD + c8 * 8) * 2;
        cp16(dst + so, Kh + g);
        cp16(dst + FARR + so, Kl + g);
        cp16(dst + 2 * FARR + so, Vh + g);
        cp16(dst + 3 * FARR + so, Vl + g);
    }
}

__global__ __launch_bounds__(128) void flash_mma(
    const __nv_bfloat16* __restrict__ Qh, const __nv_bfloat16* __restrict__ Ql,
    const __nv_bfloat16* __restrict__ Kh, const __nv_bfloat16* __restrict__ Kl,
    const __half* __restrict__ Vh, const __half* __restrict__ Vl,
    __nv_bfloat16* __restrict__ aH, __nv_bfloat16* __restrict__ aL) {
    extern __shared__ char fsm[];
    const u32 base = smem_to_u32(fsm);
    const int pa = blockIdx.x, h = blockIdx.y, kvh = h / GROUPS;
    const int tid = threadIdx.x, warp = tid >> 5, lane = tid & 31;
    const int sel = lane >> 3, l7 = lane & 7;

    for (int hp = 0; hp < 2; hp++) {
        const int qt = hp ? 63 - pa : pa;
        const int q0 = qt * 64;

        // prefetch KV tile 0 into buf0 (async; overlaps Q staging below)
        kv_async(base, Kh, Kl, Vh, Vl, 0, kvh, tid);
        CP_COMMIT();

        // stage Q via buf1, extract fragments
        for (int u = tid; u < 512; u += 128) {
            int row = u >> 3, c8 = u & 7;
            size_t g = (size_t)(q0 + row) * (NH * HD) + h * HD + c8 * 8;
            u32 so = (u32)(row * FD + c8 * 8) * 2;
            *(uint4*)(fsm + FBUF + so) = *(const uint4*)(Qh + g);
            *(uint4*)(fsm + FBUF + FARR + so) = *(const uint4*)(Ql + g);
        }
        __syncthreads();
        u32 aQh[4][4], aQl[4][4];
        {
            int row = warp * 16 + (lane & 15);
            int csel = (lane >> 4) * 8;
#pragma unroll
            for (int ks = 0; ks < 4; ks++) {
                u32 off = (u32)(row * FD + ks * 16 + csel) * 2;
                ldsm4(aQh[ks], base + FBUF + off);
                ldsm4(aQl[ks], base + FBUF + FARR + off);
            }
        }
        __syncthreads();  // Q frags extracted before buf1 is overwritten (kt=1 prefetch)

        float m_i[2] = {-1e30f, -1e30f}, l_i[2] = {0.f, 0.f};
        float acc_o[8][4];
#pragma unroll
        for (int j = 0; j < 8; j++)
#pragma unroll
            for (int e = 0; e < 4; e++) acc_o[j][e] = 0.f;

        for (int kt = 0; kt <= qt; kt++) {
            if (kt < qt) {
                kv_async(base + ((kt + 1) & 1) * FBUF, Kh, Kl, Vh, Vl,
                         (kt + 1) * 64, kvh, tid);
                CP_COMMIT();
                CP_WAIT1();
            } else {
                CP_WAIT0();
            }
            __syncthreads();
            const u32 pKh = base + (kt & 1) * FBUF;
            const u32 pKl = pKh + FARR, pVh = pKh + 2 * FARR, pVl = pKh + 3 * FARR;

            // ---- S = Q K^T (3-term bf16 split)
            float s[8][4];
#pragma unroll
            for (int j = 0; j < 8; j++)
#pragma unroll
                for (int e = 0; e < 4; e++) s[j][e] = 0.f;

#pragma unroll
            for (int ks = 0; ks < 4; ks++) {
#pragma unroll
                for (int g2 = 0; g2 < 4; g2++) {
                    int key = 16 * g2 + ((sel >> 1) << 3) + l7;
                    int col = ks * 16 + (sel & 1) * 8;
                    u32 off = (u32)(key * FD + col) * 2;
                    u32 bh[4], bl[4];
                    ldsm4(bh, pKh + off);
                    ldsm4(bl, pKl + off);
                    mma_bf16(s[2 * g2], aQh[ks], bh);
                    mma_bf16(s[2 * g2], aQh[ks], bl);
                    mma_bf16(s[2 * g2], aQl[ks], bh);
                    mma_bf16(s[2 * g2 + 1], aQh[ks], bh + 2);
                    mma_bf16(s[2 * g2 + 1], aQh[ks], bl + 2);
                    mma_bf16(s[2 * g2 + 1], aQl[ks], bh + 2);
                }
            }

            // ---- causal mask (diagonal tile only)
            if (kt == qt) {
                const int c0 = (lane & 3) * 2, r0l = warp * 16 + (lane >> 2);
#pragma unroll
                for (int j = 0; j < 8; j++)
#pragma unroll
                    for (int e = 0; e < 4; e++) {
                        int key = 8 * j + c0 + (e & 1);
                        int qr = r0l + (e >> 1) * 8;
                        if (key > qr) s[j][e] = -1e30f;
                    }
            }

            // ---- online softmax (base-2), P -> fp16 fragments
            u32 ph2[8][2];
#pragma unroll
            for (int hf = 0; hf < 2; hf++) {
                float rm = -1e30f;
#pragma unroll
                for (int j = 0; j < 8; j++)
                    rm = fmaxf(rm, fmaxf(s[j][2 * hf], s[j][2 * hf + 1]));
                rm = fmaxf(rm, __shfl_xor_sync(0xffffffffu, rm, 1));
                rm = fmaxf(rm, __shfl_xor_sync(0xffffffffu, rm, 2));
                float mnew = fmaxf(m_i[hf], rm);
                float corr = ex2f(m_i[hf] - mnew);
                m_i[hf] = mnew;
                float rsum = 0.f;
#pragma unroll
                for (int j = 0; j < 8; j++) {
                    float p0 = ex2f(s[j][2 * hf] - mnew);
                    float p1 = ex2f(s[j][2 * hf + 1] - mnew);
                    ph2[j][hf] = pack_h2(p0, p1);
                    rsum += p0 + p1;
                }
                rsum += __shfl_xor_sync(0xffffffffu, rsum, 1);
                rsum += __shfl_xor_sync(0xffffffffu, rsum, 2);
                l_i[hf] = l_i[hf] * corr + rsum;
#pragma unroll
                for (int j = 0; j < 8; j++) {
                    acc_o[j][2 * hf] *= corr;
                    acc_o[j][2 * hf + 1] *= corr;
                }
            }

            // ---- O += P V (fp16, 2-term split V)
#pragma unroll
            for (int g2 = 0; g2 < 4; g2++) {
                u32 pa4[4] = {ph2[2 * g2][0], ph2[2 * g2][1],
                              ph2[2 * g2 + 1][0], ph2[2 * g2 + 1][1]};
#pragma unroll
                for (int dd = 0; dd < 4; dd++) {
                    int key = 16 * g2 + ((sel & 1) << 3) + l7;
                    int col = 16 * dd + ((sel >> 1) << 3);
                    u32 off = (u32)(key * FD + col) * 2;
                    u32 bh[4], bl[4];
                    ldsm4t(bh, pVh + off);
                    ldsm4t(bl, pVl + off);
                    mma_f16(acc_o[2 * dd], pa4, bh);
                    mma_f16(acc_o[2 * dd], pa4, bl);
                    mma_f16(acc_o[2 * dd + 1], pa4, bh + 2);
                    mma_f16(acc_o[2 * dd + 1], pa4, bl + 2);
                }
            }
            __syncthreads();  // all reads of buf[kt&1] done before kt+2 prefetch
        }

        // ---- normalize + write bf16 hi/lo
        const float inv0 = 1.0f / l_i[0], inv1 = 1.0f / l_i[1];
        const int r0 = q0 + warp * 16 + (lane >> 2), c0 = (lane & 3) * 2;
#pragma unroll
        for (int j = 0; j < 8; j++) {
            int col = h * HD + 8 * j + c0;
#pragma unroll
            for (int hf = 0; hf < 2; hf++) {
                float a0 = acc_o[j][2 * hf] * (hf ? inv1 : inv0);
                float a1 = acc_o[j][2 * hf + 1] * (hf ? inv1 : inv0);
                __nv_bfloat16 h0 = __float2bfloat16(a0);
                __nv_bfloat16 h1 = __float2bfloat16(a1);
                __nv_bfloat16 l0 = __float2bfloat16(a0 - __bfloat162float(h0));
                __nv_bfloat16 l1 = __float2bfloat16(a1 - __bfloat162float(h1));
                size_t o = (size_t)(r0 + hf * 8) * EMB + col;
                *(__nv_bfloat162*)(aH + o) = __nv_bfloat162{h0, h1};
                *(__nv_bfloat162*)(aL + o) = __nv_bfloat162{l0, l1};
            }
        }
    }
}

// ---------------------------------------------------------------------------
extern "C" void kernel_launch(void* const* d_in, const int* in_sizes, int n_in,
                              void* d_out, int out_size) {
    const float* hidden = (const float*)d_in[0];
    const float* Wq = (const float*)d_in[1];
    const float* Wk = (const float*)d_in[2];
    const float* Wv = (const float*)d_in[3];
    const float* Wo = (const float*)d_in[4];
    const int* pos = (const int*)d_in[6];
    float* out = (float*)d_out;

    float *q, *k;
    __nv_bfloat16 *hidH, *hidL, *wH, *wL, *woH, *woL, *aH, *aL, *qh, *ql, *kh, *kl;
    __half *vh, *vl;
    cudaGetSymbolAddress((void**)&q, g_q);
    cudaGetSymbolAddress((void**)&k, g_k);
    cudaGetSymbolAddress((void**)&hidH, g_hidH);
    cudaGetSymbolAddress((void**)&hidL, g_hidL);
    cudaGetSymbolAddress((void**)&wH, g_wH);
    cudaGetSymbolAddress((void**)&wL, g_wL);
    cudaGetSymbolAddress((void**)&woH, g_woH);
    cudaGetSymbolAddress((void**)&woL, g_woL);
    cudaGetSymbolAddress((void**)&aH, g_aH);
    cudaGetSymbolAddress((void**)&aL, g_aL);
    cudaGetSymbolAddress((void**)&qh, g_qh);
    cudaGetSymbolAddress((void**)&ql, g_ql);
    cudaGetSymbolAddress((void**)&kh, g_kh);
    cudaGetSymbolAddress((void**)&kl, g_kl);
    cudaGetSymbolAddress((void**)&vh, g_vh);
    cudaGetSymbolAddress((void**)&vl, g_vl);

    static bool attr_set = false;
    if (!attr_set) {
        cudaFuncSetAttribute(flash_mma, cudaFuncAttributeMaxDynamicSharedMemorySize,
                             2 * FBUF);
        attr_set = true;
    }

    // bf16 hi/lo splits (inputs only)
    cvt_split<<<(SEQ * EMB + 255) / 256, 256>>>(hidden, hidH, hidL, SEQ * EMB);
    cvt_split<<<(EMB * KDIM + 255) / 256, 256>>>(Wq, wH, wL, EMB * KDIM);
    cvt_split<<<(320 * KDIM + 255) / 256, 256>>>(Wk, wH + (size_t)960 * KDIM,
                                                 wL + (size_t)960 * KDIM, 320 * KDIM);
    cvt_split<<<(320 * KDIM + 255) / 256, 256>>>(Wv, wH + (size_t)1280 * KDIM,
                                                 wL + (size_t)1280 * KDIM, 320 * KDIM);
    cvt_split<<<(EMB * KDIM + 255) / 256, 256>>>(Wo, woH, woL, EMB * KDIM);

    // fused QKV projection (HMMA, cp.async pipelined); V emitted as fp16 split
    gemm_mma<<<dim3(NQKV / 64, SEQ / 64), 128>>>(hidH, hidL, wH, wL, 0,
                                                 q, k, vh, vl, nullptr);

    // RoPE + split (q pre-scaled)
    rope_split<<<(SEQ * 32 + 255) / 256, 256>>>(q, k, pos, qh, ql, kh, kl);

    // flash attention (HMMA, balanced pairs, double-buffered)
    flash_mma<<<dim3(32, NH), 128, 2 * FBUF>>>(qh, ql, kh, kl, vh, vl, aH, aL);

    // O projection (HMMA)
    gemm_mma<<<dim3(EMB / 64, SEQ / 64), 128>>>(aH, aL, woH, woL, 1,
                                                nullptr, nullptr, nullptr, nullptr, out);
}

// round 9
// speedup vs baseline: 5.0542x; 1.1198x over previous
#include <cuda_runtime.h>
#include <cuda_bf16.h>
#include <cuda_fp16.h>
#include <stdint.h>
#include <math.h>

#define SEQ 4096
#define EMB 960
#define NH 15
#define NKV 5
#define HD 64
#define GROUPS 3
#define KDIM 960
#define NQKV 1600
#define FD 72                 // flash smem row stride (elems)
#define FARR (64 * FD * 2)    // 9216 B per flash array
#define FBUF (3 * FARR)       // 27648 B per flash KV buffer (Kh, Kl, Vh)
#define QSCALE 0.18033688011112042f  // 0.125 * log2(e)

typedef uint32_t u32;

// ---- PTX helpers ----------------------------------------------------------
__device__ __forceinline__ uint32_t smem_to_u32(const void* p) {
    uint32_t a;
    asm("{ .reg .u64 t; cvta.to.shared.u64 t, %1; cvt.u32.u64 %0, t; }" : "=r"(a) : "l"(p));
    return a;
}
__device__ __forceinline__ void mma_bf16(float* c, const u32* a, const u32* b) {
    asm volatile(
        "mma.sync.aligned.m16n8k16.row.col.f32.bf16.bf16.f32 "
        "{%0,%1,%2,%3}, {%4,%5,%6,%7}, {%8,%9}, {%0,%1,%2,%3};"
        : "+f"(c[0]), "+f"(c[1]), "+f"(c[2]), "+f"(c[3])
        : "r"(a[0]), "r"(a[1]), "r"(a[2]), "r"(a[3]), "r"(b[0]), "r"(b[1]));
}
__device__ __forceinline__ void mma_f16(float* c, const u32* a, const u32* b) {
    asm volatile(
        "mma.sync.aligned.m16n8k16.row.col.f32.f16.f16.f32 "
        "{%0,%1,%2,%3}, {%4,%5,%6,%7}, {%8,%9}, {%0,%1,%2,%3};"
        : "+f"(c[0]), "+f"(c[1]), "+f"(c[2]), "+f"(c[3])
        : "r"(a[0]), "r"(a[1]), "r"(a[2]), "r"(a[3]), "r"(b[0]), "r"(b[1]));
}
__device__ __forceinline__ void ldsm4(u32* r, u32 addr) {
    asm volatile("ldmatrix.sync.aligned.m8n8.x4.shared.b16 {%0,%1,%2,%3}, [%4];"
                 : "=r"(r[0]), "=r"(r[1]), "=r"(r[2]), "=r"(r[3]) : "r"(addr));
}
__device__ __forceinline__ void ldsm4t(u32* r, u32 addr) {
    asm volatile("ldmatrix.sync.aligned.m8n8.x4.trans.shared.b16 {%0,%1,%2,%3}, [%4];"
                 : "=r"(r[0]), "=r"(r[1]), "=r"(r[2]), "=r"(r[3]) : "r"(addr));
}
__device__ __forceinline__ float ex2f(float x) {
    float y; asm("ex2.approx.f32 %0, %1;" : "=f"(y) : "f"(x)); return y;
}
__device__ __forceinline__ u32 pack_h2(float lo, float hi) {
    u32 r; asm("cvt.rn.f16x2.f32 %0, %1, %2;" : "=r"(r) : "f"(hi), "f"(lo)); return r;
}
__device__ __forceinline__ void cp16(u32 saddr, const void* g) {
    asm volatile("cp.async.cg.shared.global [%0], [%1], 16;" :: "r"(saddr), "l"(g));
}
#define CP_COMMIT() asm volatile("cp.async.commit_group;" ::: "memory")
#define CP_WAIT1() asm volatile("cp.async.wait_group 1;" ::: "memory")
#define CP_WAIT0() asm volatile("cp.async.wait_group 0;" ::: "memory")

// ---- scratch --------------------------------------------------------------
__device__ float g_q[SEQ * NH * HD];
__device__ float g_k[SEQ * NKV * HD];
__device__ __nv_bfloat16 g_hidH[SEQ * EMB];
__device__ __nv_bfloat16 g_hidL[SEQ * EMB];
__device__ __nv_bfloat16 g_wH[NQKV * KDIM];
__device__ __nv_bfloat16 g_wL[NQKV * KDIM];
__device__ __nv_bfloat16 g_woH[EMB * KDIM];
__device__ __nv_bfloat16 g_woL[EMB * KDIM];
__device__ __nv_bfloat16 g_aH[SEQ * EMB];
__device__ __nv_bfloat16 g_aL[SEQ * EMB];
__device__ __nv_bfloat16 g_qh[SEQ * NH * HD];
__device__ __nv_bfloat16 g_ql[SEQ * NH * HD];
__device__ __nv_bfloat16 g_kh[SEQ * NKV * HD];
__device__ __nv_bfloat16 g_kl[SEQ * NKV * HD];
__device__ __half g_vh[SEQ * NKV * HD];

// ---------------------------------------------------------------------------
__global__ void cvt_split(const float* __restrict__ src, __nv_bfloat16* __restrict__ hi,
                          __nv_bfloat16* __restrict__ lo, int n) {
    int i = blockIdx.x * blockDim.x + threadIdx.x;
    if (i >= n) return;
    float x = src[i];
    __nv_bfloat16 h = __float2bfloat16(x);
    hi[i] = h;
    lo[i] = __float2bfloat16(x - __bfloat162float(h));
}

// ---------------------------------------------------------------------------
// HMMA bf16-split GEMM with cp.async double buffering.
// mode 0: q fp32 (col<960), k fp32 (<1280), V as single fp16 (>=1280)
// mode 1: C fp32
// ---------------------------------------------------------------------------
#define PAD 40
#define GARR (64 * PAD * 2)   // 5120 B
#define GBUF (4 * GARR)       // 20480 B

__device__ __forceinline__ void gemm_ld(
    u32 sbase, const __nv_bfloat16* Ah, const __nv_bfloat16* Al,
    const __nv_bfloat16* Bh, const __nv_bfloat16* Bl, int bm, int bn, int k0, int tid) {
#pragma unroll
    for (int it = 0; it < 2; it++) {
        int idx = tid + it * 128;
        int row = idx >> 2, c16 = idx & 3;
        size_t ga = (size_t)(bm + row) * KDIM + k0 + c16 * 8;
        size_t gb = (size_t)(bn + row) * KDIM + k0 + c16 * 8;
        u32 so = (u32)(row * PAD + c16 * 8) * 2;
        cp16(sbase + so, Ah + ga);
        cp16(sbase + GARR + so, Al + ga);
        cp16(sbase + 2 * GARR + so, Bh + gb);
        cp16(sbase + 3 * GARR + so, Bl + gb);
    }
}

__global__ __launch_bounds__(128) void gemm_mma(
    const __nv_bfloat16* __restrict__ Ah, const __nv_bfloat16* __restrict__ Al,
    const __nv_bfloat16* __restrict__ Bh, const __nv_bfloat16* __restrict__ Bl,
    int mode, float* __restrict__ q, float* __restrict__ k,
    __half* __restrict__ vh, float* __restrict__ C) {
    __shared__ __nv_bfloat16 gsm[2 * 4 * 64 * PAD];
    const u32 base = smem_to_u32(gsm);
    const int tid = threadIdx.x;
    const int warp = tid >> 5, lane = tid & 31;
    const int wm = warp & 1, wn = warp >> 1;
    const int bm = blockIdx.y * 64, bn = blockIdx.x * 64;

    float acc[2][4][4];
#pragma unroll
    for (int am = 0; am < 2; am++)
#pragma unroll
        for (int nj = 0; nj < 4; nj++)
#pragma unroll
            for (int e = 0; e < 4; e++) acc[am][nj][e] = 0.f;

    const int a_r = lane & 15, a_h = lane >> 4;
    const int b_r = lane & 7, b_q = lane >> 3;
    const int NCH = KDIM / 32;  // 30

    gemm_ld(base, Ah, Al, Bh, Bl, bm, bn, 0, tid);
    CP_COMMIT();

    for (int ch = 0; ch < NCH; ch++) {
        if (ch < NCH - 1) {
            gemm_ld(base + ((ch + 1) & 1) * GBUF, Ah, Al, Bh, Bl, bm, bn, (ch + 1) * 32, tid);
            CP_COMMIT();
            CP_WAIT1();
        } else {
            CP_WAIT0();
        }
        __syncthreads();
        const u32 pAh = base + (ch & 1) * GBUF;
        const u32 pAl = pAh + GARR, pBh = pAh + 2 * GARR, pBl = pAh + 3 * GARR;

#pragma unroll
        for (int kg = 0; kg < 2; kg++) {
            u32 aH[2][4], aL[2][4], bH[2][4], bL[2][4];
#pragma unroll
            for (int am = 0; am < 2; am++) {
                u32 off = (u32)((wm * 32 + am * 16 + a_r) * PAD + kg * 16 + a_h * 8) * 2;
                ldsm4(aH[am], pAh + off);
                ldsm4(aL[am], pAl + off);
            }
#pragma unroll
            for (int np = 0; np < 2; np++) {
                u32 off = (u32)((wn * 32 + np * 16 + (b_q >> 1) * 8 + b_r) * PAD +
                                kg * 16 + (b_q & 1) * 8) * 2;
                ldsm4(bH[np], pBh + off);
                ldsm4(bL[np], pBl + off);
            }
#pragma unroll
            for (int am = 0; am < 2; am++)
#pragma unroll
                for (int nj = 0; nj < 4; nj++) {
                    const u32* bh = &bH[nj >> 1][(nj & 1) * 2];
                    const u32* bl = &bL[nj >> 1][(nj & 1) * 2];
                    mma_bf16(acc[am][nj], aH[am], bh);
                    mma_bf16(acc[am][nj], aH[am], bl);
                    mma_bf16(acc[am][nj], aL[am], bh);
                }
        }
        __syncthreads();
    }

    const int r0 = lane >> 2, cpair = (lane & 3) * 2;
#pragma unroll
    for (int am = 0; am < 2; am++)
#pragma unroll
        for (int half = 0; half < 2; half++) {
            int row = bm + wm * 32 + am * 16 + half * 8 + r0;
#pragma unroll
            for (int nj = 0; nj < 4; nj++) {
                int col = bn + wn * 32 + nj * 8 + cpair;
                float2 val = {acc[am][nj][half * 2], acc[am][nj][half * 2 + 1]};
                if (mode == 0) {
                    if (col < 960) {
                        *(float2*)(q + (size_t)row * 960 + col) = val;
                    } else if (col < 1280) {
                        *(float2*)(k + (size_t)row * 320 + (col - 960)) = val;
                    } else {
                        size_t o = (size_t)row * 320 + (col - 1280);
                        *(__half2*)(vh + o) =
                            __halves2half2(__float2half_rn(val.x), __float2half_rn(val.y));
                    }
                } else {
                    *(float2*)(C + (size_t)row * 960 + col) = val;
                }
            }
        }
}

// ---------------------------------------------------------------------------
// RoPE + split: q fp32 -> qh/ql (bf16, pre-scaled by QSCALE), k -> kh/kl.
// ---------------------------------------------------------------------------
__global__ void rope_split(const float* __restrict__ q, const float* __restrict__ k,
                           const int* __restrict__ pos,
                           __nv_bfloat16* __restrict__ qh, __nv_bfloat16* __restrict__ ql,
                           __nv_bfloat16* __restrict__ kh, __nv_bfloat16* __restrict__ kl) {
    int idx = blockIdx.x * blockDim.x + threadIdx.x;
    if (idx >= SEQ * 32) return;
    int i = idx & 31;
    int s = idx >> 5;
    float p = (float)pos[s];
    float inv = powf(10000.0f, -(float)i * (1.0f / 32.0f));
    float sn, c;
    sincosf(p * inv, &sn, &c);

    const float* qrow = q + (size_t)s * NH * HD;
#pragma unroll
    for (int h = 0; h < NH; h++) {
        float x1 = qrow[h * HD + i];
        float x2 = qrow[h * HD + i + 32];
        float r1 = (x1 * c - x2 * sn) * QSCALE;
        float r2 = (x2 * c + x1 * sn) * QSCALE;
        size_t o = (size_t)s * NH * HD + h * HD + i;
        __nv_bfloat16 h1 = __float2bfloat16(r1);
        __nv_bfloat16 h2 = __float2bfloat16(r2);
        qh[o] = h1;
        qh[o + 32] = h2;
        ql[o] = __float2bfloat16(r1 - __bfloat162float(h1));
        ql[o + 32] = __float2bfloat16(r2 - __bfloat162float(h2));
    }
    const float* krow = k + (size_t)s * NKV * HD;
#pragma unroll
    for (int h = 0; h < NKV; h++) {
        float x1 = krow[h * HD + i];
        float x2 = krow[h * HD + i + 32];
        float r1 = x1 * c - x2 * sn;
        float r2 = x2 * c + x1 * sn;
        size_t o = (size_t)s * NKV * HD + h * HD + i;
        __nv_bfloat16 h1 = __float2bfloat16(r1);
        __nv_bfloat16 h2 = __float2bfloat16(r2);
        kh[o] = h1;
        kh[o + 32] = h2;
        kl[o] = __float2bfloat16(r1 - __bfloat162float(h1));
        kl[o + 32] = __float2bfloat16(r2 - __bfloat162float(h2));
    }
}

// ---------------------------------------------------------------------------
// HMMA causal flash attention, double-buffered cp.async KV, balanced pairs.
// Grid (32, 15): CTA processes q-tiles {pa, 63-pa} -> uniform 65 iterations.
// V is single fp16. Output written as bf16 hi/lo (aH/aL) for the O-projection.
// ---------------------------------------------------------------------------
__device__ __forceinline__ void kv_async(u32 dst, const __nv_bfloat16* Kh,
                                         const __nv_bfloat16* Kl, const __half* Vh,
                                         int k0, int kvh, int tid) {
#pragma unroll
    for (int u = tid; u < 512; u += 128) {
        int row = u >> 3, c8 = u & 7;
        size_t g = (size_t)(k0 + row) * (NKV * HD) + kvh * HD + c8 * 8;
        u32 so = (u32)(row * FD + c8 * 8) * 2;
        cp16(dst + so, Kh + g);
        cp16(dst + FARR + so, Kl + g);
        cp16(dst + 2 * FARR + so, Vh + g);
    }
}

__global__ __launch_bounds__(128) void flash_mma(
    const __nv_bfloat16* __restrict__ Qh, const __nv_bfloat16* __restrict__ Ql,
    const __nv_bfloat16* __restrict__ Kh, const __nv_bfloat16* __restrict__ Kl,
    const __half* __restrict__ Vh,
    __nv_bfloat16* __restrict__ aH, __nv_bfloat16* __restrict__ aL) {
    extern __shared__ char fsm[];
    const u32 base = smem_to_u32(fsm);
    const int pa = blockIdx.x, h = blockIdx.y, kvh = h / GROUPS;
    const int tid = threadIdx.x, warp = tid >> 5, lane = tid & 31;
    const int sel = lane >> 3, l7 = lane & 7;

    for (int hp = 0; hp < 2; hp++) {
        const int qt = hp ? 63 - pa : pa;
        const int q0 = qt * 64;

        // prefetch KV tile 0 into buf0 (async; overlaps Q staging below)
        kv_async(base, Kh, Kl, Vh, 0, kvh, tid);
        CP_COMMIT();

        // stage Q via buf1, extract fragments
        for (int u = tid; u < 512; u += 128) {
            int row = u >> 3, c8 = u & 7;
            size_t g = (size_t)(q0 + row) * (NH * HD) + h * HD + c8 * 8;
            u32 so = (u32)(row * FD + c8 * 8) * 2;
            *(uint4*)(fsm + FBUF + so) = *(const uint4*)(Qh + g);
            *(uint4*)(fsm + FBUF + FARR + so) = *(const uint4*)(Ql + g);
        }
        __syncthreads();
        u32 aQh[4][4], aQl[4][4];
        {
            int row = warp * 16 + (lane & 15);
            int csel = (lane >> 4) * 8;
#pragma unroll
            for (int ks = 0; ks < 4; ks++) {
                u32 off = (u32)(row * FD + ks * 16 + csel) * 2;
                ldsm4(aQh[ks], base + FBUF + off);
                ldsm4(aQl[ks], base + FBUF + FARR + off);
            }
        }
        __syncthreads();  // Q frags extracted before buf1 is overwritten (kt=1 prefetch)

        float m_i[2] = {-1e30f, -1e30f}, l_i[2] = {0.f, 0.f};
        float acc_o[8][4];
#pragma unroll
        for (int j = 0; j < 8; j++)
#pragma unroll
            for (int e = 0; e < 4; e++) acc_o[j][e] = 0.f;

        for (int kt = 0; kt <= qt; kt++) {
            if (kt < qt) {
                kv_async(base + ((kt + 1) & 1) * FBUF, Kh, Kl, Vh, (kt + 1) * 64, kvh, tid);
                CP_COMMIT();
                CP_WAIT1();
            } else {
                CP_WAIT0();
            }
            __syncthreads();
            const u32 pKh = base + (kt & 1) * FBUF;
            const u32 pKl = pKh + FARR, pVh = pKh + 2 * FARR;

            // ---- S = Q K^T (3-term bf16 split)
            float s[8][4];
#pragma unroll
            for (int j = 0; j < 8; j++)
#pragma unroll
                for (int e = 0; e < 4; e++) s[j][e] = 0.f;

#pragma unroll
            for (int ks = 0; ks < 4; ks++) {
#pragma unroll
                for (int g2 = 0; g2 < 4; g2++) {
                    int key = 16 * g2 + ((sel >> 1) << 3) + l7;
                    int col = ks * 16 + (sel & 1) * 8;
                    u32 off = (u32)(key * FD + col) * 2;
                    u32 bh[4], bl[4];
                    ldsm4(bh, pKh + off);
                    ldsm4(bl, pKl + off);
                    mma_bf16(s[2 * g2], aQh[ks], bh);
                    mma_bf16(s[2 * g2], aQh[ks], bl);
                    mma_bf16(s[2 * g2], aQl[ks], bh);
                    mma_bf16(s[2 * g2 + 1], aQh[ks], bh + 2);
                    mma_bf16(s[2 * g2 + 1], aQh[ks], bl + 2);
                    mma_bf16(s[2 * g2 + 1], aQl[ks], bh + 2);
                }
            }

            // ---- causal mask (diagonal tile only)
            if (kt == qt) {
                const int c0 = (lane & 3) * 2, r0l = warp * 16 + (lane >> 2);
#pragma unroll
                for (int j = 0; j < 8; j++)
#pragma unroll
                    for (int e = 0; e < 4; e++) {
                        int key = 8 * j + c0 + (e & 1);
                        int qr = r0l + (e >> 1) * 8;
                        if (key > qr) s[j][e] = -1e30f;
                    }
            }

            // ---- online softmax (base-2), P -> fp16 fragments
            u32 ph2[8][2];
#pragma unroll
            for (int hf = 0; hf < 2; hf++) {
                float rm = -1e30f;
#pragma unroll
                for (int j = 0; j < 8; j++)
                    rm = fmaxf(rm, fmaxf(s[j][2 * hf], s[j][2 * hf + 1]));
                rm = fmaxf(rm, __shfl_xor_sync(0xffffffffu, rm, 1));
                rm = fmaxf(rm, __shfl_xor_sync(0xffffffffu, rm, 2));
                float mnew = fmaxf(m_i[hf], rm);
                float corr = ex2f(m_i[hf] - mnew);
                m_i[hf] = mnew;
                float rsum = 0.f;
#pragma unroll
                for (int j = 0; j < 8; j++) {
                    float p0 = ex2f(s[j][2 * hf] - mnew);
                    float p1 = ex2f(s[j][2 * hf + 1] - mnew);
                    ph2[j][hf] = pack_h2(p0, p1);
                    rsum += p0 + p1;
                }
                rsum += __shfl_xor_sync(0xffffffffu, rsum, 1);
                rsum += __shfl_xor_sync(0xffffffffu, rsum, 2);
                l_i[hf] = l_i[hf] * corr + rsum;
#pragma unroll
                for (int j = 0; j < 8; j++) {
                    acc_o[j][2 * hf] *= corr;
                    acc_o[j][2 * hf + 1] *= corr;
                }
            }

            // ---- O += P V (fp16, single-term V)
#pragma unroll
            for (int g2 = 0; g2 < 4; g2++) {
                u32 pa4[4] = {ph2[2 * g2][0], ph2[2 * g2][1],
                              ph2[2 * g2 + 1][0], ph2[2 * g2 + 1][1]};
#pragma unroll
                for (int dd = 0; dd < 4; dd++) {
                    int key = 16 * g2 + ((sel & 1) << 3) + l7;
                    int col = 16 * dd + ((sel >> 1) << 3);
                    u32 off = (u32)(key * FD + col) * 2;
                    u32 bh[4];
                    ldsm4t(bh, pVh + off);
                    mma_f16(acc_o[2 * dd], pa4, bh);
                    mma_f16(acc_o[2 * dd + 1], pa4, bh + 2);
                }
            }
            __syncthreads();  // all reads of buf[kt&1] done before kt+2 prefetch
        }

        // ---- normalize + write bf16 hi/lo
        const float inv0 = 1.0f / l_i[0], inv1 = 1.0f / l_i[1];
        const int r0 = q0 + warp * 16 + (lane >> 2), c0 = (lane & 3) * 2;
#pragma unroll
        for (int j = 0; j < 8; j++) {
            int col = h * HD + 8 * j + c0;
#pragma unroll
            for (int hf = 0; hf < 2; hf++) {
                float a0 = acc_o[j][2 * hf] * (hf ? inv1 : inv0);
                float a1 = acc_o[j][2 * hf + 1] * (hf ? inv1 : inv0);
                __nv_bfloat16 h0 = __float2bfloat16(a0);
                __nv_bfloat16 h1 = __float2bfloat16(a1);
                __nv_bfloat16 l0 = __float2bfloat16(a0 - __bfloat162float(h0));
                __nv_bfloat16 l1 = __float2bfloat16(a1 - __bfloat162float(h1));
                size_t o = (size_t)(r0 + hf * 8) * EMB + col;
                *(__nv_bfloat162*)(aH + o) = __nv_bfloat162{h0, h1};
                *(__nv_bfloat162*)(aL + o) = __nv_bfloat162{l0, l1};
            }
        }
    }
}

// ---------------------------------------------------------------------------
extern "C" void kernel_launch(void* const* d_in, const int* in_sizes, int n_in,
                              void* d_out, int out_size) {
    const float* hidden = (const float*)d_in[0];
    const float* Wq = (const float*)d_in[1];
    const float* Wk = (const float*)d_in[2];
    const float* Wv = (const float*)d_in[3];
    const float* Wo = (const float*)d_in[4];
    const int* pos = (const int*)d_in[6];
    float* out = (float*)d_out;

    float *q, *k;
    __nv_bfloat16 *hidH, *hidL, *wH, *wL, *woH, *woL, *aH, *aL, *qh, *ql, *kh, *kl;
    __half *vh;
    cudaGetSymbolAddress((void**)&q, g_q);
    cudaGetSymbolAddress((void**)&k, g_k);
    cudaGetSymbolAddress((void**)&hidH, g_hidH);
    cudaGetSymbolAddress((void**)&hidL, g_hidL);
    cudaGetSymbolAddress((void**)&wH, g_wH);
    cudaGetSymbolAddress((void**)&wL, g_wL);
    cudaGetSymbolAddress((void**)&woH, g_woH);
    cudaGetSymbolAddress((void**)&woL, g_woL);
    cudaGetSymbolAddress((void**)&aH, g_aH);
    cudaGetSymbolAddress((void**)&aL, g_aL);
    cudaGetSymbolAddress((void**)&qh, g_qh);
    cudaGetSymbolAddress((void**)&ql, g_ql);
    cudaGetSymbolAddress((void**)&kh, g_kh);
    cudaGetSymbolAddress((void**)&kl, g_kl);
    cudaGetSymbolAddress((void**)&vh, g_vh);

    static bool attr_set = false;
    if (!attr_set) {
        cudaFuncSetAttribute(flash_mma, cudaFuncAttributeMaxDynamicSharedMemorySize,
                             2 * FBUF);
        attr_set = true;
    }

    // bf16 hi/lo splits (inputs only)
    cvt_split<<<(SEQ * EMB + 255) / 256, 256>>>(hidden, hidH, hidL, SEQ * EMB);
    cvt_split<<<(EMB * KDIM + 255) / 256, 256>>>(Wq, wH, wL, EMB * KDIM);
    cvt_split<<<(320 * KDIM + 255) / 256, 256>>>(Wk, wH + (size_t)960 * KDIM,
                                                 wL + (size_t)960 * KDIM, 320 * KDIM);
    cvt_split<<<(320 * KDIM + 255) / 256, 256>>>(Wv, wH + (size_t)1280 * KDIM,
                                                 wL + (size_t)1280 * KDIM, 320 * KDIM);
    cvt_split<<<(EMB * KDIM + 255) / 256, 256>>>(Wo, woH, woL, EMB * KDIM);

    // fused QKV projection (HMMA, cp.async pipelined); V emitted as fp16
    gemm_mma<<<dim3(NQKV / 64, SEQ / 64), 128>>>(hidH, hidL, wH, wL, 0,
                                                 q, k, vh, nullptr);

    // RoPE + split (q pre-scaled)
    rope_split<<<(SEQ * 32 + 255) / 256, 256>>>(q, k, pos, qh, ql, kh, kl);

    // flash attention (HMMA, balanced pairs, double-buffered)
    flash_mma<<<dim3(32, NH), 128, 2 * FBUF>>>(qh, ql, kh, kl, vh, aH, aL);

    // O projection (HMMA)
    gemm_mma<<<dim3(EMB / 64, SEQ / 64), 128>>>(aH, aL, woH, woL, 1,
                                                nullptr, nullptr, nullptr, out);
}

// round 10
// speedup vs baseline: 6.5093x; 1.2879x over previous
#include <cuda_runtime.h>
#include <cuda_bf16.h>
#include <cuda_fp16.h>
#include <stdint.h>
#include <math.h>

#define SEQ 4096
#define EMB 960
#define NH 15
#define NKV 5
#define HD 64
#define GROUPS 3
#define KDIM 960
#define NQKV 1600
#define FD 72                 // flash smem row stride (elems)
#define FARR (64 * FD * 2)    // 9216 B per flash array
#define FBUF (2 * FARR)       // 18432 B per flash KV buffer (Kf, Vf)
#define QSCALE 0.18033688011112042f  // 0.125 * log2(e), folded into K

typedef uint32_t u32;

// ---- PTX helpers ----------------------------------------------------------
__device__ __forceinline__ uint32_t smem_to_u32(const void* p) {
    uint32_t a;
    asm("{ .reg .u64 t; cvta.to.shared.u64 t, %1; cvt.u32.u64 %0, t; }" : "=r"(a) : "l"(p));
    return a;
}
__device__ __forceinline__ void mma_f16(float* c, const u32* a, const u32* b) {
    asm volatile(
        "mma.sync.aligned.m16n8k16.row.col.f32.f16.f16.f32 "
        "{%0,%1,%2,%3}, {%4,%5,%6,%7}, {%8,%9}, {%0,%1,%2,%3};"
        : "+f"(c[0]), "+f"(c[1]), "+f"(c[2]), "+f"(c[3])
        : "r"(a[0]), "r"(a[1]), "r"(a[2]), "r"(a[3]), "r"(b[0]), "r"(b[1]));
}
__device__ __forceinline__ void ldsm4(u32* r, u32 addr) {
    asm volatile("ldmatrix.sync.aligned.m8n8.x4.shared.b16 {%0,%1,%2,%3}, [%4];"
                 : "=r"(r[0]), "=r"(r[1]), "=r"(r[2]), "=r"(r[3]) : "r"(addr));
}
__device__ __forceinline__ void ldsm4t(u32* r, u32 addr) {
    asm volatile("ldmatrix.sync.aligned.m8n8.x4.trans.shared.b16 {%0,%1,%2,%3}, [%4];"
                 : "=r"(r[0]), "=r"(r[1]), "=r"(r[2]), "=r"(r[3]) : "r"(addr));
}
__device__ __forceinline__ float ex2f(float x) {
    float y; asm("ex2.approx.f32 %0, %1;" : "=f"(y) : "f"(x)); return y;
}
__device__ __forceinline__ u32 pack_h2(float lo, float hi) {
    u32 r; asm("cvt.rn.f16x2.f32 %0, %1, %2;" : "=r"(r) : "f"(hi), "f"(lo)); return r;
}
__device__ __forceinline__ void cp16(u32 saddr, const void* g) {
    asm volatile("cp.async.cg.shared.global [%0], [%1], 16;" :: "r"(saddr), "l"(g));
}
#define CP_COMMIT() asm volatile("cp.async.commit_group;" ::: "memory")
#define CP_WAIT1() asm volatile("cp.async.wait_group 1;" ::: "memory")
#define CP_WAIT0() asm volatile("cp.async.wait_group 0;" ::: "memory")

// ---- scratch --------------------------------------------------------------
__device__ float g_q[SEQ * NH * HD];
__device__ float g_k[SEQ * NKV * HD];
__device__ __half g_hidF[SEQ * EMB];
__device__ __half g_wH[NQKV * KDIM];
__device__ __half g_wL[NQKV * KDIM];
__device__ __half g_woH[EMB * KDIM];
__device__ __half g_woL[EMB * KDIM];
__device__ __half g_aF[SEQ * EMB];
__device__ __half g_qh[SEQ * NH * HD];
__device__ __half g_ql[SEQ * NH * HD];
__device__ __half g_kf[SEQ * NKV * HD];
__device__ __half g_vh[SEQ * NKV * HD];

// ---------------------------------------------------------------------------
__global__ void cvt_f16(const float* __restrict__ src, __half* __restrict__ dst, int n) {
    int i = blockIdx.x * blockDim.x + threadIdx.x;
    if (i >= n) return;
    dst[i] = __float2half_rn(src[i]);
}
__global__ void cvt_split_f16(const float* __restrict__ src, __half* __restrict__ hi,
                              __half* __restrict__ lo, int n) {
    int i = blockIdx.x * blockDim.x + threadIdx.x;
    if (i >= n) return;
    float x = src[i];
    __half h = __float2half_rn(x);
    hi[i] = h;
    lo[i] = __float2half_rn(x - __half2float(h));
}

// ---------------------------------------------------------------------------
// HMMA fp16 GEMM: C[M,N] = A(fp16) @ (Bh+Bl)(fp16 split)^T, fp32 acc,
// cp.async double buffered. 2 MMAs per (am,nj) instead of 3.
// mode 0: q fp32 (col<960), k fp32 (<1280), V as fp16 (>=1280); mode 1: C fp32
// ---------------------------------------------------------------------------
#define PAD 40
#define GARR (64 * PAD * 2)   // 5120 B
#define GBUF (3 * GARR)       // 15360 B

__device__ __forceinline__ void gemm_ld(
    u32 sbase, const __half* A, const __half* Bh, const __half* Bl,
    int bm, int bn, int k0, int tid) {
#pragma unroll
    for (int it = 0; it < 2; it++) {
        int idx = tid + it * 128;
        int row = idx >> 2, c16 = idx & 3;
        size_t ga = (size_t)(bm + row) * KDIM + k0 + c16 * 8;
        size_t gb = (size_t)(bn + row) * KDIM + k0 + c16 * 8;
        u32 so = (u32)(row * PAD + c16 * 8) * 2;
        cp16(sbase + so, A + ga);
        cp16(sbase + GARR + so, Bh + gb);
        cp16(sbase + 2 * GARR + so, Bl + gb);
    }
}

__global__ __launch_bounds__(128) void gemm_mma(
    const __half* __restrict__ A, const __half* __restrict__ Bh,
    const __half* __restrict__ Bl, int mode, float* __restrict__ q,
    float* __restrict__ k, __half* __restrict__ vh, float* __restrict__ C) {
    __shared__ __half gsm[2 * 3 * 64 * PAD];
    const u32 base = smem_to_u32(gsm);
    const int tid = threadIdx.x;
    const int warp = tid >> 5, lane = tid & 31;
    const int wm = warp & 1, wn = warp >> 1;
    const int bm = blockIdx.y * 64, bn = blockIdx.x * 64;

    float acc[2][4][4];
#pragma unroll
    for (int am = 0; am < 2; am++)
#pragma unroll
        for (int nj = 0; nj < 4; nj++)
#pragma unroll
            for (int e = 0; e < 4; e++) acc[am][nj][e] = 0.f;

    const int a_r = lane & 15, a_h = lane >> 4;
    const int b_r = lane & 7, b_q = lane >> 3;
    const int NCH = KDIM / 32;  // 30

    gemm_ld(base, A, Bh, Bl, bm, bn, 0, tid);
    CP_COMMIT();

    for (int ch = 0; ch < NCH; ch++) {
        if (ch < NCH - 1) {
            gemm_ld(base + ((ch + 1) & 1) * GBUF, A, Bh, Bl, bm, bn, (ch + 1) * 32, tid);
            CP_COMMIT();
            CP_WAIT1();
        } else {
            CP_WAIT0();
        }
        __syncthreads();
        const u32 pA = base + (ch & 1) * GBUF;
        const u32 pBh = pA + GARR, pBl = pA + 2 * GARR;

#pragma unroll
        for (int kg = 0; kg < 2; kg++) {
            u32 aF[2][4], bH[2][4], bL[2][4];
#pragma unroll
            for (int am = 0; am < 2; am++) {
                u32 off = (u32)((wm * 32 + am * 16 + a_r) * PAD + kg * 16 + a_h * 8) * 2;
                ldsm4(aF[am], pA + off);
            }
#pragma unroll
            for (int np = 0; np < 2; np++) {
                u32 off = (u32)((wn * 32 + np * 16 + (b_q >> 1) * 8 + b_r) * PAD +
                                kg * 16 + (b_q & 1) * 8) * 2;
                ldsm4(bH[np], pBh + off);
                ldsm4(bL[np], pBl + off);
            }
#pragma unroll
            for (int am = 0; am < 2; am++)
#pragma unroll
                for (int nj = 0; nj < 4; nj++) {
                    const u32* bh = &bH[nj >> 1][(nj & 1) * 2];
                    const u32* bl = &bL[nj >> 1][(nj & 1) * 2];
                    mma_f16(acc[am][nj], aF[am], bh);
                    mma_f16(acc[am][nj], aF[am], bl);
                }
        }
        __syncthreads();
    }

    const int r0 = lane >> 2, cpair = (lane & 3) * 2;
#pragma unroll
    for (int am = 0; am < 2; am++)
#pragma unroll
        for (int half = 0; half < 2; half++) {
            int row = bm + wm * 32 + am * 16 + half * 8 + r0;
#pragma unroll
            for (int nj = 0; nj < 4; nj++) {
                int col = bn + wn * 32 + nj * 8 + cpair;
                float2 val = {acc[am][nj][half * 2], acc[am][nj][half * 2 + 1]};
                if (mode == 0) {
                    if (col < 960) {
                        *(float2*)(q + (size_t)row * 960 + col) = val;
                    } else if (col < 1280) {
                        *(float2*)(k + (size_t)row * 320 + (col - 960)) = val;
                    } else {
                        size_t o = (size_t)row * 320 + (col - 1280);
                        *(__half2*)(vh + o) =
                            __halves2half2(__float2half_rn(val.x), __float2half_rn(val.y));
                    }
                } else {
                    *(float2*)(C + (size_t)row * 960 + col) = val;
                }
            }
        }
}

// ---------------------------------------------------------------------------
// RoPE + split: q -> qh/ql (fp16 hi/lo, UNscaled: residuals stay normal-range),
// k -> kf (single fp16, pre-scaled by QSCALE).
// ---------------------------------------------------------------------------
__global__ void rope_split(const float* __restrict__ q, const float* __restrict__ k,
                           const int* __restrict__ pos,
                           __half* __restrict__ qh, __half* __restrict__ ql,
                           __half* __restrict__ kf) {
    int idx = blockIdx.x * blockDim.x + threadIdx.x;
    if (idx >= SEQ * 32) return;
    int i = idx & 31;
    int s = idx >> 5;
    float p = (float)pos[s];
    float inv = powf(10000.0f, -(float)i * (1.0f / 32.0f));
    float sn, c;
    sincosf(p * inv, &sn, &c);

    const float* qrow = q + (size_t)s * NH * HD;
#pragma unroll
    for (int h = 0; h < NH; h++) {
        float x1 = qrow[h * HD + i];
        float x2 = qrow[h * HD + i + 32];
        float r1 = x1 * c - x2 * sn;
        float r2 = x2 * c + x1 * sn;
        size_t o = (size_t)s * NH * HD + h * HD + i;
        __half h1 = __float2half_rn(r1);
        __half h2 = __float2half_rn(r2);
        qh[o] = h1;
        qh[o + 32] = h2;
        ql[o] = __float2half_rn(r1 - __half2float(h1));
        ql[o + 32] = __float2half_rn(r2 - __half2float(h2));
    }
    const float* krow = k + (size_t)s * NKV * HD;
#pragma unroll
    for (int h = 0; h < NKV; h++) {
        float x1 = krow[h * HD + i];
        float x2 = krow[h * HD + i + 32];
        size_t o = (size_t)s * NKV * HD + h * HD + i;
        kf[o] = __float2half_rn((x1 * c - x2 * sn) * QSCALE);
        kf[o + 32] = __float2half_rn((x2 * c + x1 * sn) * QSCALE);
    }
}

// ---------------------------------------------------------------------------
// HMMA causal flash attention, fp16 2-term S split (Qh+Ql vs single K).
// Grid (32, 15): CTA processes q-tiles {pa, 63-pa} -> uniform 65 iterations.
// Output written as single fp16 (aF) for the O-projection.
// ---------------------------------------------------------------------------
__device__ __forceinline__ void kv_async(u32 dst, const __half* Kf, const __half* Vf,
                                         int k0, int kvh, int tid) {
#pragma unroll
    for (int u = tid; u < 512; u += 128) {
        int row = u >> 3, c8 = u & 7;
        size_t g = (size_t)(k0 + row) * (NKV * HD) + kvh * HD + c8 * 8;
        u32 so = (u32)(row * FD + c8 * 8) * 2;
        cp16(dst + so, Kf + g);
        cp16(dst + FARR + so, Vf + g);
    }
}

__global__ __launch_bounds__(128) void flash_mma(
    const __half* __restrict__ Qh, const __half* __restrict__ Ql,
    const __half* __restrict__ Kf, const __half* __restrict__ Vf,
    __half* __restrict__ aF) {
    extern __shared__ char fsm[];
    const u32 base = smem_to_u32(fsm);
    const int pa = blockIdx.x, h = blockIdx.y, kvh = h / GROUPS;
    const int tid = threadIdx.x, warp = tid >> 5, lane = tid & 31;
    const int sel = lane >> 3, l7 = lane & 7;

    for (int hp = 0; hp < 2; hp++) {
        const int qt = hp ? 63 - pa : pa;
        const int q0 = qt * 64;

        // prefetch KV tile 0 into buf0 (async; overlaps Q staging below)
        kv_async(base, Kf, Vf, 0, kvh, tid);
        CP_COMMIT();

        // stage Q via buf1, extract fragments
        for (int u = tid; u < 512; u += 128) {
            int row = u >> 3, c8 = u & 7;
            size_t g = (size_t)(q0 + row) * (NH * HD) + h * HD + c8 * 8;
            u32 so = (u32)(row * FD + c8 * 8) * 2;
            *(uint4*)(fsm + FBUF + so) = *(const uint4*)(Qh + g);
            *(uint4*)(fsm + FBUF + FARR + so) = *(const uint4*)(Ql + g);
        }
        __syncthreads();
        u32 aQh[4][4], aQl[4][4];
        {
            int row = warp * 16 + (lane & 15);
            int csel = (lane >> 4) * 8;
#pragma unroll
            for (int ks = 0; ks < 4; ks++) {
                u32 off = (u32)(row * FD + ks * 16 + csel) * 2;
                ldsm4(aQh[ks], base + FBUF + off);
                ldsm4(aQl[ks], base + FBUF + FARR + off);
            }
        }
        __syncthreads();  // Q frags extracted before buf1 is overwritten (kt=1 prefetch)

        float m_i[2] = {-1e30f, -1e30f}, l_i[2] = {0.f, 0.f};
        float acc_o[8][4];
#pragma unroll
        for (int j = 0; j < 8; j++)
#pragma unroll
            for (int e = 0; e < 4; e++) acc_o[j][e] = 0.f;

        for (int kt = 0; kt <= qt; kt++) {
            if (kt < qt) {
                kv_async(base + ((kt + 1) & 1) * FBUF, Kf, Vf, (kt + 1) * 64, kvh, tid);
                CP_COMMIT();
                CP_WAIT1();
            } else {
                CP_WAIT0();
            }
            __syncthreads();
            const u32 pKf = base + (kt & 1) * FBUF;
            const u32 pVf = pKf + FARR;

            // ---- S = (Qh + Ql) K^T, single fp16 K (scaled)
            float s[8][4];
#pragma unroll
            for (int j = 0; j < 8; j++)
#pragma unroll
                for (int e = 0; e < 4; e++) s[j][e] = 0.f;

#pragma unroll
            for (int ks = 0; ks < 4; ks++) {
#pragma unroll
                for (int g2 = 0; g2 < 4; g2++) {
                    int key = 16 * g2 + ((sel >> 1) << 3) + l7;
                    int col = ks * 16 + (sel & 1) * 8;
                    u32 off = (u32)(key * FD + col) * 2;
                    u32 bf[4];
                    ldsm4(bf, pKf + off);
                    mma_f16(s[2 * g2], aQh[ks], bf);
                    mma_f16(s[2 * g2], aQl[ks], bf);
                    mma_f16(s[2 * g2 + 1], aQh[ks], bf + 2);
                    mma_f16(s[2 * g2 + 1], aQl[ks], bf + 2);
                }
            }

            // ---- causal mask (diagonal tile only)
            if (kt == qt) {
                const int c0 = (lane & 3) * 2, r0l = warp * 16 + (lane >> 2);
#pragma unroll
                for (int j = 0; j < 8; j++)
#pragma unroll
                    for (int e = 0; e < 4; e++) {
                        int key = 8 * j + c0 + (e & 1);
                        int qr = r0l + (e >> 1) * 8;
                        if (key > qr) s[j][e] = -1e30f;
                    }
            }

            // ---- online softmax (base-2), P -> fp16 fragments
            u32 ph2[8][2];
#pragma unroll
            for (int hf = 0; hf < 2; hf++) {
                float rm = -1e30f;
#pragma unroll
                for (int j = 0; j < 8; j++)
                    rm = fmaxf(rm, fmaxf(s[j][2 * hf], s[j][2 * hf + 1]));
                rm = fmaxf(rm, __shfl_xor_sync(0xffffffffu, rm, 1));
                rm = fmaxf(rm, __shfl_xor_sync(0xffffffffu, rm, 2));
                float mnew = fmaxf(m_i[hf], rm);
                float corr = ex2f(m_i[hf] - mnew);
                m_i[hf] = mnew;
                float rsum = 0.f;
#pragma unroll
                for (int j = 0; j < 8; j++) {
                    float p0 = ex2f(s[j][2 * hf] - mnew);
                    float p1 = ex2f(s[j][2 * hf + 1] - mnew);
                    ph2[j][hf] = pack_h2(p0, p1);
                    rsum += p0 + p1;
                }
                rsum += __shfl_xor_sync(0xffffffffu, rsum, 1);
                rsum += __shfl_xor_sync(0xffffffffu, rsum, 2);
                l_i[hf] = l_i[hf] * corr + rsum;
#pragma unroll
                for (int j = 0; j < 8; j++) {
                    acc_o[j][2 * hf] *= corr;
                    acc_o[j][2 * hf + 1] *= corr;
                }
            }

            // ---- O += P V (fp16 V)
#pragma unroll
            for (int g2 = 0; g2 < 4; g2++) {
                u32 pa4[4] = {ph2[2 * g2][0], ph2[2 * g2][1],
                              ph2[2 * g2 + 1][0], ph2[2 * g2 + 1][1]};
#pragma unroll
                for (int dd = 0; dd < 4; dd++) {
                    int key = 16 * g2 + ((sel & 1) << 3) + l7;
                    int col = 16 * dd + ((sel >> 1) << 3);
                    u32 off = (u32)(key * FD + col) * 2;
                    u32 bh[4];
                    ldsm4t(bh, pVf + off);
                    mma_f16(acc_o[2 * dd], pa4, bh);
                    mma_f16(acc_o[2 * dd + 1], pa4, bh + 2);
                }
            }
            __syncthreads();  // all reads of buf[kt&1] done before kt+2 prefetch
        }

        // ---- normalize + write single fp16
        const float inv0 = 1.0f / l_i[0], inv1 = 1.0f / l_i[1];
        const int r0 = q0 + warp * 16 + (lane >> 2), c0 = (lane & 3) * 2;
#pragma unroll
        for (int j = 0; j < 8; j++) {
            int col = h * HD + 8 * j + c0;
#pragma unroll
            for (int hf = 0; hf < 2; hf++) {
                float a0 = acc_o[j][2 * hf] * (hf ? inv1 : inv0);
                float a1 = acc_o[j][2 * hf + 1] * (hf ? inv1 : inv0);
                size_t o = (size_t)(r0 + hf * 8) * EMB + col;
                *(__half2*)(aF + o) =
                    __halves2half2(__float2half_rn(a0), __float2half_rn(a1));
            }
        }
    }
}

// ---------------------------------------------------------------------------
extern "C" void kernel_launch(void* const* d_in, const int* in_sizes, int n_in,
                              void* d_out, int out_size) {
    const float* hidden = (const float*)d_in[0];
    const float* Wq = (const float*)d_in[1];
    const float* Wk = (const float*)d_in[2];
    const float* Wv = (const float*)d_in[3];
    const float* Wo = (const float*)d_in[4];
    const int* pos = (const int*)d_in[6];
    float* out = (float*)d_out;

    float *q, *k;
    __half *hidF, *wH, *wL, *woH, *woL, *aF, *qh, *ql, *kf, *vh;
    cudaGetSymbolAddress((void**)&q, g_q);
    cudaGetSymbolAddress((void**)&k, g_k);
    cudaGetSymbolAddress((void**)&hidF, g_hidF);
    cudaGetSymbolAddress((void**)&wH, g_wH);
    cudaGetSymbolAddress((void**)&wL, g_wL);
    cudaGetSymbolAddress((void**)&woH, g_woH);
    cudaGetSymbolAddress((void**)&woL, g_woL);
    cudaGetSymbolAddress((void**)&aF, g_aF);
    cudaGetSymbolAddress((void**)&qh, g_qh);
    cudaGetSymbolAddress((void**)&ql, g_ql);
    cudaGetSymbolAddress((void**)&kf, g_kf);
    cudaGetSymbolAddress((void**)&vh, g_vh);

    static bool attr_set = false;
    if (!attr_set) {
        cudaFuncSetAttribute(flash_mma, cudaFuncAttributeMaxDynamicSharedMemorySize,
                             2 * FBUF);
        attr_set = true;
    }

    // fp16 conversions
    cvt_f16<<<(SEQ * EMB + 255) / 256, 256>>>(hidden, hidF, SEQ * EMB);
    cvt_split_f16<<<(EMB * KDIM + 255) / 256, 256>>>(Wq, wH, wL, EMB * KDIM);
    cvt_split_f16<<<(320 * KDIM + 255) / 256, 256>>>(Wk, wH + (size_t)960 * KDIM,
                                                     wL + (size_t)960 * KDIM, 320 * KDIM);
    cvt_split_f16<<<(320 * KDIM + 255) / 256, 256>>>(Wv, wH + (size_t)1280 * KDIM,
                                                     wL + (size_t)1280 * KDIM, 320 * KDIM);
    cvt_split_f16<<<(EMB * KDIM + 255) / 256, 256>>>(Wo, woH, woL, EMB * KDIM);

    // fused QKV projection (fp16 HMMA, cp.async pipelined); V emitted as fp16
    gemm_mma<<<dim3(NQKV / 64, SEQ / 64), 128>>>(hidF, wH, wL, 0, q, k, vh, nullptr);

    // RoPE + split (Q unscaled hi/lo; K single fp16, scale folded in)
    rope_split<<<(SEQ * 32 + 255) / 256, 256>>>(q, k, pos, qh, ql, kf);

    // flash attention (fp16 HMMA, balanced pairs, double-buffered)
    flash_mma<<<dim3(32, NH), 128, 2 * FBUF>>>(qh, ql, kf, vh, aF);

    // O projection (fp16 HMMA)
    gemm_mma<<<dim3(EMB / 64, SEQ / 64), 128>>>(aF, woH, woL, 1,
                                                nullptr, nullptr, nullptr, out);
}

// round 11
// speedup vs baseline: 6.6820x; 1.0265x over previous
#include <cuda_runtime.h>
#include <cuda_bf16.h>
#include <cuda_fp16.h>
#include <stdint.h>
#include <math.h>

#define SEQ 4096
#define EMB 960
#define NH 15
#define NKV 5
#define HD 64
#define GROUPS 3
#define KDIM 960
#define NQKV 1600
#define FD 72                 // flash smem row stride (elems)
#define FARR (64 * FD * 2)    // 9216 B per flash array
#define FBUF (2 * FARR)       // 18432 B per flash KV buffer (Kf, Vf)
#define QSCALE 0.18033688011112042f  // 0.125 * log2(e), folded into K

typedef uint32_t u32;

// ---- PTX helpers ----------------------------------------------------------
__device__ __forceinline__ uint32_t smem_to_u32(const void* p) {
    uint32_t a;
    asm("{ .reg .u64 t; cvta.to.shared.u64 t, %1; cvt.u32.u64 %0, t; }" : "=r"(a) : "l"(p));
    return a;
}
__device__ __forceinline__ void mma_f16(float* c, const u32* a, const u32* b) {
    asm volatile(
        "mma.sync.aligned.m16n8k16.row.col.f32.f16.f16.f32 "
        "{%0,%1,%2,%3}, {%4,%5,%6,%7}, {%8,%9}, {%0,%1,%2,%3};"
        : "+f"(c[0]), "+f"(c[1]), "+f"(c[2]), "+f"(c[3])
        : "r"(a[0]), "r"(a[1]), "r"(a[2]), "r"(a[3]), "r"(b[0]), "r"(b[1]));
}
__device__ __forceinline__ void ldsm4(u32* r, u32 addr) {
    asm volatile("ldmatrix.sync.aligned.m8n8.x4.shared.b16 {%0,%1,%2,%3}, [%4];"
                 : "=r"(r[0]), "=r"(r[1]), "=r"(r[2]), "=r"(r[3]) : "r"(addr));
}
__device__ __forceinline__ void ldsm4t(u32* r, u32 addr) {
    asm volatile("ldmatrix.sync.aligned.m8n8.x4.trans.shared.b16 {%0,%1,%2,%3}, [%4];"
                 : "=r"(r[0]), "=r"(r[1]), "=r"(r[2]), "=r"(r[3]) : "r"(addr));
}
__device__ __forceinline__ float ex2f(float x) {
    float y; asm("ex2.approx.f32 %0, %1;" : "=f"(y) : "f"(x)); return y;
}
__device__ __forceinline__ u32 pack_h2(float lo, float hi) {
    u32 r; asm("cvt.rn.f16x2.f32 %0, %1, %2;" : "=r"(r) : "f"(hi), "f"(lo)); return r;
}
__device__ __forceinline__ void cp16(u32 saddr, const void* g) {
    asm volatile("cp.async.cg.shared.global [%0], [%1], 16;" :: "r"(saddr), "l"(g));
}
#define CP_COMMIT() asm volatile("cp.async.commit_group;" ::: "memory")
#define CP_WAIT1() asm volatile("cp.async.wait_group 1;" ::: "memory")
#define CP_WAIT0() asm volatile("cp.async.wait_group 0;" ::: "memory")

// ---- scratch --------------------------------------------------------------
__device__ float g_q[SEQ * NH * HD];
__device__ float g_k[SEQ * NKV * HD];
__device__ __half g_hidF[SEQ * EMB];
__device__ __half g_wH[NQKV * KDIM];
__device__ __half g_wL[NQKV * KDIM];
__device__ __half g_woH[EMB * KDIM];
__device__ __half g_woL[EMB * KDIM];
__device__ __half g_aF[SEQ * EMB];
__device__ __half g_qh[SEQ * NH * HD];
__device__ __half g_ql[SEQ * NH * HD];
__device__ __half g_kf[SEQ * NKV * HD];
__device__ __half g_vh[SEQ * NKV * HD];

// ---------------------------------------------------------------------------
__global__ void cvt_f16(const float* __restrict__ src, __half* __restrict__ dst, int n) {
    int i = blockIdx.x * blockDim.x + threadIdx.x;
    if (i >= n) return;
    dst[i] = __float2half_rn(src[i]);
}

// all four weight matrices split in ONE launch
__global__ void cvt_weights(const float* __restrict__ Wq, const float* __restrict__ Wk,
                            const float* __restrict__ Wv, const float* __restrict__ Wo,
                            __half* __restrict__ wH, __half* __restrict__ wL,
                            __half* __restrict__ woH, __half* __restrict__ woL) {
    int i = blockIdx.x * blockDim.x + threadIdx.x;
    const int NQ = EMB * KDIM;           // 921600
    const int NKVW = 320 * KDIM;         // 307200
    const int TOT = NQ + 2 * NKVW + NQ;  // 2457600
    if (i >= TOT) return;
    const float* src;
    __half *dh, *dl;
    int j = i;
    if (j < NQ) {
        src = Wq; dh = wH; dl = wL;
    } else if (j < NQ + NKVW) {
        j -= NQ; src = Wk; dh = wH + NQ; dl = wL + NQ;
    } else if (j < NQ + 2 * NKVW) {
        j -= NQ + NKVW; src = Wv; dh = wH + NQ + NKVW; dl = wL + NQ + NKVW;
    } else {
        j -= NQ + 2 * NKVW; src = Wo; dh = woH; dl = woL;
    }
    float x = src[j];
    __half h = __float2half_rn(x);
    dh[j] = h;
    dl[j] = __float2half_rn(x - __half2float(h));
}

// ---------------------------------------------------------------------------
// HMMA fp16 GEMM: C[M,N] = A(fp16) @ (Bh+Bl)(fp16 split)^T, fp32 acc,
// cp.async double buffered.
// mode 0: q fp32 (col<960), k fp32 (<1280), V as fp16 (>=1280); mode 1: C fp32
// ---------------------------------------------------------------------------
#define PAD 40
#define GARR (64 * PAD * 2)   // 5120 B
#define GBUF (3 * GARR)       // 15360 B

__device__ __forceinline__ void gemm_ld(
    u32 sbase, const __half* A, const __half* Bh, const __half* Bl,
    int bm, int bn, int k0, int tid) {
#pragma unroll
    for (int it = 0; it < 2; it++) {
        int idx = tid + it * 128;
        int row = idx >> 2, c16 = idx & 3;
        size_t ga = (size_t)(bm + row) * KDIM + k0 + c16 * 8;
        size_t gb = (size_t)(bn + row) * KDIM + k0 + c16 * 8;
        u32 so = (u32)(row * PAD + c16 * 8) * 2;
        cp16(sbase + so, A + ga);
        cp16(sbase + GARR + so, Bh + gb);
        cp16(sbase + 2 * GARR + so, Bl + gb);
    }
}

__global__ __launch_bounds__(128) void gemm_mma(
    const __half* __restrict__ A, const __half* __restrict__ Bh,
    const __half* __restrict__ Bl, int mode, float* __restrict__ q,
    float* __restrict__ k, __half* __restrict__ vh, float* __restrict__ C) {
    __shared__ __half gsm[2 * 3 * 64 * PAD];
    const u32 base = smem_to_u32(gsm);
    const int tid = threadIdx.x;
    const int warp = tid >> 5, lane = tid & 31;
    const int wm = warp & 1, wn = warp >> 1;
    const int bm = blockIdx.y * 64, bn = blockIdx.x * 64;

    float acc[2][4][4];
#pragma unroll
    for (int am = 0; am < 2; am++)
#pragma unroll
        for (int nj = 0; nj < 4; nj++)
#pragma unroll
            for (int e = 0; e < 4; e++) acc[am][nj][e] = 0.f;

    const int a_r = lane & 15, a_h = lane >> 4;
    const int b_r = lane & 7, b_q = lane >> 3;
    const int NCH = KDIM / 32;  // 30

    gemm_ld(base, A, Bh, Bl, bm, bn, 0, tid);
    CP_COMMIT();

    for (int ch = 0; ch < NCH; ch++) {
        if (ch < NCH - 1) {
            gemm_ld(base + ((ch + 1) & 1) * GBUF, A, Bh, Bl, bm, bn, (ch + 1) * 32, tid);
            CP_COMMIT();
            CP_WAIT1();
        } else {
            CP_WAIT0();
        }
        __syncthreads();
        const u32 pA = base + (ch & 1) * GBUF;
        const u32 pBh = pA + GARR, pBl = pA + 2 * GARR;

#pragma unroll
        for (int kg = 0; kg < 2; kg++) {
            u32 aF[2][4], bH[2][4], bL[2][4];
#pragma unroll
            for (int am = 0; am < 2; am++) {
                u32 off = (u32)((wm * 32 + am * 16 + a_r) * PAD + kg * 16 + a_h * 8) * 2;
                ldsm4(aF[am], pA + off);
            }
#pragma unroll
            for (int np = 0; np < 2; np++) {
                u32 off = (u32)((wn * 32 + np * 16 + (b_q >> 1) * 8 + b_r) * PAD +
                                kg * 16 + (b_q & 1) * 8) * 2;
                ldsm4(bH[np], pBh + off);
                ldsm4(bL[np], pBl + off);
            }
#pragma unroll
            for (int am = 0; am < 2; am++)
#pragma unroll
                for (int nj = 0; nj < 4; nj++) {
                    const u32* bh = &bH[nj >> 1][(nj & 1) * 2];
                    const u32* bl = &bL[nj >> 1][(nj & 1) * 2];
                    mma_f16(acc[am][nj], aF[am], bh);
                    mma_f16(acc[am][nj], aF[am], bl);
                }
        }
        __syncthreads();
    }

    const int r0 = lane >> 2, cpair = (lane & 3) * 2;
#pragma unroll
    for (int am = 0; am < 2; am++)
#pragma unroll
        for (int half = 0; half < 2; half++) {
            int row = bm + wm * 32 + am * 16 + half * 8 + r0;
#pragma unroll
            for (int nj = 0; nj < 4; nj++) {
                int col = bn + wn * 32 + nj * 8 + cpair;
                float2 val = {acc[am][nj][half * 2], acc[am][nj][half * 2 + 1]};
                if (mode == 0) {
                    if (col < 960) {
                        *(float2*)(q + (size_t)row * 960 + col) = val;
                    } else if (col < 1280) {
                        *(float2*)(k + (size_t)row * 320 + (col - 960)) = val;
                    } else {
                        size_t o = (size_t)row * 320 + (col - 1280);
                        *(__half2*)(vh + o) =
                            __halves2half2(__float2half_rn(val.x), __float2half_rn(val.y));
                    }
                } else {
                    *(float2*)(C + (size_t)row * 960 + col) = val;
                }
            }
        }
}

// ---------------------------------------------------------------------------
// RoPE + split: q -> qh/ql (fp16 hi/lo, UNscaled), k -> kf (fp16, QSCALE folded)
// ---------------------------------------------------------------------------
__global__ void rope_split(const float* __restrict__ q, const float* __restrict__ k,
                           const int* __restrict__ pos,
                           __half* __restrict__ qh, __half* __restrict__ ql,
                           __half* __restrict__ kf) {
    int idx = blockIdx.x * blockDim.x + threadIdx.x;
    if (idx >= SEQ * 32) return;
    int i = idx & 31;
    int s = idx >> 5;
    float p = (float)pos[s];
    float inv = powf(10000.0f, -(float)i * (1.0f / 32.0f));
    float sn, c;
    sincosf(p * inv, &sn, &c);

    const float* qrow = q + (size_t)s * NH * HD;
#pragma unroll
    for (int h = 0; h < NH; h++) {
        float x1 = qrow[h * HD + i];
        float x2 = qrow[h * HD + i + 32];
        float r1 = x1 * c - x2 * sn;
        float r2 = x2 * c + x1 * sn;
        size_t o = (size_t)s * NH * HD + h * HD + i;
        __half h1 = __float2half_rn(r1);
        __half h2 = __float2half_rn(r2);
        qh[o] = h1;
        qh[o + 32] = h2;
        ql[o] = __float2half_rn(r1 - __half2float(h1));
        ql[o + 32] = __float2half_rn(r2 - __half2float(h2));
    }
    const float* krow = k + (size_t)s * NKV * HD;
#pragma unroll
    for (int h = 0; h < NKV; h++) {
        float x1 = krow[h * HD + i];
        float x2 = krow[h * HD + i + 32];
        size_t o = (size_t)s * NKV * HD + h * HD + i;
        kf[o] = __float2half_rn((x1 * c - x2 * sn) * QSCALE);
        kf[o + 32] = __float2half_rn((x2 * c + x1 * sn) * QSCALE);
    }
}

// ---------------------------------------------------------------------------
// HMMA causal flash attention, fp16 2-term S split (Qh+Ql vs single K).
// Grid (64, 15): ONE q-tile per CTA, qt = 63 - blockIdx.x (largest first).
// ~5 CTAs/SM resident -> ~5 warps/SMSP for stall hiding; ~6.5 fine waves
// smooth the causal imbalance. Output single fp16 (aF).
// ---------------------------------------------------------------------------
__device__ __forceinline__ void kv_async(u32 dst, const __half* Kf, const __half* Vf,
                                         int k0, int kvh, int tid) {
#pragma unroll
    for (int u = tid; u < 512; u += 128) {
        int row = u >> 3, c8 = u & 7;
        size_t g = (size_t)(k0 + row) * (NKV * HD) + kvh * HD + c8 * 8;
        u32 so = (u32)(row * FD + c8 * 8) * 2;
        cp16(dst + so, Kf + g);
        cp16(dst + FARR + so, Vf + g);
    }
}

__global__ __launch_bounds__(128) void flash_mma(
    const __half* __restrict__ Qh, const __half* __restrict__ Ql,
    const __half* __restrict__ Kf, const __half* __restrict__ Vf,
    __half* __restrict__ aF) {
    extern __shared__ char fsm[];
    const u32 base = smem_to_u32(fsm);
    const int qt = 63 - (int)blockIdx.x, h = blockIdx.y, kvh = h / GROUPS;
    const int q0 = qt * 64;
    const int tid = threadIdx.x, warp = tid >> 5, lane = tid & 31;
    const int sel = lane >> 3, l7 = lane & 7;

    // prefetch KV tile 0 into buf0 (async; overlaps Q staging below)
    kv_async(base, Kf, Vf, 0, kvh, tid);
    CP_COMMIT();

    // stage Q via buf1, extract fragments
    for (int u = tid; u < 512; u += 128) {
        int row = u >> 3, c8 = u & 7;
        size_t g = (size_t)(q0 + row) * (NH * HD) + h * HD + c8 * 8;
        u32 so = (u32)(row * FD + c8 * 8) * 2;
        *(uint4*)(fsm + FBUF + so) = *(const uint4*)(Qh + g);
        *(uint4*)(fsm + FBUF + FARR + so) = *(const uint4*)(Ql + g);
    }
    __syncthreads();
    u32 aQh[4][4], aQl[4][4];
    {
        int row = warp * 16 + (lane & 15);
        int csel = (lane >> 4) * 8;
#pragma unroll
        for (int ks = 0; ks < 4; ks++) {
            u32 off = (u32)(row * FD + ks * 16 + csel) * 2;
            ldsm4(aQh[ks], base + FBUF + off);
            ldsm4(aQl[ks], base + FBUF + FARR + off);
        }
    }
    __syncthreads();  // Q frags extracted before buf1 is overwritten (kt=1 prefetch)

    float m_i[2] = {-1e30f, -1e30f}, l_i[2] = {0.f, 0.f};
    float acc_o[8][4];
#pragma unroll
    for (int j = 0; j < 8; j++)
#pragma unroll
        for (int e = 0; e < 4; e++) acc_o[j][e] = 0.f;

    for (int kt = 0; kt <= qt; kt++) {
        if (kt < qt) {
            kv_async(base + ((kt + 1) & 1) * FBUF, Kf, Vf, (kt + 1) * 64, kvh, tid);
            CP_COMMIT();
            CP_WAIT1();
        } else {
            CP_WAIT0();
        }
        __syncthreads();
        const u32 pKf = base + (kt & 1) * FBUF;
        const u32 pVf = pKf + FARR;

        // ---- S = (Qh + Ql) K^T, single fp16 K (scaled)
        float s[8][4];
#pragma unroll
        for (int j = 0; j < 8; j++)
#pragma unroll
            for (int e = 0; e < 4; e++) s[j][e] = 0.f;

#pragma unroll
        for (int ks = 0; ks < 4; ks++) {
#pragma unroll
            for (int g2 = 0; g2 < 4; g2++) {
                int key = 16 * g2 + ((sel >> 1) << 3) + l7;
                int col = ks * 16 + (sel & 1) * 8;
                u32 off = (u32)(key * FD + col) * 2;
                u32 bf[4];
                ldsm4(bf, pKf + off);
                mma_f16(s[2 * g2], aQh[ks], bf);
                mma_f16(s[2 * g2], aQl[ks], bf);
                mma_f16(s[2 * g2 + 1], aQh[ks], bf + 2);
                mma_f16(s[2 * g2 + 1], aQl[ks], bf + 2);
            }
        }

        // ---- causal mask (diagonal tile only)
        if (kt == qt) {
            const int c0 = (lane & 3) * 2, r0l = warp * 16 + (lane >> 2);
#pragma unroll
            for (int j = 0; j < 8; j++)
#pragma unroll
                for (int e = 0; e < 4; e++) {
                    int key = 8 * j + c0 + (e & 1);
                    int qr = r0l + (e >> 1) * 8;
                    if (key > qr) s[j][e] = -1e30f;
                }
        }

        // ---- online softmax (base-2), P -> fp16 fragments
        u32 ph2[8][2];
#pragma unroll
        for (int hf = 0; hf < 2; hf++) {
            float rm = -1e30f;
#pragma unroll
            for (int j = 0; j < 8; j++)
                rm = fmaxf(rm, fmaxf(s[j][2 * hf], s[j][2 * hf + 1]));
            rm = fmaxf(rm, __shfl_xor_sync(0xffffffffu, rm, 1));
            rm = fmaxf(rm, __shfl_xor_sync(0xffffffffu, rm, 2));
            float mnew = fmaxf(m_i[hf], rm);
            float corr = ex2f(m_i[hf] - mnew);
            m_i[hf] = mnew;
            float rsum = 0.f;
#pragma unroll
            for (int j = 0; j < 8; j++) {
                float p0 = ex2f(s[j][2 * hf] - mnew);
                float p1 = ex2f(s[j][2 * hf + 1] - mnew);
                ph2[j][hf] = pack_h2(p0, p1);
                rsum += p0 + p1;
            }
            rsum += __shfl_xor_sync(0xffffffffu, rsum, 1);
            rsum += __shfl_xor_sync(0xffffffffu, rsum, 2);
            l_i[hf] = l_i[hf] * corr + rsum;
#pragma unroll
            for (int j = 0; j < 8; j++) {
                acc_o[j][2 * hf] *= corr;
                acc_o[j][2 * hf + 1] *= corr;
            }
        }

        // ---- O += P V (fp16 V)
#pragma unroll
        for (int g2 = 0; g2 < 4; g2++) {
            u32 pa4[4] = {ph2[2 * g2][0], ph2[2 * g2][1],
                          ph2[2 * g2 + 1][0], ph2[2 * g2 + 1][1]};
#pragma unroll
            for (int dd = 0; dd < 4; dd++) {
                int key = 16 * g2 + ((sel & 1) << 3) + l7;
                int col = 16 * dd + ((sel >> 1) << 3);
                u32 off = (u32)(key * FD + col) * 2;
                u32 bh[4];
                ldsm4t(bh, pVf + off);
                mma_f16(acc_o[2 * dd], pa4, bh);
                mma_f16(acc_o[2 * dd + 1], pa4, bh + 2);
            }
        }
        __syncthreads();  // all reads of buf[kt&1] done before kt+2 prefetch
    }

    // ---- normalize + write single fp16
    const float inv0 = 1.0f / l_i[0], inv1 = 1.0f / l_i[1];
    const int r0 = q0 + warp * 16 + (lane >> 2), c0 = (lane & 3) * 2;
#pragma unroll
    for (int j = 0; j < 8; j++) {
        int col = h * HD + 8 * j + c0;
#pragma unroll
        for (int hf = 0; hf < 2; hf++) {
            float a0 = acc_o[j][2 * hf] * (hf ? inv1 : inv0);
            float a1 = acc_o[j][2 * hf + 1] * (hf ? inv1 : inv0);
            size_t o = (size_t)(r0 + hf * 8) * EMB + col;
            *(__half2*)(aF + o) =
                __halves2half2(__float2half_rn(a0), __float2half_rn(a1));
        }
    }
}

// ---------------------------------------------------------------------------
extern "C" void kernel_launch(void* const* d_in, const int* in_sizes, int n_in,
                              void* d_out, int out_size) {
    const float* hidden = (const float*)d_in[0];
    const float* Wq = (const float*)d_in[1];
    const float* Wk = (const float*)d_in[2];
    const float* Wv = (const float*)d_in[3];
    const float* Wo = (const float*)d_in[4];
    const int* pos = (const int*)d_in[6];
    float* out = (float*)d_out;

    float *q, *k;
    __half *hidF, *wH, *wL, *woH, *woL, *aF, *qh, *ql, *kf, *vh;
    cudaGetSymbolAddress((void**)&q, g_q);
    cudaGetSymbolAddress((void**)&k, g_k);
    cudaGetSymbolAddress((void**)&hidF, g_hidF);
    cudaGetSymbolAddress((void**)&wH, g_wH);
    cudaGetSymbolAddress((void**)&wL, g_wL);
    cudaGetSymbolAddress((void**)&woH, g_woH);
    cudaGetSymbolAddress((void**)&woL, g_woL);
    cudaGetSymbolAddress((void**)&aF, g_aF);
    cudaGetSymbolAddress((void**)&qh, g_qh);
    cudaGetSymbolAddress((void**)&ql, g_ql);
    cudaGetSymbolAddress((void**)&kf, g_kf);
    cudaGetSymbolAddress((void**)&vh, g_vh);

    static bool attr_set = false;
    if (!attr_set) {
        cudaFuncSetAttribute(flash_mma, cudaFuncAttributeMaxDynamicSharedMemorySize,
                             2 * FBUF);
        attr_set = true;
    }

    // fp16 conversions (hidden + ALL weights in 2 launches)
    cvt_f16<<<(SEQ * EMB + 255) / 256, 256>>>(hidden, hidF, SEQ * EMB);
    cvt_weights<<<(2457600 + 255) / 256, 256>>>(Wq, Wk, Wv, Wo, wH, wL, woH, woL);

    // fused QKV projection (fp16 HMMA, cp.async pipelined); V emitted as fp16
    gemm_mma<<<dim3(NQKV / 64, SEQ / 64), 128>>>(hidF, wH, wL, 0, q, k, vh, nullptr);

    // RoPE + split (Q unscaled hi/lo; K single fp16, scale folded in)
    rope_split<<<(SEQ * 32 + 255) / 256, 256>>>(q, k, pos, qh, ql, kf);

    // flash attention (fp16 HMMA, one q-tile per CTA, largest first)
    flash_mma<<<dim3(64, NH), 128, 2 * FBUF>>>(qh, ql, kf, vh, aF);

    // O projection (fp16 HMMA)
    gemm_mma<<<dim3(EMB / 64, SEQ / 64), 128>>>(aF, woH, woL, 1,
                                                nullptr, nullptr, nullptr, out);
}

// round 12
// speedup vs baseline: 7.4251x; 1.1112x over previous
#include <cuda_runtime.h>
#include <cuda_bf16.h>
#include <cuda_fp16.h>
#include <stdint.h>
#include <math.h>

#define SEQ 4096
#define EMB 960
#define NH 15
#define NKV 5
#define HD 64
#define GROUPS 3
#define KDIM 960
#define NQKV 1600
#define FD 72                 // flash smem row stride (elems)
#define FARR (64 * FD * 2)    // 9216 B per flash array
#define FBUF (2 * FARR)       // 18432 B per flash KV buffer (Kf, Vf)
#define QSCALE 0.18033688011112042f  // 0.125 * log2(e), folded into K

typedef uint32_t u32;

// ---- PTX helpers ----------------------------------------------------------
__device__ __forceinline__ uint32_t smem_to_u32(const void* p) {
    uint32_t a;
    asm("{ .reg .u64 t; cvta.to.shared.u64 t, %1; cvt.u32.u64 %0, t; }" : "=r"(a) : "l"(p));
    return a;
}
__device__ __forceinline__ void mma_f16(float* c, const u32* a, const u32* b) {
    asm volatile(
        "mma.sync.aligned.m16n8k16.row.col.f32.f16.f16.f32 "
        "{%0,%1,%2,%3}, {%4,%5,%6,%7}, {%8,%9}, {%0,%1,%2,%3};"
        : "+f"(c[0]), "+f"(c[1]), "+f"(c[2]), "+f"(c[3])
        : "r"(a[0]), "r"(a[1]), "r"(a[2]), "r"(a[3]), "r"(b[0]), "r"(b[1]));
}
__device__ __forceinline__ void ldsm4(u32* r, u32 addr) {
    asm volatile("ldmatrix.sync.aligned.m8n8.x4.shared.b16 {%0,%1,%2,%3}, [%4];"
                 : "=r"(r[0]), "=r"(r[1]), "=r"(r[2]), "=r"(r[3]) : "r"(addr));
}
__device__ __forceinline__ void ldsm4t(u32* r, u32 addr) {
    asm volatile("ldmatrix.sync.aligned.m8n8.x4.trans.shared.b16 {%0,%1,%2,%3}, [%4];"
                 : "=r"(r[0]), "=r"(r[1]), "=r"(r[2]), "=r"(r[3]) : "r"(addr));
}
__device__ __forceinline__ float ex2f(float x) {
    float y; asm("ex2.approx.f32 %0, %1;" : "=f"(y) : "f"(x)); return y;
}
__device__ __forceinline__ u32 pack_h2(float lo, float hi) {
    u32 r; asm("cvt.rn.f16x2.f32 %0, %1, %2;" : "=r"(r) : "f"(hi), "f"(lo)); return r;
}
__device__ __forceinline__ void cp16(u32 saddr, const void* g) {
    asm volatile("cp.async.cg.shared.global [%0], [%1], 16;" :: "r"(saddr), "l"(g));
}
#define CP_COMMIT() asm volatile("cp.async.commit_group;" ::: "memory")
#define CP_WAIT1() asm volatile("cp.async.wait_group 1;" ::: "memory")
#define CP_WAIT0() asm volatile("cp.async.wait_group 0;" ::: "memory")

// ---- scratch --------------------------------------------------------------
__device__ float g_q[SEQ * NH * HD];
__device__ float g_k[SEQ * NKV * HD];
__device__ __half g_hidF[SEQ * EMB];
__device__ __half g_wH[NQKV * KDIM];
__device__ __half g_wL[NQKV * KDIM];
__device__ __half g_woH[EMB * KDIM];
__device__ __half g_woL[EMB * KDIM];
__device__ __half g_aF[SEQ * EMB];
__device__ __half g_qf[SEQ * NH * HD];
__device__ __half g_kf[SEQ * NKV * HD];
__device__ __half g_vh[SEQ * NKV * HD];

// ---------------------------------------------------------------------------
__global__ void cvt_f16(const float* __restrict__ src, __half* __restrict__ dst, int n) {
    int i = blockIdx.x * blockDim.x + threadIdx.x;
    if (i >= n) return;
    dst[i] = __float2half_rn(src[i]);
}

// all four weight matrices split in ONE launch
__global__ void cvt_weights(const float* __restrict__ Wq, const float* __restrict__ Wk,
                            const float* __restrict__ Wv, const float* __restrict__ Wo,
                            __half* __restrict__ wH, __half* __restrict__ wL,
                            __half* __restrict__ woH, __half* __restrict__ woL) {
    int i = blockIdx.x * blockDim.x + threadIdx.x;
    const int NQ = EMB * KDIM;           // 921600
    const int NKVW = 320 * KDIM;         // 307200
    const int TOT = NQ + 2 * NKVW + NQ;  // 2457600
    if (i >= TOT) return;
    const float* src;
    __half *dh, *dl;
    int j = i;
    if (j < NQ) {
        src = Wq; dh = wH; dl = wL;
    } else if (j < NQ + NKVW) {
        j -= NQ; src = Wk; dh = wH + NQ; dl = wL + NQ;
    } else if (j < NQ + 2 * NKVW) {
        j -= NQ + NKVW; src = Wv; dh = wH + NQ + NKVW; dl = wL + NQ + NKVW;
    } else {
        j -= NQ + 2 * NKVW; src = Wo; dh = woH; dl = woL;
    }
    float x = src[j];
    __half h = __float2half_rn(x);
    dh[j] = h;
    dl[j] = __float2half_rn(x - __half2float(h));
}

// ---------------------------------------------------------------------------
// HMMA fp16 GEMM: C[M,N] = A(fp16) @ (Bh+Bl)(fp16 split)^T, fp32 acc,
// cp.async double buffered.
// mode 0: q fp32 (col<960), k fp32 (<1280), V as fp16 (>=1280); mode 1: C fp32
// ---------------------------------------------------------------------------
#define PAD 40
#define GARR (64 * PAD * 2)   // 5120 B
#define GBUF (3 * GARR)       // 15360 B

__device__ __forceinline__ void gemm_ld(
    u32 sbase, const __half* A, const __half* Bh, const __half* Bl,
    int bm, int bn, int k0, int tid) {
#pragma unroll
    for (int it = 0; it < 2; it++) {
        int idx = tid + it * 128;
        int row = idx >> 2, c16 = idx & 3;
        size_t ga = (size_t)(bm + row) * KDIM + k0 + c16 * 8;
        size_t gb = (size_t)(bn + row) * KDIM + k0 + c16 * 8;
        u32 so = (u32)(row * PAD + c16 * 8) * 2;
        cp16(sbase + so, A + ga);
        cp16(sbase + GARR + so, Bh + gb);
        cp16(sbase + 2 * GARR + so, Bl + gb);
    }
}

__global__ __launch_bounds__(128) void gemm_mma(
    const __half* __restrict__ A, const __half* __restrict__ Bh,
    const __half* __restrict__ Bl, int mode, float* __restrict__ q,
    float* __restrict__ k, __half* __restrict__ vh, float* __restrict__ C) {
    __shared__ __half gsm[2 * 3 * 64 * PAD];
    const u32 base = smem_to_u32(gsm);
    const int tid = threadIdx.x;
    const int warp = tid >> 5, lane = tid & 31;
    const int wm = warp & 1, wn = warp >> 1;
    const int bm = blockIdx.y * 64, bn = blockIdx.x * 64;

    float acc[2][4][4];
#pragma unroll
    for (int am = 0; am < 2; am++)
#pragma unroll
        for (int nj = 0; nj < 4; nj++)
#pragma unroll
            for (int e = 0; e < 4; e++) acc[am][nj][e] = 0.f;

    const int a_r = lane & 15, a_h = lane >> 4;
    const int b_r = lane & 7, b_q = lane >> 3;
    const int NCH = KDIM / 32;  // 30

    gemm_ld(base, A, Bh, Bl, bm, bn, 0, tid);
    CP_COMMIT();

    for (int ch = 0; ch < NCH; ch++) {
        if (ch < NCH - 1) {
            gemm_ld(base + ((ch + 1) & 1) * GBUF, A, Bh, Bl, bm, bn, (ch + 1) * 32, tid);
            CP_COMMIT();
            CP_WAIT1();
        } else {
            CP_WAIT0();
        }
        __syncthreads();
        const u32 pA = base + (ch & 1) * GBUF;
        const u32 pBh = pA + GARR, pBl = pA + 2 * GARR;

#pragma unroll
        for (int kg = 0; kg < 2; kg++) {
            u32 aF[2][4], bH[2][4], bL[2][4];
#pragma unroll
            for (int am = 0; am < 2; am++) {
                u32 off = (u32)((wm * 32 + am * 16 + a_r) * PAD + kg * 16 + a_h * 8) * 2;
                ldsm4(aF[am], pA + off);
            }
#pragma unroll
            for (int np = 0; np < 2; np++) {
                u32 off = (u32)((wn * 32 + np * 16 + (b_q >> 1) * 8 + b_r) * PAD +
                                kg * 16 + (b_q & 1) * 8) * 2;
                ldsm4(bH[np], pBh + off);
                ldsm4(bL[np], pBl + off);
            }
#pragma unroll
            for (int am = 0; am < 2; am++)
#pragma unroll
                for (int nj = 0; nj < 4; nj++) {
                    const u32* bh = &bH[nj >> 1][(nj & 1) * 2];
                    const u32* bl = &bL[nj >> 1][(nj & 1) * 2];
                    mma_f16(acc[am][nj], aF[am], bh);
                    mma_f16(acc[am][nj], aF[am], bl);
                }
        }
        __syncthreads();
    }

    const int r0 = lane >> 2, cpair = (lane & 3) * 2;
#pragma unroll
    for (int am = 0; am < 2; am++)
#pragma unroll
        for (int half = 0; half < 2; half++) {
            int row = bm + wm * 32 + am * 16 + half * 8 + r0;
#pragma unroll
            for (int nj = 0; nj < 4; nj++) {
                int col = bn + wn * 32 + nj * 8 + cpair;
                float2 val = {acc[am][nj][half * 2], acc[am][nj][half * 2 + 1]};
                if (mode == 0) {
                    if (col < 960) {
                        *(float2*)(q + (size_t)row * 960 + col) = val;
                    } else if (col < 1280) {
                        *(float2*)(k + (size_t)row * 320 + (col - 960)) = val;
                    } else {
                        size_t o = (size_t)row * 320 + (col - 1280);
                        *(__half2*)(vh + o) =
                            __halves2half2(__float2half_rn(val.x), __float2half_rn(val.y));
                    }
                } else {
                    *(float2*)(C + (size_t)row * 960 + col) = val;
                }
            }
        }
}

// ---------------------------------------------------------------------------
// RoPE + convert: q -> qf (single fp16), k -> kf (fp16, QSCALE folded)
// ---------------------------------------------------------------------------
__global__ void rope_split(const float* __restrict__ q, const float* __restrict__ k,
                           const int* __restrict__ pos,
                           __half* __restrict__ qf, __half* __restrict__ kf) {
    int idx = blockIdx.x * blockDim.x + threadIdx.x;
    if (idx >= SEQ * 32) return;
    int i = idx & 31;
    int s = idx >> 5;
    float p = (float)pos[s];
    float inv = powf(10000.0f, -(float)i * (1.0f / 32.0f));
    float sn, c;
    sincosf(p * inv, &sn, &c);

    const float* qrow = q + (size_t)s * NH * HD;
#pragma unroll
    for (int h = 0; h < NH; h++) {
        float x1 = qrow[h * HD + i];
        float x2 = qrow[h * HD + i + 32];
        size_t o = (size_t)s * NH * HD + h * HD + i;
        qf[o] = __float2half_rn(x1 * c - x2 * sn);
        qf[o + 32] = __float2half_rn(x2 * c + x1 * sn);
    }
    const float* krow = k + (size_t)s * NKV * HD;
#pragma unroll
    for (int h = 0; h < NKV; h++) {
        float x1 = krow[h * HD + i];
        float x2 = krow[h * HD + i + 32];
        size_t o = (size_t)s * NKV * HD + h * HD + i;
        kf[o] = __float2half_rn((x1 * c - x2 * sn) * QSCALE);
        kf[o + 32] = __float2half_rn((x2 * c + x1 * sn) * QSCALE);
    }
}

// ---------------------------------------------------------------------------
// HMMA causal flash attention, single-fp16 Q and K (scale folded into K).
// Grid (64, 15): ONE q-tile per CTA, qt = 63 - blockIdx.x (largest first).
// Output single fp16 (aF).
// ---------------------------------------------------------------------------
__device__ __forceinline__ void kv_async(u32 dst, const __half* Kf, const __half* Vf,
                                         int k0, int kvh, int tid) {
#pragma unroll
    for (int u = tid; u < 512; u += 128) {
        int row = u >> 3, c8 = u & 7;
        size_t g = (size_t)(k0 + row) * (NKV * HD) + kvh * HD + c8 * 8;
        u32 so = (u32)(row * FD + c8 * 8) * 2;
        cp16(dst + so, Kf + g);
        cp16(dst + FARR + so, Vf + g);
    }
}

__global__ __launch_bounds__(128) void flash_mma(
    const __half* __restrict__ Qf, const __half* __restrict__ Kf,
    const __half* __restrict__ Vf, __half* __restrict__ aF) {
    extern __shared__ char fsm[];
    const u32 base = smem_to_u32(fsm);
    const int qt = 63 - (int)blockIdx.x, h = blockIdx.y, kvh = h / GROUPS;
    const int q0 = qt * 64;
    const int tid = threadIdx.x, warp = tid >> 5, lane = tid & 31;
    const int sel = lane >> 3, l7 = lane & 7;

    // prefetch KV tile 0 into buf0 (async; overlaps Q staging below)
    kv_async(base, Kf, Vf, 0, kvh, tid);
    CP_COMMIT();

    // stage Q via buf1, extract fragments
    for (int u = tid; u < 512; u += 128) {
        int row = u >> 3, c8 = u & 7;
        size_t g = (size_t)(q0 + row) * (NH * HD) + h * HD + c8 * 8;
        u32 so = (u32)(row * FD + c8 * 8) * 2;
        *(uint4*)(fsm + FBUF + so) = *(const uint4*)(Qf + g);
    }
    __syncthreads();
    u32 aQ[4][4];
    {
        int row = warp * 16 + (lane & 15);
        int csel = (lane >> 4) * 8;
#pragma unroll
        for (int ks = 0; ks < 4; ks++) {
            u32 off = (u32)(row * FD + ks * 16 + csel) * 2;
            ldsm4(aQ[ks], base + FBUF + off);
        }
    }
    __syncthreads();  // Q frags extracted before buf1 is overwritten (kt=1 prefetch)

    float m_i[2] = {-1e30f, -1e30f}, l_i[2] = {0.f, 0.f};
    float acc_o[8][4];
#pragma unroll
    for (int j = 0; j < 8; j++)
#pragma unroll
        for (int e = 0; e < 4; e++) acc_o[j][e] = 0.f;

    for (int kt = 0; kt <= qt; kt++) {
        if (kt < qt) {
            kv_async(base + ((kt + 1) & 1) * FBUF, Kf, Vf, (kt + 1) * 64, kvh, tid);
            CP_COMMIT();
            CP_WAIT1();
        } else {
            CP_WAIT0();
        }
        __syncthreads();
        const u32 pKf = base + (kt & 1) * FBUF;
        const u32 pVf = pKf + FARR;

        // ---- S = Q K^T (single fp16 each; scale pre-folded into K)
        float s[8][4];
#pragma unroll
        for (int j = 0; j < 8; j++)
#pragma unroll
            for (int e = 0; e < 4; e++) s[j][e] = 0.f;

#pragma unroll
        for (int ks = 0; ks < 4; ks++) {
#pragma unroll
            for (int g2 = 0; g2 < 4; g2++) {
                int key = 16 * g2 + ((sel >> 1) << 3) + l7;
                int col = ks * 16 + (sel & 1) * 8;
                u32 off = (u32)(key * FD + col) * 2;
                u32 bf[4];
                ldsm4(bf, pKf + off);
                mma_f16(s[2 * g2], aQ[ks], bf);
                mma_f16(s[2 * g2 + 1], aQ[ks], bf + 2);
            }
        }

        // ---- causal mask (diagonal tile only)
        if (kt == qt) {
            const int c0 = (lane & 3) * 2, r0l = warp * 16 + (lane >> 2);
#pragma unroll
            for (int j = 0; j < 8; j++)
#pragma unroll
                for (int e = 0; e < 4; e++) {
                    int key = 8 * j + c0 + (e & 1);
                    int qr = r0l + (e >> 1) * 8;
                    if (key > qr) s[j][e] = -1e30f;
                }
        }

        // ---- online softmax (base-2), P -> fp16 fragments
        u32 ph2[8][2];
#pragma unroll
        for (int hf = 0; hf < 2; hf++) {
            float rm = -1e30f;
#pragma unroll
            for (int j = 0; j < 8; j++)
                rm = fmaxf(rm, fmaxf(s[j][2 * hf], s[j][2 * hf + 1]));
            rm = fmaxf(rm, __shfl_xor_sync(0xffffffffu, rm, 1));
            rm = fmaxf(rm, __shfl_xor_sync(0xffffffffu, rm, 2));
            float mnew = fmaxf(m_i[hf], rm);
            float corr = ex2f(m_i[hf] - mnew);
            m_i[hf] = mnew;
            float rsum = 0.f;
#pragma unroll
            for (int j = 0; j < 8; j++) {
                float p0 = ex2f(s[j][2 * hf] - mnew);
                float p1 = ex2f(s[j][2 * hf + 1] - mnew);
                ph2[j][hf] = pack_h2(p0, p1);
                rsum += p0 + p1;
            }
            rsum += __shfl_xor_sync(0xffffffffu, rsum, 1);
            rsum += __shfl_xor_sync(0xffffffffu, rsum, 2);
            l_i[hf] = l_i[hf] * corr + rsum;
#pragma unroll
            for (int j = 0; j < 8; j++) {
                acc_o[j][2 * hf] *= corr;
                acc_o[j][2 * hf + 1] *= corr;
            }
        }

        // ---- O += P V (fp16 V)
#pragma unroll
        for (int g2 = 0; g2 < 4; g2++) {
            u32 pa4[4] = {ph2[2 * g2][0], ph2[2 * g2][1],
                          ph2[2 * g2 + 1][0], ph2[2 * g2 + 1][1]};
#pragma unroll
            for (int dd = 0; dd < 4; dd++) {
                int key = 16 * g2 + ((sel & 1) << 3) + l7;
                int col = 16 * dd + ((sel >> 1) << 3);
                u32 off = (u32)(key * FD + col) * 2;
                u32 bh[4];
                ldsm4t(bh, pVf + off);
                mma_f16(acc_o[2 * dd], pa4, bh);
                mma_f16(acc_o[2 * dd + 1], pa4, bh + 2);
            }
        }
        __syncthreads();  // all reads of buf[kt&1] done before kt+2 prefetch
    }

    // ---- normalize + write single fp16
    const float inv0 = 1.0f / l_i[0], inv1 = 1.0f / l_i[1];
    const int r0 = q0 + warp * 16 + (lane >> 2), c0 = (lane & 3) * 2;
#pragma unroll
    for (int j = 0; j < 8; j++) {
        int col = h * HD + 8 * j + c0;
#pragma unroll
        for (int hf = 0; hf < 2; hf++) {
            float a0 = acc_o[j][2 * hf] * (hf ? inv1 : inv0);
            float a1 = acc_o[j][2 * hf + 1] * (hf ? inv1 : inv0);
            size_t o = (size_t)(r0 + hf * 8) * EMB + col;
            *(__half2*)(aF + o) =
                __halves2half2(__float2half_rn(a0), __float2half_rn(a1));
        }
    }
}

// ---------------------------------------------------------------------------
extern "C" void kernel_launch(void* const* d_in, const int* in_sizes, int n_in,
                              void* d_out, int out_size) {
    const float* hidden = (const float*)d_in[0];
    const float* Wq = (const float*)d_in[1];
    const float* Wk = (const float*)d_in[2];
    const float* Wv = (const float*)d_in[3];
    const float* Wo = (const float*)d_in[4];
    const int* pos = (const int*)d_in[6];
    float* out = (float*)d_out;

    float *q, *k;
    __half *hidF, *wH, *wL, *woH, *woL, *aF, *qf, *kf, *vh;
    cudaGetSymbolAddress((void**)&q, g_q);
    cudaGetSymbolAddress((void**)&k, g_k);
    cudaGetSymbolAddress((void**)&hidF, g_hidF);
    cudaGetSymbolAddress((void**)&wH, g_wH);
    cudaGetSymbolAddress((void**)&wL, g_wL);
    cudaGetSymbolAddress((void**)&woH, g_woH);
    cudaGetSymbolAddress((void**)&woL, g_woL);
    cudaGetSymbolAddress((void**)&aF, g_aF);
    cudaGetSymbolAddress((void**)&qf, g_qf);
    cudaGetSymbolAddress((void**)&kf, g_kf);
    cudaGetSymbolAddress((void**)&vh, g_vh);

    static bool attr_set = false;
    if (!attr_set) {
        cudaFuncSetAttribute(flash_mma, cudaFuncAttributeMaxDynamicSharedMemorySize,
                             2 * FBUF + FARR);
        attr_set = true;
    }

    // fp16 conversions (hidden + ALL weights in 2 launches)
    cvt_f16<<<(SEQ * EMB + 255) / 256, 256>>>(hidden, hidF, SEQ * EMB);
    cvt_weights<<<(2457600 + 255) / 256, 256>>>(Wq, Wk, Wv, Wo, wH, wL, woH, woL);

    // fused QKV projection (fp16 HMMA, cp.async pipelined); V emitted as fp16
    gemm_mma<<<dim3(NQKV / 64, SEQ / 64), 128>>>(hidF, wH, wL, 0, q, k, vh, nullptr);

    // RoPE + convert (Q single fp16; K single fp16, scale folded in)
    rope_split<<<(SEQ * 32 + 255) / 256, 256>>>(q, k, pos, qf, kf);

    // flash attention (fp16 HMMA, one q-tile per CTA, largest first)
    flash_mma<<<dim3(64, NH), 128, 2 * FBUF + FARR>>>(qf, kf, vh, aF);

    // O projection (fp16 HMMA)
    gemm_mma<<<dim3(EMB / 64, SEQ / 64), 128>>>(aF, woH, woL, 1,
                                                nullptr, nullptr, nullptr, out);
}

// round 13
// speedup vs baseline: 8.6520x; 1.1652x over previous
#include <cuda_runtime.h>
#include <cuda_bf16.h>
#include <cuda_fp16.h>
#include <stdint.h>
#include <math.h>

#define SEQ 4096
#define EMB 960
#define NH 15
#define NKV 5
#define HD 64
#define GROUPS 3
#define KDIM 960
#define NQKV 1600
#define FD 72                 // flash smem row stride (elems)
#define FARR (64 * FD * 2)    // 9216 B per flash array
#define FBUF (2 * FARR)       // 18432 B per flash KV buffer (Kf, Vf)
#define QSCALE 0.18033688011112042f  // 0.125 * log2(e), folded into K

typedef uint32_t u32;

// ---- PTX helpers ----------------------------------------------------------
__device__ __forceinline__ uint32_t smem_to_u32(const void* p) {
    uint32_t a;
    asm("{ .reg .u64 t; cvta.to.shared.u64 t, %1; cvt.u32.u64 %0, t; }" : "=r"(a) : "l"(p));
    return a;
}
__device__ __forceinline__ void mma_f16(float* c, const u32* a, const u32* b) {
    asm volatile(
        "mma.sync.aligned.m16n8k16.row.col.f32.f16.f16.f32 "
        "{%0,%1,%2,%3}, {%4,%5,%6,%7}, {%8,%9}, {%0,%1,%2,%3};"
        : "+f"(c[0]), "+f"(c[1]), "+f"(c[2]), "+f"(c[3])
        : "r"(a[0]), "r"(a[1]), "r"(a[2]), "r"(a[3]), "r"(b[0]), "r"(b[1]));
}
__device__ __forceinline__ void ldsm4(u32* r, u32 addr) {
    asm volatile("ldmatrix.sync.aligned.m8n8.x4.shared.b16 {%0,%1,%2,%3}, [%4];"
                 : "=r"(r[0]), "=r"(r[1]), "=r"(r[2]), "=r"(r[3]) : "r"(addr));
}
__device__ __forceinline__ void ldsm4t(u32* r, u32 addr) {
    asm volatile("ldmatrix.sync.aligned.m8n8.x4.trans.shared.b16 {%0,%1,%2,%3}, [%4];"
                 : "=r"(r[0]), "=r"(r[1]), "=r"(r[2]), "=r"(r[3]) : "r"(addr));
}
__device__ __forceinline__ float ex2f(float x) {
    float y; asm("ex2.approx.f32 %0, %1;" : "=f"(y) : "f"(x)); return y;
}
__device__ __forceinline__ u32 pack_h2(float lo, float hi) {
    u32 r; asm("cvt.rn.f16x2.f32 %0, %1, %2;" : "=r"(r) : "f"(hi), "f"(lo)); return r;
}
__device__ __forceinline__ void cp16(u32 saddr, const void* g) {
    asm volatile("cp.async.cg.shared.global [%0], [%1], 16;" :: "r"(saddr), "l"(g));
}
#define CP_COMMIT() asm volatile("cp.async.commit_group;" ::: "memory")
#define CP_WAIT1() asm volatile("cp.async.wait_group 1;" ::: "memory")
#define CP_WAIT0() asm volatile("cp.async.wait_group 0;" ::: "memory")

// ---- scratch --------------------------------------------------------------
__device__ float g_q[SEQ * NH * HD];
__device__ float g_k[SEQ * NKV * HD];
__device__ __half g_hidF[SEQ * EMB];
__device__ __half g_wF[NQKV * KDIM];
__device__ __half g_woF[EMB * KDIM];
__device__ __half g_aF[SEQ * EMB];
__device__ __half g_qf[SEQ * NH * HD];
__device__ __half g_kf[SEQ * NKV * HD];
__device__ __half g_vh[SEQ * NKV * HD];

// ---------------------------------------------------------------------------
__global__ void cvt_f16(const float* __restrict__ src, __half* __restrict__ dst, int n) {
    int i = blockIdx.x * blockDim.x + threadIdx.x;
    if (i >= n) return;
    dst[i] = __float2half_rn(src[i]);
}

// all four weight matrices -> single fp16 in ONE launch
__global__ void cvt_weights(const float* __restrict__ Wq, const float* __restrict__ Wk,
                            const float* __restrict__ Wv, const float* __restrict__ Wo,
                            __half* __restrict__ wF, __half* __restrict__ woF) {
    int i = blockIdx.x * blockDim.x + threadIdx.x;
    const int NQ = EMB * KDIM;           // 921600
    const int NKVW = 320 * KDIM;         // 307200
    const int TOT = NQ + 2 * NKVW + NQ;  // 2457600
    if (i >= TOT) return;
    const float* src;
    __half* dst;
    int j = i;
    if (j < NQ) {
        src = Wq; dst = wF;
    } else if (j < NQ + NKVW) {
        j -= NQ; src = Wk; dst = wF + NQ;
    } else if (j < NQ + 2 * NKVW) {
        j -= NQ + NKVW; src = Wv; dst = wF + NQ + NKVW;
    } else {
        j -= NQ + 2 * NKVW; src = Wo; dst = woF;
    }
    dst[j] = __float2half_rn(src[j]);
}

// ---------------------------------------------------------------------------
// HMMA fp16 GEMM: C[M,N] = A(fp16) @ B(fp16)^T, fp32 acc, cp.async double buf.
// mode 0: q fp32 (col<960), k fp32 (<1280), V as fp16 (>=1280); mode 1: C fp32
// ---------------------------------------------------------------------------
#define PAD 40
#define GARR (64 * PAD * 2)   // 5120 B
#define GBUF (2 * GARR)       // 10240 B

__device__ __forceinline__ void gemm_ld(
    u32 sbase, const __half* A, const __half* B, int bm, int bn, int k0, int tid) {
#pragma unroll
    for (int it = 0; it < 2; it++) {
        int idx = tid + it * 128;
        int row = idx >> 2, c16 = idx & 3;
        size_t ga = (size_t)(bm + row) * KDIM + k0 + c16 * 8;
        size_t gb = (size_t)(bn + row) * KDIM + k0 + c16 * 8;
        u32 so = (u32)(row * PAD + c16 * 8) * 2;
        cp16(sbase + so, A + ga);
        cp16(sbase + GARR + so, B + gb);
    }
}

__global__ __launch_bounds__(128) void gemm_mma(
    const __half* __restrict__ A, const __half* __restrict__ B,
    int mode, float* __restrict__ q, float* __restrict__ k,
    __half* __restrict__ vh, float* __restrict__ C) {
    __shared__ __half gsm[2 * 2 * 64 * PAD];
    const u32 base = smem_to_u32(gsm);
    const int tid = threadIdx.x;
    const int warp = tid >> 5, lane = tid & 31;
    const int wm = warp & 1, wn = warp >> 1;
    const int bm = blockIdx.y * 64, bn = blockIdx.x * 64;

    float acc[2][4][4];
#pragma unroll
    for (int am = 0; am < 2; am++)
#pragma unroll
        for (int nj = 0; nj < 4; nj++)
#pragma unroll
            for (int e = 0; e < 4; e++) acc[am][nj][e] = 0.f;

    const int a_r = lane & 15, a_h = lane >> 4;
    const int b_r = lane & 7, b_q = lane >> 3;
    const int NCH = KDIM / 32;  // 30

    gemm_ld(base, A, B, bm, bn, 0, tid);
    CP_COMMIT();

    for (int ch = 0; ch < NCH; ch++) {
        if (ch < NCH - 1) {
            gemm_ld(base + ((ch + 1) & 1) * GBUF, A, B, bm, bn, (ch + 1) * 32, tid);
            CP_COMMIT();
            CP_WAIT1();
        } else {
            CP_WAIT0();
        }
        __syncthreads();
        const u32 pA = base + (ch & 1) * GBUF;
        const u32 pB = pA + GARR;

#pragma unroll
        for (int kg = 0; kg < 2; kg++) {
            u32 aF[2][4], bF[2][4];
#pragma unroll
            for (int am = 0; am < 2; am++) {
                u32 off = (u32)((wm * 32 + am * 16 + a_r) * PAD + kg * 16 + a_h * 8) * 2;
                ldsm4(aF[am], pA + off);
            }
#pragma unroll
            for (int np = 0; np < 2; np++) {
                u32 off = (u32)((wn * 32 + np * 16 + (b_q >> 1) * 8 + b_r) * PAD +
                                kg * 16 + (b_q & 1) * 8) * 2;
                ldsm4(bF[np], pB + off);
            }
#pragma unroll
            for (int am = 0; am < 2; am++)
#pragma unroll
                for (int nj = 0; nj < 4; nj++) {
                    mma_f16(acc[am][nj], aF[am], &bF[nj >> 1][(nj & 1) * 2]);
                }
        }
        __syncthreads();
    }

    const int r0 = lane >> 2, cpair = (lane & 3) * 2;
#pragma unroll
    for (int am = 0; am < 2; am++)
#pragma unroll
        for (int half = 0; half < 2; half++) {
            int row = bm + wm * 32 + am * 16 + half * 8 + r0;
#pragma unroll
            for (int nj = 0; nj < 4; nj++) {
                int col = bn + wn * 32 + nj * 8 + cpair;
                float2 val = {acc[am][nj][half * 2], acc[am][nj][half * 2 + 1]};
                if (mode == 0) {
                    if (col < 960) {
                        *(float2*)(q + (size_t)row * 960 + col) = val;
                    } else if (col < 1280) {
                        *(float2*)(k + (size_t)row * 320 + (col - 960)) = val;
                    } else {
                        size_t o = (size_t)row * 320 + (col - 1280);
                        *(__half2*)(vh + o) =
                            __halves2half2(__float2half_rn(val.x), __float2half_rn(val.y));
                    }
                } else {
                    *(float2*)(C + (size_t)row * 960 + col) = val;
                }
            }
        }
}

// ---------------------------------------------------------------------------
// RoPE + convert: q -> qf (single fp16), k -> kf (fp16, QSCALE folded)
// ---------------------------------------------------------------------------
__global__ void rope_split(const float* __restrict__ q, const float* __restrict__ k,
                           const int* __restrict__ pos,
                           __half* __restrict__ qf, __half* __restrict__ kf) {
    int idx = blockIdx.x * blockDim.x + threadIdx.x;
    if (idx >= SEQ * 32) return;
    int i = idx & 31;
    int s = idx >> 5;
    float p = (float)pos[s];
    float inv = powf(10000.0f, -(float)i * (1.0f / 32.0f));
    float sn, c;
    sincosf(p * inv, &sn, &c);

    const float* qrow = q + (size_t)s * NH * HD;
#pragma unroll
    for (int h = 0; h < NH; h++) {
        float x1 = qrow[h * HD + i];
        float x2 = qrow[h * HD + i + 32];
        size_t o = (size_t)s * NH * HD + h * HD + i;
        qf[o] = __float2half_rn(x1 * c - x2 * sn);
        qf[o + 32] = __float2half_rn(x2 * c + x1 * sn);
    }
    const float* krow = k + (size_t)s * NKV * HD;
#pragma unroll
    for (int h = 0; h < NKV; h++) {
        float x1 = krow[h * HD + i];
        float x2 = krow[h * HD + i + 32];
        size_t o = (size_t)s * NKV * HD + h * HD + i;
        kf[o] = __float2half_rn((x1 * c - x2 * sn) * QSCALE);
        kf[o + 32] = __float2half_rn((x2 * c + x1 * sn) * QSCALE);
    }
}

// ---------------------------------------------------------------------------
// HMMA causal flash attention, single-fp16 Q and K (scale folded into K).
// Grid (64, 15): ONE q-tile per CTA, qt = 63 - blockIdx.x (largest first).
// Output single fp16 (aF).
// ---------------------------------------------------------------------------
__device__ __forceinline__ void kv_async(u32 dst, const __half* Kf, const __half* Vf,
                                         int k0, int kvh, int tid) {
#pragma unroll
    for (int u = tid; u < 512; u += 128) {
        int row = u >> 3, c8 = u & 7;
        size_t g = (size_t)(k0 + row) * (NKV * HD) + kvh * HD + c8 * 8;
        u32 so = (u32)(row * FD + c8 * 8) * 2;
        cp16(dst + so, Kf + g);
        cp16(dst + FARR + so, Vf + g);
    }
}

__global__ __launch_bounds__(128) void flash_mma(
    const __half* __restrict__ Qf, const __half* __restrict__ Kf,
    const __half* __restrict__ Vf, __half* __restrict__ aF) {
    extern __shared__ char fsm[];
    const u32 base = smem_to_u32(fsm);
    const int qt = 63 - (int)blockIdx.x, h = blockIdx.y, kvh = h / GROUPS;
    const int q0 = qt * 64;
    const int tid = threadIdx.x, warp = tid >> 5, lane = tid & 31;
    const int sel = lane >> 3, l7 = lane & 7;

    // prefetch KV tile 0 into buf0 (async; overlaps Q staging below)
    kv_async(base, Kf, Vf, 0, kvh, tid);
    CP_COMMIT();

    // stage Q via buf1, extract fragments
    for (int u = tid; u < 512; u += 128) {
        int row = u >> 3, c8 = u & 7;
        size_t g = (size_t)(q0 + row) * (NH * HD) + h * HD + c8 * 8;
        u32 so = (u32)(row * FD + c8 * 8) * 2;
        *(uint4*)(fsm + FBUF + so) = *(const uint4*)(Qf + g);
    }
    __syncthreads();
    u32 aQ[4][4];
    {
        int row = warp * 16 + (lane & 15);
        int csel = (lane >> 4) * 8;
#pragma unroll
        for (int ks = 0; ks < 4; ks++) {
            u32 off = (u32)(row * FD + ks * 16 + csel) * 2;
            ldsm4(aQ[ks], base + FBUF + off);
        }
    }
    __syncthreads();  // Q frags extracted before buf1 is overwritten (kt=1 prefetch)

    float m_i[2] = {-1e30f, -1e30f}, l_i[2] = {0.f, 0.f};
    float acc_o[8][4];
#pragma unroll
    for (int j = 0; j < 8; j++)
#pragma unroll
        for (int e = 0; e < 4; e++) acc_o[j][e] = 0.f;

    for (int kt = 0; kt <= qt; kt++) {
        if (kt < qt) {
            kv_async(base + ((kt + 1) & 1) * FBUF, Kf, Vf, (kt + 1) * 64, kvh, tid);
            CP_COMMIT();
            CP_WAIT1();
        } else {
            CP_WAIT0();
        }
        __syncthreads();
        const u32 pKf = base + (kt & 1) * FBUF;
        const u32 pVf = pKf + FARR;

        // ---- S = Q K^T (single fp16 each; scale pre-folded into K)
        float s[8][4];
#pragma unroll
        for (int j = 0; j < 8; j++)
#pragma unroll
            for (int e = 0; e < 4; e++) s[j][e] = 0.f;

#pragma unroll
        for (int ks = 0; ks < 4; ks++) {
#pragma unroll
            for (int g2 = 0; g2 < 4; g2++) {
                int key = 16 * g2 + ((sel >> 1) << 3) + l7;
                int col = ks * 16 + (sel & 1) * 8;
                u32 off = (u32)(key * FD + col) * 2;
                u32 bf[4];
                ldsm4(bf, pKf + off);
                mma_f16(s[2 * g2], aQ[ks], bf);
                mma_f16(s[2 * g2 + 1], aQ[ks], bf + 2);
            }
        }

        // ---- causal mask (diagonal tile only)
        if (kt == qt) {
            const int c0 = (lane & 3) * 2, r0l = warp * 16 + (lane >> 2);
#pragma unroll
            for (int j = 0; j < 8; j++)
#pragma unroll
                for (int e = 0; e < 4; e++) {
                    int key = 8 * j + c0 + (e & 1);
                    int qr = r0l + (e >> 1) * 8;
                    if (key > qr) s[j][e] = -1e30f;
                }
        }

        // ---- online softmax (base-2), P -> fp16 fragments
        u32 ph2[8][2];
#pragma unroll
        for (int hf = 0; hf < 2; hf++) {
            float rm = -1e30f;
#pragma unroll
            for (int j = 0; j < 8; j++)
                rm = fmaxf(rm, fmaxf(s[j][2 * hf], s[j][2 * hf + 1]));
            rm = fmaxf(rm, __shfl_xor_sync(0xffffffffu, rm, 1));
            rm = fmaxf(rm, __shfl_xor_sync(0xffffffffu, rm, 2));
            float mnew = fmaxf(m_i[hf], rm);
            float corr = ex2f(m_i[hf] - mnew);
            m_i[hf] = mnew;
            float rsum = 0.f;
#pragma unroll
            for (int j = 0; j < 8; j++) {
                float p0 = ex2f(s[j][2 * hf] - mnew);
                float p1 = ex2f(s[j][2 * hf + 1] - mnew);
                ph2[j][hf] = pack_h2(p0, p1);
                rsum += p0 + p1;
            }
            rsum += __shfl_xor_sync(0xffffffffu, rsum, 1);
            rsum += __shfl_xor_sync(0xffffffffu, rsum, 2);
            l_i[hf] = l_i[hf] * corr + rsum;
#pragma unroll
            for (int j = 0; j < 8; j++) {
                acc_o[j][2 * hf] *= corr;
                acc_o[j][2 * hf + 1] *= corr;
            }
        }

        // ---- O += P V (fp16 V)
#pragma unroll
        for (int g2 = 0; g2 < 4; g2++) {
            u32 pa4[4] = {ph2[2 * g2][0], ph2[2 * g2][1],
                          ph2[2 * g2 + 1][0], ph2[2 * g2 + 1][1]};
#pragma unroll
            for (int dd = 0; dd < 4; dd++) {
                int key = 16 * g2 + ((sel & 1) << 3) + l7;
                int col = 16 * dd + ((sel >> 1) << 3);
                u32 off = (u32)(key * FD + col) * 2;
                u32 bh[4];
                ldsm4t(bh, pVf + off);
                mma_f16(acc_o[2 * dd], pa4, bh);
                mma_f16(acc_o[2 * dd + 1], pa4, bh + 2);
            }
        }
        __syncthreads();  // all reads of buf[kt&1] done before kt+2 prefetch
    }

    // ---- normalize + write single fp16
    const float inv0 = 1.0f / l_i[0], inv1 = 1.0f / l_i[1];
    const int r0 = q0 + warp * 16 + (lane >> 2), c0 = (lane & 3) * 2;
#pragma unroll
    for (int j = 0; j < 8; j++) {
        int col = h * HD + 8 * j + c0;
#pragma unroll
        for (int hf = 0; hf < 2; hf++) {
            float a0 = acc_o[j][2 * hf] * (hf ? inv1 : inv0);
            float a1 = acc_o[j][2 * hf + 1] * (hf ? inv1 : inv0);
            size_t o = (size_t)(r0 + hf * 8) * EMB + col;
            *(__half2*)(aF + o) =
                __halves2half2(__float2half_rn(a0), __float2half_rn(a1));
        }
    }
}

// ---------------------------------------------------------------------------
extern "C" void kernel_launch(void* const* d_in, const int* in_sizes, int n_in,
                              void* d_out, int out_size) {
    const float* hidden = (const float*)d_in[0];
    const float* Wq = (const float*)d_in[1];
    const float* Wk = (const float*)d_in[2];
    const float* Wv = (const float*)d_in[3];
    const float* Wo = (const float*)d_in[4];
    const int* pos = (const int*)d_in[6];
    float* out = (float*)d_out;

    float *q, *k;
    __half *hidF, *wF, *woF, *aF, *qf, *kf, *vh;
    cudaGetSymbolAddress((void**)&q, g_q);
    cudaGetSymbolAddress((void**)&k, g_k);
    cudaGetSymbolAddress((void**)&hidF, g_hidF);
    cudaGetSymbolAddress((void**)&wF, g_wF);
    cudaGetSymbolAddress((void**)&woF, g_woF);
    cudaGetSymbolAddress((void**)&aF, g_aF);
    cudaGetSymbolAddress((void**)&qf, g_qf);
    cudaGetSymbolAddress((void**)&kf, g_kf);
    cudaGetSymbolAddress((void**)&vh, g_vh);

    static bool attr_set = false;
    if (!attr_set) {
        cudaFuncSetAttribute(flash_mma, cudaFuncAttributeMaxDynamicSharedMemorySize,
                             2 * FBUF + FARR);
        attr_set = true;
    }

    // fp16 conversions (hidden + ALL weights in 2 launches)
    cvt_f16<<<(SEQ * EMB + 255) / 256, 256>>>(hidden, hidF, SEQ * EMB);
    cvt_weights<<<(2457600 + 255) / 256, 256>>>(Wq, Wk, Wv, Wo, wF, woF);

    // fused QKV projection (pure fp16 HMMA, cp.async pipelined); V emitted fp16
    gemm_mma<<<dim3(NQKV / 64, SEQ / 64), 128>>>(hidF, wF, 0, q, k, vh, nullptr);

    // RoPE + convert (Q single fp16; K single fp16, scale folded in)
    rope_split<<<(SEQ * 32 + 255) / 256, 256>>>(q, k, pos, qf, kf);

    // flash attention (fp16 HMMA, one q-tile per CTA, largest first)
    flash_mma<<<dim3(64, NH), 128, 2 * FBUF + FARR>>>(qf, kf, vh, aF);

    // O projection (pure fp16 HMMA)
    gemm_mma<<<dim3(EMB / 64, SEQ / 64), 128>>>(aF, woF, 1,
                                                nullptr, nullptr, nullptr, out);
}